// round 1
// baseline (speedup 1.0000x reference)
#include <cuda_runtime.h>
#include <math.h>

// Problem constants
#define B_  2
#define S_  2048
#define D_  2048
#define H_  16
#define DH_ 128
#define M_  (B_*S_)   // 4096

// ---------------------------------------------------------------------------
// Scratch (no cudaMalloc allowed)
// ---------------------------------------------------------------------------
__device__ __align__(16) float g_Q[(size_t)M_ * D_];
__device__ __align__(16) float g_K[(size_t)M_ * D_];
__device__ __align__(16) float g_V[(size_t)M_ * D_];
__device__ __align__(16) float g_O[(size_t)M_ * D_];
__device__ __align__(16) float2 g_rope[S_ * (DH_ / 2)];

// ---------------------------------------------------------------------------
// RoPE cos/sin table: g_rope[s*64 + i] = (cos, sin) of pos[s] * theta^(-2i/128)
// ---------------------------------------------------------------------------
__global__ void rope_table_kernel(const int* __restrict__ pos)
{
    int idx = blockIdx.x * blockDim.x + threadIdx.x;
    if (idx >= S_ * (DH_ / 2)) return;
    int s = idx / (DH_ / 2);
    int i = idx % (DH_ / 2);
    float p    = (float)pos[s];
    float freq = powf(1.0f / 10000.0f, (2.0f * (float)i) / (float)DH_);
    float ang  = p * freq;
    g_rope[idx] = make_float2(cosf(ang), sinf(ang));
}

// ---------------------------------------------------------------------------
// SGEMM  C[M,N] = A[M,K] @ W[N,K]^T   (both row-major, K contiguous)
// Tiles: BM=128, BN=128, BK=16; 256 threads; 8x8 micro-tile per thread.
// If ROPE: apply interleaved RoPE to the output (row -> position, col -> head dim).
// ---------------------------------------------------------------------------
template <bool ROPE>
__global__ __launch_bounds__(256) void sgemm_nt(
    const float* __restrict__ A, const float* __restrict__ W,
    float* __restrict__ C, int K, int N)
{
    __shared__ float As[16][132];
    __shared__ float Bs[16][132];

    const int tid = threadIdx.x;
    const int tx  = tid & 15;
    const int ty  = tid >> 4;
    const int bm  = blockIdx.y * 128;
    const int bn  = blockIdx.x * 128;

    float acc[8][8];
#pragma unroll
    for (int i = 0; i < 8; i++)
#pragma unroll
        for (int j = 0; j < 8; j++) acc[i][j] = 0.0f;

    for (int k0 = 0; k0 < K; k0 += 16) {
#pragma unroll
        for (int v = 0; v < 2; v++) {
            int idx = tid + v * 256;          // 0..511
            int row = idx >> 2;               // 0..127
            int c4  = (idx & 3) * 4;          // 0,4,8,12
            float4 a = *(const float4*)(A + (size_t)(bm + row) * K + k0 + c4);
            As[c4 + 0][row] = a.x; As[c4 + 1][row] = a.y;
            As[c4 + 2][row] = a.z; As[c4 + 3][row] = a.w;
            float4 b = *(const float4*)(W + (size_t)(bn + row) * K + k0 + c4);
            Bs[c4 + 0][row] = b.x; Bs[c4 + 1][row] = b.y;
            Bs[c4 + 2][row] = b.z; Bs[c4 + 3][row] = b.w;
        }
        __syncthreads();

#pragma unroll
        for (int kk = 0; kk < 16; kk++) {
            float a[8], b[8];
#pragma unroll
            for (int i = 0; i < 8; i++) a[i] = As[kk][ty * 8 + i];
#pragma unroll
            for (int j = 0; j < 8; j++) b[j] = Bs[kk][tx * 8 + j];
#pragma unroll
            for (int i = 0; i < 8; i++)
#pragma unroll
                for (int j = 0; j < 8; j++) acc[i][j] += a[i] * b[j];
        }
        __syncthreads();
    }

    // Epilogue (+ optional fused RoPE)
#pragma unroll
    for (int i = 0; i < 8; i++) {
        int gr = bm + ty * 8 + i;
        float* Crow = C + (size_t)gr * N + bn + tx * 8;
        if (ROPE) {
            int s   = gr & (S_ - 1);         // row -> sequence position
            int ih0 = tx * 4;                // (col % 128) / 2 with col = bn + tx*8
#pragma unroll
            for (int j = 0; j < 8; j += 2) {
                float2 cs = g_rope[s * (DH_ / 2) + ih0 + (j >> 1)];
                float e = acc[i][j], o = acc[i][j + 1];
                acc[i][j]     = e * cs.x - o * cs.y;
                acc[i][j + 1] = e * cs.y + o * cs.x;
            }
        }
        *(float4*)(Crow)     = make_float4(acc[i][0], acc[i][1], acc[i][2], acc[i][3]);
        *(float4*)(Crow + 4) = make_float4(acc[i][4], acc[i][5], acc[i][6], acc[i][7]);
    }
}

// ---------------------------------------------------------------------------
// Causal flash attention, fp32. One CTA = 64 query rows of one (b,h).
// BLOCK_M = BLOCK_N = 64, DH = 128, 256 threads (16x16 grid).
//  - S micro-tile per thread: 4 rows x 4 cols
//  - PV micro-tile per thread: 4 rows x 8 cols (two 4-col blocks at +0 / +64)
// ---------------------------------------------------------------------------
#define FA_SMEM ((64*132 + 128*68 + 64*132 + 64*68) * 4)

__global__ __launch_bounds__(256) void flash_kernel()
{
    extern __shared__ float sm[];
    float (*Qs)[132] = (float(*)[132])sm;                                // 64 x 132
    float (*Kt)[68]  = (float(*)[68]) (sm + 64 * 132);                   // 128 x 68 (transposed)
    float (*Vs)[132] = (float(*)[132])(sm + 64 * 132 + 128 * 68);        // 64 x 132
    float (*Ps)[68]  = (float(*)[68]) (sm + 64 * 132 + 128 * 68 + 64 * 132); // 64 x 68

    const int tid = threadIdx.x;
    const int tx  = tid & 15;
    const int ty  = tid >> 4;
    const int bh  = blockIdx.y;
    const int b   = bh >> 4;
    const int h   = bh & 15;
    const int qt  = (int)gridDim.x - 1 - (int)blockIdx.x; // heavy tiles first
    const int q0  = qt * 64;

    const float* Qg = g_Q + ((size_t)(b * S_ + q0)) * D_ + h * DH_;

    // Load Q tile [64 x 128]
#pragma unroll
    for (int v = 0; v < 8; v++) {
        int idx = tid + v * 256;
        int row = idx >> 5;
        int c4  = (idx & 31) * 4;
        float4 q = *(const float4*)(Qg + (size_t)row * D_ + c4);
        *(float4*)&Qs[row][c4] = q;
    }

    float m_r[4], l_r[4], acc[4][8];
#pragma unroll
    for (int r = 0; r < 4; r++) {
        m_r[r] = -INFINITY; l_r[r] = 0.0f;
#pragma unroll
        for (int c = 0; c < 8; c++) acc[r][c] = 0.0f;
    }
    const float scale = 0.08838834764831845f; // 1/sqrt(128)

    for (int j = 0; j <= qt; j++) {
        __syncthreads();   // prev-iter smem reads done; Q tile ready on iter 0
        const float* Kg = g_K + ((size_t)(b * S_ + j * 64)) * D_ + h * DH_;
        const float* Vg = g_V + ((size_t)(b * S_ + j * 64)) * D_ + h * DH_;
#pragma unroll
        for (int v = 0; v < 8; v++) {
            int idx = tid + v * 256;
            int row = idx >> 5;
            int c4  = (idx & 31) * 4;
            float4 k = *(const float4*)(Kg + (size_t)row * D_ + c4);
            Kt[c4 + 0][row] = k.x; Kt[c4 + 1][row] = k.y;
            Kt[c4 + 2][row] = k.z; Kt[c4 + 3][row] = k.w;
            float4 vv = *(const float4*)(Vg + (size_t)row * D_ + c4);
            *(float4*)&Vs[row][c4] = vv;
        }
        __syncthreads();

        // S = Q @ K^T  (4x4 per thread)
        float s[4][4];
#pragma unroll
        for (int r = 0; r < 4; r++)
#pragma unroll
            for (int c = 0; c < 4; c++) s[r][c] = 0.0f;

#pragma unroll 8
        for (int kk = 0; kk < 128; kk++) {
            float4 kv = *(float4*)&Kt[kk][tx * 4];
#pragma unroll
            for (int r = 0; r < 4; r++) {
                float q = Qs[ty * 4 + r][kk];
                s[r][0] += q * kv.x; s[r][1] += q * kv.y;
                s[r][2] += q * kv.z; s[r][3] += q * kv.w;
            }
        }

        const bool diag = (j == qt);
#pragma unroll
        for (int r = 0; r < 4; r++) {
#pragma unroll
            for (int c = 0; c < 4; c++) {
                float val = s[r][c] * scale;
                if (diag && (tx * 4 + c > ty * 4 + r)) val = -INFINITY;
                s[r][c] = val;
            }
        }

        // Online softmax (row groups = 16 lanes with same ty)
#pragma unroll
        for (int r = 0; r < 4; r++) {
            float mx = fmaxf(fmaxf(s[r][0], s[r][1]), fmaxf(s[r][2], s[r][3]));
#pragma unroll
            for (int off = 8; off >= 1; off >>= 1)
                mx = fmaxf(mx, __shfl_xor_sync(0xffffffffu, mx, off, 16));
            float m_new = fmaxf(m_r[r], mx);
            float corr  = __expf(m_r[r] - m_new);
            float p0 = __expf(s[r][0] - m_new);
            float p1 = __expf(s[r][1] - m_new);
            float p2 = __expf(s[r][2] - m_new);
            float p3 = __expf(s[r][3] - m_new);
            *(float4*)&Ps[ty * 4 + r][tx * 4] = make_float4(p0, p1, p2, p3);
            float psum = p0 + p1 + p2 + p3;
#pragma unroll
            for (int off = 8; off >= 1; off >>= 1)
                psum += __shfl_xor_sync(0xffffffffu, psum, off, 16);
            l_r[r] = l_r[r] * corr + psum;
            m_r[r] = m_new;
#pragma unroll
            for (int c = 0; c < 8; c++) acc[r][c] *= corr;
        }
        __syncwarp();  // P producers/consumers share a half-warp per row group

        // O += P @ V  (4 rows x 8 cols per thread: col blocks at tx*4 and 64+tx*4)
#pragma unroll 4
        for (int kk = 0; kk < 64; kk++) {
            float4 v0 = *(float4*)&Vs[kk][tx * 4];
            float4 v1 = *(float4*)&Vs[kk][64 + tx * 4];
#pragma unroll
            for (int r = 0; r < 4; r++) {
                float p = Ps[ty * 4 + r][kk];
                acc[r][0] += p * v0.x; acc[r][1] += p * v0.y;
                acc[r][2] += p * v0.z; acc[r][3] += p * v0.w;
                acc[r][4] += p * v1.x; acc[r][5] += p * v1.y;
                acc[r][6] += p * v1.z; acc[r][7] += p * v1.w;
            }
        }
    }

    // Epilogue: normalize and store
    float* Og = g_O + ((size_t)(b * S_ + q0)) * D_ + h * DH_;
#pragma unroll
    for (int r = 0; r < 4; r++) {
        float inv = 1.0f / l_r[r];
        int row = ty * 4 + r;
        *(float4*)(Og + (size_t)row * D_ + tx * 4) =
            make_float4(acc[r][0] * inv, acc[r][1] * inv, acc[r][2] * inv, acc[r][3] * inv);
        *(float4*)(Og + (size_t)row * D_ + 64 + tx * 4) =
            make_float4(acc[r][4] * inv, acc[r][5] * inv, acc[r][6] * inv, acc[r][7] * inv);
    }
}

// ---------------------------------------------------------------------------
// Launch
// ---------------------------------------------------------------------------
extern "C" void kernel_launch(void* const* d_in, const int* in_sizes, int n_in,
                              void* d_out, int out_size)
{
    const float* x   = (const float*)d_in[0];
    const int*   pos = (const int*)  d_in[1];
    const float* Wq  = (const float*)d_in[2];
    const float* Wk  = (const float*)d_in[3];
    const float* Wv  = (const float*)d_in[4];
    const float* Wo  = (const float*)d_in[5];
    float*       out = (float*)d_out;

    float *Qp, *Kp, *Vp, *Op;
    cudaGetSymbolAddress((void**)&Qp, g_Q);
    cudaGetSymbolAddress((void**)&Kp, g_K);
    cudaGetSymbolAddress((void**)&Vp, g_V);
    cudaGetSymbolAddress((void**)&Op, g_O);

    cudaFuncSetAttribute(flash_kernel, cudaFuncAttributeMaxDynamicSharedMemorySize, FA_SMEM);

    // RoPE table
    rope_table_kernel<<<(S_ * (DH_ / 2) + 255) / 256, 256>>>(pos);

    dim3 gemm_grid(D_ / 128, M_ / 128);  // (16, 32)
    sgemm_nt<true ><<<gemm_grid, 256>>>(x,  Wq, Qp, D_, D_);   // Q = rope(x @ Wq^T)
    sgemm_nt<true ><<<gemm_grid, 256>>>(x,  Wk, Kp, D_, D_);   // K = rope(x @ Wk^T)
    sgemm_nt<false><<<gemm_grid, 256>>>(x,  Wv, Vp, D_, D_);   // V = x @ Wv^T

    flash_kernel<<<dim3(S_ / 64, B_ * H_), 256, FA_SMEM>>>();  // O (attention)

    sgemm_nt<false><<<gemm_grid, 256>>>(Op, Wo, out, D_, D_);  // out = O @ Wo^T
}

// round 3
// speedup vs baseline: 1.6516x; 1.6516x over previous
#include <cuda_runtime.h>
#include <cuda_bf16.h>
#include <math.h>
#include <stdint.h>

// Problem constants
#define B_  2
#define S_  2048
#define D_  2048
#define H_  16
#define DH_ 128
#define M_  (B_*S_)   // 4096

// ---------------------------------------------------------------------------
// Scratch (no cudaMalloc allowed)
// ---------------------------------------------------------------------------
__device__ __align__(16) float g_Q[(size_t)M_ * D_];
__device__ __align__(16) float g_K[(size_t)M_ * D_];
__device__ __align__(16) float g_V[(size_t)M_ * D_];
__device__ __align__(16) float g_O[(size_t)M_ * D_];
__device__ __align__(16) float2 g_rope[S_ * (DH_ / 2)];

__device__ __align__(16) __nv_bfloat16 g_xhi[(size_t)M_ * D_];
__device__ __align__(16) __nv_bfloat16 g_xlo[(size_t)M_ * D_];
__device__ __align__(16) __nv_bfloat16 g_Whi[(size_t)4 * D_ * D_];
__device__ __align__(16) __nv_bfloat16 g_Wlo[(size_t)4 * D_ * D_];
__device__ __align__(16) __nv_bfloat16 g_Ohi[(size_t)M_ * D_];
__device__ __align__(16) __nv_bfloat16 g_Olo[(size_t)M_ * D_];

// ---------------------------------------------------------------------------
// PTX helpers (compute_103-safe: sm_80-era instructions only)
// ---------------------------------------------------------------------------
__device__ __forceinline__ uint32_t smem_u32(const void* p) {
    uint32_t a;
    asm("{ .reg .u64 t; cvta.to.shared.u64 t, %1; cvt.u32.u64 %0, t; }"
        : "=r"(a) : "l"(p));
    return a;
}

__device__ __forceinline__ void cp16(uint32_t dst, const void* src) {
    asm volatile("cp.async.cg.shared.global [%0], [%1], 16;" :: "r"(dst), "l"(src));
}
__device__ __forceinline__ void cp_commit() { asm volatile("cp.async.commit_group;" ::: "memory"); }
__device__ __forceinline__ void cp_wait1()  { asm volatile("cp.async.wait_group 1;" ::: "memory"); }

__device__ __forceinline__ void ldsm_x4(uint32_t (&r)[4], uint32_t addr) {
    asm volatile("ldmatrix.sync.aligned.m8n8.x4.shared.b16 {%0,%1,%2,%3}, [%4];"
                 : "=r"(r[0]), "=r"(r[1]), "=r"(r[2]), "=r"(r[3]) : "r"(addr));
}
__device__ __forceinline__ void ldsm_x2(uint32_t (&r)[2], uint32_t addr) {
    asm volatile("ldmatrix.sync.aligned.m8n8.x2.shared.b16 {%0,%1}, [%2];"
                 : "=r"(r[0]), "=r"(r[1]) : "r"(addr));
}

__device__ __forceinline__ void mma16816(float (&c)[4], const uint32_t (&a)[4],
                                         const uint32_t (&b)[2]) {
    asm volatile(
        "mma.sync.aligned.m16n8k16.row.col.f32.bf16.bf16.f32 "
        "{%0,%1,%2,%3}, {%4,%5,%6,%7}, {%8,%9}, {%0,%1,%2,%3};"
        : "+f"(c[0]), "+f"(c[1]), "+f"(c[2]), "+f"(c[3])
        : "r"(a[0]), "r"(a[1]), "r"(a[2]), "r"(a[3]), "r"(b[0]), "r"(b[1]));
}

// ---------------------------------------------------------------------------
// RoPE cos/sin table
// ---------------------------------------------------------------------------
__global__ void rope_table_kernel(const int* __restrict__ pos)
{
    int idx = blockIdx.x * blockDim.x + threadIdx.x;
    if (idx >= S_ * (DH_ / 2)) return;
    int s = idx / (DH_ / 2);
    int i = idx % (DH_ / 2);
    float p    = (float)pos[s];
    float freq = powf(1.0f / 10000.0f, (2.0f * (float)i) / (float)DH_);
    float ang  = p * freq;
    g_rope[idx] = make_float2(cosf(ang), sinf(ang));
}

// ---------------------------------------------------------------------------
// fp32 -> bf16 hi/lo split (lo = bf16(v - fp32(hi)))
// ---------------------------------------------------------------------------
__global__ void split_kernel(const float* __restrict__ src,
                             __nv_bfloat16* __restrict__ hi,
                             __nv_bfloat16* __restrict__ lo, int n4)
{
    int i = blockIdx.x * blockDim.x + threadIdx.x;
    if (i >= n4) return;
    float4 v = ((const float4*)src)[i];
    __nv_bfloat16 h0 = __float2bfloat16_rn(v.x);
    __nv_bfloat16 h1 = __float2bfloat16_rn(v.y);
    __nv_bfloat16 h2 = __float2bfloat16_rn(v.z);
    __nv_bfloat16 h3 = __float2bfloat16_rn(v.w);
    __nv_bfloat16 l0 = __float2bfloat16_rn(v.x - __bfloat162float(h0));
    __nv_bfloat16 l1 = __float2bfloat16_rn(v.y - __bfloat162float(h1));
    __nv_bfloat16 l2 = __float2bfloat16_rn(v.z - __bfloat162float(h2));
    __nv_bfloat16 l3 = __float2bfloat16_rn(v.w - __bfloat162float(h3));
    ((__nv_bfloat162*)hi)[2 * i]     = __halves2bfloat162(h0, h1);
    ((__nv_bfloat162*)hi)[2 * i + 1] = __halves2bfloat162(h2, h3);
    ((__nv_bfloat162*)lo)[2 * i]     = __halves2bfloat162(l0, l1);
    ((__nv_bfloat162*)lo)[2 * i + 1] = __halves2bfloat162(l2, l3);
}

// ---------------------------------------------------------------------------
// bf16x3 GEMM via mma.sync:  C[M,N] = (Ahi+Alo)[M,K] @ (Bhi+Blo)[N,K]^T
// CTA tile 128x128, BK=32, 8 warps (2x4), 64x32 per warp.
// Smem per stage: 4 tiles [128 rows x 32 bf16, stride 40 bf16 (80B)].
// ---------------------------------------------------------------------------
#define BK_       32
#define NCHUNK_   (D_ / BK_)            // 64
#define T_STRIDE_ 80                     // bytes per smem row
#define TILE_B_   (128 * T_STRIDE_)      // 10240 bytes
#define STAGE_B_  (4 * TILE_B_)          // 40960 bytes
#define GEMM_SMEM (2 * STAGE_B_)         // 81920 bytes

__device__ __forceinline__ void load_stage(
    uint32_t base, const __nv_bfloat16* __restrict__ pAh,
    const __nv_bfloat16* __restrict__ pAl,
    const __nv_bfloat16* __restrict__ pBh,
    const __nv_bfloat16* __restrict__ pBl, int c, int tid)
{
    const __nv_bfloat16* srcs[4] = { pAh + c * BK_, pAl + c * BK_,
                                     pBh + c * BK_, pBl + c * BK_ };
#pragma unroll
    for (int t = 0; t < 4; t++) {
#pragma unroll
        for (int v = 0; v < 2; v++) {
            int idx = tid + v * 256;        // 0..511
            int row = idx >> 2;             // 0..127
            int seg = idx & 3;              // 16B segment
            cp16(base + t * TILE_B_ + row * T_STRIDE_ + seg * 16,
                 srcs[t] + (size_t)row * D_ + seg * 8);
        }
    }
}

template <bool ROPE>
__global__ __launch_bounds__(256, 1) void gemm_mma(
    const __nv_bfloat16* __restrict__ Ahi, const __nv_bfloat16* __restrict__ Alo,
    const __nv_bfloat16* __restrict__ Bhi, const __nv_bfloat16* __restrict__ Blo,
    float* __restrict__ C)
{
    extern __shared__ __align__(128) char smem[];
    const uint32_t sb = smem_u32(smem);

    const int tid    = threadIdx.x;
    const int lane   = tid & 31;
    const int wid    = tid >> 5;
    const int warp_m = wid & 1;      // 0..1  -> 64 rows each
    const int warp_n = wid >> 1;     // 0..3  -> 32 cols each
    const int bm     = blockIdx.y * 128;
    const int bn     = blockIdx.x * 128;

    const __nv_bfloat16* pAh = Ahi + (size_t)bm * D_;
    const __nv_bfloat16* pAl = Alo + (size_t)bm * D_;
    const __nv_bfloat16* pBh = Bhi + (size_t)bn * D_;
    const __nv_bfloat16* pBl = Blo + (size_t)bn * D_;

    float acc[4][4][4];
#pragma unroll
    for (int mt = 0; mt < 4; mt++)
#pragma unroll
        for (int nt = 0; nt < 4; nt++)
#pragma unroll
            for (int q = 0; q < 4; q++) acc[mt][nt][q] = 0.0f;

    load_stage(sb,            pAh, pAl, pBh, pBl, 0, tid); cp_commit();
    load_stage(sb + STAGE_B_, pAh, pAl, pBh, pBl, 1, tid); cp_commit();

    // Per-lane ldmatrix offsets
    const uint32_t a_lane = (lane & 15) * T_STRIDE_ + (lane >> 4) * 16
                          + warp_m * 64 * T_STRIDE_;
    const uint32_t b_lane = (lane & 7) * T_STRIDE_ + ((lane >> 3) & 1) * 16
                          + warp_n * 32 * T_STRIDE_;

    for (int c = 0; c < NCHUNK_; c++) {
        cp_wait1();
        __syncthreads();
        const uint32_t base = sb + (c & 1) * STAGE_B_;

#pragma unroll
        for (int s = 0; s < 2; s++) {
            const uint32_t abase = base + s * 32 + a_lane;                 // Ahi
            const uint32_t bbase = base + 2 * TILE_B_ + s * 32 + b_lane;   // Bhi
            uint32_t ah[4][4], al[4][4], bh[4][2], bl[4][2];
#pragma unroll
            for (int mt = 0; mt < 4; mt++) {
                ldsm_x4(ah[mt], abase + mt * 16 * T_STRIDE_);
                ldsm_x4(al[mt], abase + TILE_B_ + mt * 16 * T_STRIDE_);
            }
#pragma unroll
            for (int nt = 0; nt < 4; nt++) {
                ldsm_x2(bh[nt], bbase + nt * 8 * T_STRIDE_);
                ldsm_x2(bl[nt], bbase + TILE_B_ + nt * 8 * T_STRIDE_);
            }
#pragma unroll
            for (int mt = 0; mt < 4; mt++)
#pragma unroll
                for (int nt = 0; nt < 4; nt++) {
                    mma16816(acc[mt][nt], ah[mt], bh[nt]);
                    mma16816(acc[mt][nt], ah[mt], bl[nt]);
                    mma16816(acc[mt][nt], al[mt], bh[nt]);
                }
        }
        __syncthreads();
        if (c + 2 < NCHUNK_)
            load_stage(base, pAh, pAl, pBh, pBl, c + 2, tid);
        cp_commit();
    }

    // Epilogue (+ fused RoPE). C fragment: lane gid=lane>>2, tig=lane&3:
    // c0,c1 = C[gid][2*tig, 2*tig+1]; c2,c3 = C[gid+8][...]
    const int gid = lane >> 2, tig = lane & 3;
#pragma unroll
    for (int mt = 0; mt < 4; mt++) {
        const int row0 = bm + warp_m * 64 + mt * 16 + gid;
        const int row1 = row0 + 8;
        const int s0 = row0 & (S_ - 1);
        const int s1 = row1 & (S_ - 1);
#pragma unroll
        for (int nt = 0; nt < 4; nt++) {
            const int col  = bn + warp_n * 32 + nt * 8 + tig * 2;
            float c0 = acc[mt][nt][0], c1 = acc[mt][nt][1];
            float c2 = acc[mt][nt][2], c3 = acc[mt][nt][3];
            if (ROPE) {
                const int pr = (col & (DH_ - 1)) >> 1;
                float2 csa = g_rope[s0 * (DH_ / 2) + pr];
                float2 csb = g_rope[s1 * (DH_ / 2) + pr];
                float e0 = c0, o0 = c1, e1 = c2, o1 = c3;
                c0 = e0 * csa.x - o0 * csa.y;
                c1 = e0 * csa.y + o0 * csa.x;
                c2 = e1 * csb.x - o1 * csb.y;
                c3 = e1 * csb.y + o1 * csb.x;
            }
            *(float2*)(C + (size_t)row0 * D_ + col) = make_float2(c0, c1);
            *(float2*)(C + (size_t)row1 * D_ + col) = make_float2(c2, c3);
        }
    }
}

// ---------------------------------------------------------------------------
// Causal flash attention, fp32 (unchanged from R1)
// ---------------------------------------------------------------------------
#define FA_SMEM ((64*132 + 128*68 + 64*132 + 64*68) * 4)

__global__ __launch_bounds__(256) void flash_kernel()
{
    extern __shared__ float sm[];
    float (*Qs)[132] = (float(*)[132])sm;
    float (*Kt)[68]  = (float(*)[68]) (sm + 64 * 132);
    float (*Vs)[132] = (float(*)[132])(sm + 64 * 132 + 128 * 68);
    float (*Ps)[68]  = (float(*)[68]) (sm + 64 * 132 + 128 * 68 + 64 * 132);

    const int tid = threadIdx.x;
    const int tx  = tid & 15;
    const int ty  = tid >> 4;
    const int bh  = blockIdx.y;
    const int b   = bh >> 4;
    const int h   = bh & 15;
    const int qt  = (int)gridDim.x - 1 - (int)blockIdx.x;
    const int q0  = qt * 64;

    const float* Qg = g_Q + ((size_t)(b * S_ + q0)) * D_ + h * DH_;

#pragma unroll
    for (int v = 0; v < 8; v++) {
        int idx = tid + v * 256;
        int row = idx >> 5;
        int c4  = (idx & 31) * 4;
        float4 q = *(const float4*)(Qg + (size_t)row * D_ + c4);
        *(float4*)&Qs[row][c4] = q;
    }

    float m_r[4], l_r[4], acc[4][8];
#pragma unroll
    for (int r = 0; r < 4; r++) {
        m_r[r] = -INFINITY; l_r[r] = 0.0f;
#pragma unroll
        for (int c = 0; c < 8; c++) acc[r][c] = 0.0f;
    }
    const float scale = 0.08838834764831845f;

    for (int j = 0; j <= qt; j++) {
        __syncthreads();
        const float* Kg = g_K + ((size_t)(b * S_ + j * 64)) * D_ + h * DH_;
        const float* Vg = g_V + ((size_t)(b * S_ + j * 64)) * D_ + h * DH_;
#pragma unroll
        for (int v = 0; v < 8; v++) {
            int idx = tid + v * 256;
            int row = idx >> 5;
            int c4  = (idx & 31) * 4;
            float4 k = *(const float4*)(Kg + (size_t)row * D_ + c4);
            Kt[c4 + 0][row] = k.x; Kt[c4 + 1][row] = k.y;
            Kt[c4 + 2][row] = k.z; Kt[c4 + 3][row] = k.w;
            float4 vv = *(const float4*)(Vg + (size_t)row * D_ + c4);
            *(float4*)&Vs[row][c4] = vv;
        }
        __syncthreads();

        float s[4][4];
#pragma unroll
        for (int r = 0; r < 4; r++)
#pragma unroll
            for (int c = 0; c < 4; c++) s[r][c] = 0.0f;

#pragma unroll 8
        for (int kk = 0; kk < 128; kk++) {
            float4 kv = *(float4*)&Kt[kk][tx * 4];
#pragma unroll
            for (int r = 0; r < 4; r++) {
                float q = Qs[ty * 4 + r][kk];
                s[r][0] += q * kv.x; s[r][1] += q * kv.y;
                s[r][2] += q * kv.z; s[r][3] += q * kv.w;
            }
        }

        const bool diag = (j == qt);
#pragma unroll
        for (int r = 0; r < 4; r++) {
#pragma unroll
            for (int c = 0; c < 4; c++) {
                float val = s[r][c] * scale;
                if (diag && (tx * 4 + c > ty * 4 + r)) val = -INFINITY;
                s[r][c] = val;
            }
        }

#pragma unroll
        for (int r = 0; r < 4; r++) {
            float mx = fmaxf(fmaxf(s[r][0], s[r][1]), fmaxf(s[r][2], s[r][3]));
#pragma unroll
            for (int off = 8; off >= 1; off >>= 1)
                mx = fmaxf(mx, __shfl_xor_sync(0xffffffffu, mx, off, 16));
            float m_new = fmaxf(m_r[r], mx);
            float corr  = __expf(m_r[r] - m_new);
            float p0 = __expf(s[r][0] - m_new);
            float p1 = __expf(s[r][1] - m_new);
            float p2 = __expf(s[r][2] - m_new);
            float p3 = __expf(s[r][3] - m_new);
            *(float4*)&Ps[ty * 4 + r][tx * 4] = make_float4(p0, p1, p2, p3);
            float psum = p0 + p1 + p2 + p3;
#pragma unroll
            for (int off = 8; off >= 1; off >>= 1)
                psum += __shfl_xor_sync(0xffffffffu, psum, off, 16);
            l_r[r] = l_r[r] * corr + psum;
            m_r[r] = m_new;
#pragma unroll
            for (int c = 0; c < 8; c++) acc[r][c] *= corr;
        }
        __syncwarp();

#pragma unroll 4
        for (int kk = 0; kk < 64; kk++) {
            float4 v0 = *(float4*)&Vs[kk][tx * 4];
            float4 v1 = *(float4*)&Vs[kk][64 + tx * 4];
#pragma unroll
            for (int r = 0; r < 4; r++) {
                float p = Ps[ty * 4 + r][kk];
                acc[r][0] += p * v0.x; acc[r][1] += p * v0.y;
                acc[r][2] += p * v0.z; acc[r][3] += p * v0.w;
                acc[r][4] += p * v1.x; acc[r][5] += p * v1.y;
                acc[r][6] += p * v1.z; acc[r][7] += p * v1.w;
            }
        }
    }

    float* Og = g_O + ((size_t)(b * S_ + q0)) * D_ + h * DH_;
#pragma unroll
    for (int r = 0; r < 4; r++) {
        float inv = 1.0f / l_r[r];
        int row = ty * 4 + r;
        *(float4*)(Og + (size_t)row * D_ + tx * 4) =
            make_float4(acc[r][0] * inv, acc[r][1] * inv, acc[r][2] * inv, acc[r][3] * inv);
        *(float4*)(Og + (size_t)row * D_ + 64 + tx * 4) =
            make_float4(acc[r][4] * inv, acc[r][5] * inv, acc[r][6] * inv, acc[r][7] * inv);
    }
}

// ---------------------------------------------------------------------------
// Launch
// ---------------------------------------------------------------------------
extern "C" void kernel_launch(void* const* d_in, const int* in_sizes, int n_in,
                              void* d_out, int out_size)
{
    const float* x   = (const float*)d_in[0];
    const int*   pos = (const int*)  d_in[1];
    const float* Wq  = (const float*)d_in[2];
    const float* Wk  = (const float*)d_in[3];
    const float* Wv  = (const float*)d_in[4];
    const float* Wo  = (const float*)d_in[5];
    float*       out = (float*)d_out;

    float *Qp, *Kp, *Vp, *Op;
    __nv_bfloat16 *xhi, *xlo, *whi, *wlo, *ohi, *olo;
    cudaGetSymbolAddress((void**)&Qp,  g_Q);
    cudaGetSymbolAddress((void**)&Kp,  g_K);
    cudaGetSymbolAddress((void**)&Vp,  g_V);
    cudaGetSymbolAddress((void**)&Op,  g_O);
    cudaGetSymbolAddress((void**)&xhi, g_xhi);
    cudaGetSymbolAddress((void**)&xlo, g_xlo);
    cudaGetSymbolAddress((void**)&whi, g_Whi);
    cudaGetSymbolAddress((void**)&wlo, g_Wlo);
    cudaGetSymbolAddress((void**)&ohi, g_Ohi);
    cudaGetSymbolAddress((void**)&olo, g_Olo);

    cudaFuncSetAttribute(gemm_mma<true>,  cudaFuncAttributeMaxDynamicSharedMemorySize, GEMM_SMEM);
    cudaFuncSetAttribute(gemm_mma<false>, cudaFuncAttributeMaxDynamicSharedMemorySize, GEMM_SMEM);
    cudaFuncSetAttribute(flash_kernel,    cudaFuncAttributeMaxDynamicSharedMemorySize, FA_SMEM);

    rope_table_kernel<<<(S_ * (DH_ / 2) + 255) / 256, 256>>>(pos);

    const int nx4 = M_ * D_ / 4;
    const int nw4 = D_ * D_ / 4;
    split_kernel<<<(nx4 + 255) / 256, 256>>>(x, xhi, xlo, nx4);
    split_kernel<<<(nw4 + 255) / 256, 256>>>(Wq, whi + 0 * (size_t)D_ * D_, wlo + 0 * (size_t)D_ * D_, nw4);
    split_kernel<<<(nw4 + 255) / 256, 256>>>(Wk, whi + 1 * (size_t)D_ * D_, wlo + 1 * (size_t)D_ * D_, nw4);
    split_kernel<<<(nw4 + 255) / 256, 256>>>(Wv, whi + 2 * (size_t)D_ * D_, wlo + 2 * (size_t)D_ * D_, nw4);
    split_kernel<<<(nw4 + 255) / 256, 256>>>(Wo, whi + 3 * (size_t)D_ * D_, wlo + 3 * (size_t)D_ * D_, nw4);

    dim3 gg(D_ / 128, M_ / 128);  // (16, 32)
    gemm_mma<true ><<<gg, 256, GEMM_SMEM>>>(xhi, xlo, whi + 0 * (size_t)D_ * D_, wlo + 0 * (size_t)D_ * D_, Qp);
    gemm_mma<true ><<<gg, 256, GEMM_SMEM>>>(xhi, xlo, whi + 1 * (size_t)D_ * D_, wlo + 1 * (size_t)D_ * D_, Kp);
    gemm_mma<false><<<gg, 256, GEMM_SMEM>>>(xhi, xlo, whi + 2 * (size_t)D_ * D_, wlo + 2 * (size_t)D_ * D_, Vp);

    flash_kernel<<<dim3(S_ / 64, B_ * H_), 256, FA_SMEM>>>();

    split_kernel<<<(nx4 + 255) / 256, 256>>>(Op, ohi, olo, nx4);
    gemm_mma<false><<<gg, 256, GEMM_SMEM>>>(ohi, olo, whi + 3 * (size_t)D_ * D_, wlo + 3 * (size_t)D_ * D_, out);
}

// round 4
// speedup vs baseline: 2.4853x; 1.5047x over previous
#include <cuda_runtime.h>
#include <cuda_bf16.h>
#include <math.h>
#include <stdint.h>

// Problem constants
#define B_  2
#define S_  2048
#define D_  2048
#define H_  16
#define DH_ 128
#define M_  (B_*S_)   // 4096

// ---------------------------------------------------------------------------
// Scratch (no cudaMalloc allowed)
// ---------------------------------------------------------------------------
__device__ __align__(16) float2 g_rope[S_ * (DH_ / 2)];

__device__ __align__(16) __nv_bfloat16 g_xhi[(size_t)M_ * D_];
__device__ __align__(16) __nv_bfloat16 g_xlo[(size_t)M_ * D_];
__device__ __align__(16) __nv_bfloat16 g_Whi[(size_t)4 * D_ * D_];
__device__ __align__(16) __nv_bfloat16 g_Wlo[(size_t)4 * D_ * D_];
__device__ __align__(16) __nv_bfloat16 g_Qhi[(size_t)M_ * D_];
__device__ __align__(16) __nv_bfloat16 g_Qlo[(size_t)M_ * D_];
__device__ __align__(16) __nv_bfloat16 g_Khi[(size_t)M_ * D_];
__device__ __align__(16) __nv_bfloat16 g_Klo[(size_t)M_ * D_];
__device__ __align__(16) __nv_bfloat16 g_Vhi[(size_t)M_ * D_];
__device__ __align__(16) __nv_bfloat16 g_Vlo[(size_t)M_ * D_];
__device__ __align__(16) __nv_bfloat16 g_Ohi[(size_t)M_ * D_];
__device__ __align__(16) __nv_bfloat16 g_Olo[(size_t)M_ * D_];

// ---------------------------------------------------------------------------
// PTX helpers (compute_103-safe: sm_80-era instructions only)
// ---------------------------------------------------------------------------
__device__ __forceinline__ uint32_t smem_u32(const void* p) {
    uint32_t a;
    asm("{ .reg .u64 t; cvta.to.shared.u64 t, %1; cvt.u32.u64 %0, t; }"
        : "=r"(a) : "l"(p));
    return a;
}

__device__ __forceinline__ void cp16(uint32_t dst, const void* src) {
    asm volatile("cp.async.cg.shared.global [%0], [%1], 16;" :: "r"(dst), "l"(src));
}
__device__ __forceinline__ void cp_commit() { asm volatile("cp.async.commit_group;" ::: "memory"); }
__device__ __forceinline__ void cp_wait1()  { asm volatile("cp.async.wait_group 1;" ::: "memory"); }

__device__ __forceinline__ void ldsm_x4(uint32_t (&r)[4], uint32_t addr) {
    asm volatile("ldmatrix.sync.aligned.m8n8.x4.shared.b16 {%0,%1,%2,%3}, [%4];"
                 : "=r"(r[0]), "=r"(r[1]), "=r"(r[2]), "=r"(r[3]) : "r"(addr));
}
__device__ __forceinline__ void ldsm_x2(uint32_t (&r)[2], uint32_t addr) {
    asm volatile("ldmatrix.sync.aligned.m8n8.x2.shared.b16 {%0,%1}, [%2];"
                 : "=r"(r[0]), "=r"(r[1]) : "r"(addr));
}
__device__ __forceinline__ void ldsm_x4t(uint32_t (&r)[4], uint32_t addr) {
    asm volatile("ldmatrix.sync.aligned.m8n8.x4.trans.shared.b16 {%0,%1,%2,%3}, [%4];"
                 : "=r"(r[0]), "=r"(r[1]), "=r"(r[2]), "=r"(r[3]) : "r"(addr));
}

__device__ __forceinline__ void mma16816(float (&c)[4], const uint32_t (&a)[4],
                                         const uint32_t (&b)[2]) {
    asm volatile(
        "mma.sync.aligned.m16n8k16.row.col.f32.bf16.bf16.f32 "
        "{%0,%1,%2,%3}, {%4,%5,%6,%7}, {%8,%9}, {%0,%1,%2,%3};"
        : "+f"(c[0]), "+f"(c[1]), "+f"(c[2]), "+f"(c[3])
        : "r"(a[0]), "r"(a[1]), "r"(a[2]), "r"(a[3]), "r"(b[0]), "r"(b[1]));
}
__device__ __forceinline__ void mma16816v(float (&c)[4], const uint32_t (&a)[4],
                                          uint32_t b0, uint32_t b1) {
    asm volatile(
        "mma.sync.aligned.m16n8k16.row.col.f32.bf16.bf16.f32 "
        "{%0,%1,%2,%3}, {%4,%5,%6,%7}, {%8,%9}, {%0,%1,%2,%3};"
        : "+f"(c[0]), "+f"(c[1]), "+f"(c[2]), "+f"(c[3])
        : "r"(a[0]), "r"(a[1]), "r"(a[2]), "r"(a[3]), "r"(b0), "r"(b1));
}

__device__ __forceinline__ void split2(float a, float b, uint32_t &hi, uint32_t &lo) {
    __nv_bfloat16 ha = __float2bfloat16_rn(a), hb = __float2bfloat16_rn(b);
    float ra = a - __bfloat162float(ha), rb = b - __bfloat162float(hb);
    __nv_bfloat162 th = __halves2bfloat162(ha, hb);
    __nv_bfloat162 tl = __floats2bfloat162_rn(ra, rb);
    hi = *reinterpret_cast<uint32_t*>(&th);
    lo = *reinterpret_cast<uint32_t*>(&tl);
}

// ---------------------------------------------------------------------------
// RoPE cos/sin table
// ---------------------------------------------------------------------------
__global__ void rope_table_kernel(const int* __restrict__ pos)
{
    int idx = blockIdx.x * blockDim.x + threadIdx.x;
    if (idx >= S_ * (DH_ / 2)) return;
    int s = idx / (DH_ / 2);
    int i = idx % (DH_ / 2);
    float p    = (float)pos[s];
    float freq = powf(1.0f / 10000.0f, (2.0f * (float)i) / (float)DH_);
    float ang  = p * freq;
    g_rope[idx] = make_float2(cosf(ang), sinf(ang));
}

// ---------------------------------------------------------------------------
// fp32 -> bf16 hi/lo split
// ---------------------------------------------------------------------------
__global__ void split_kernel(const float* __restrict__ src,
                             __nv_bfloat16* __restrict__ hi,
                             __nv_bfloat16* __restrict__ lo, int n4)
{
    int i = blockIdx.x * blockDim.x + threadIdx.x;
    if (i >= n4) return;
    float4 v = ((const float4*)src)[i];
    uint32_t h01, l01, h23, l23;
    split2(v.x, v.y, h01, l01);
    split2(v.z, v.w, h23, l23);
    ((uint32_t*)hi)[2 * i]     = h01;
    ((uint32_t*)hi)[2 * i + 1] = h23;
    ((uint32_t*)lo)[2 * i]     = l01;
    ((uint32_t*)lo)[2 * i + 1] = l23;
}

// ---------------------------------------------------------------------------
// bf16x3 GEMM via mma.sync:  C = (Ahi+Alo)[M,K] @ (Bhi+Blo)[N,K]^T
// MODE: 0 = fp32 out, 1 = rope + bf16-split out, 2 = bf16-split out
// ---------------------------------------------------------------------------
#define BK_       32
#define NCHUNK_   (D_ / BK_)            // 64
#define T_STRIDE_ 80
#define TILE_B_   (128 * T_STRIDE_)
#define STAGE_B_  (4 * TILE_B_)
#define GEMM_SMEM (2 * STAGE_B_)

__device__ __forceinline__ void load_stage(
    uint32_t base, const __nv_bfloat16* __restrict__ pAh,
    const __nv_bfloat16* __restrict__ pAl,
    const __nv_bfloat16* __restrict__ pBh,
    const __nv_bfloat16* __restrict__ pBl, int c, int tid)
{
    const __nv_bfloat16* srcs[4] = { pAh + c * BK_, pAl + c * BK_,
                                     pBh + c * BK_, pBl + c * BK_ };
#pragma unroll
    for (int t = 0; t < 4; t++) {
#pragma unroll
        for (int v = 0; v < 2; v++) {
            int idx = tid + v * 256;
            int row = idx >> 2;
            int seg = idx & 3;
            cp16(base + t * TILE_B_ + row * T_STRIDE_ + seg * 16,
                 srcs[t] + (size_t)row * D_ + seg * 8);
        }
    }
}

template <int MODE>
__global__ __launch_bounds__(256, 1) void gemm_mma(
    const __nv_bfloat16* __restrict__ Ahi, const __nv_bfloat16* __restrict__ Alo,
    const __nv_bfloat16* __restrict__ Bhi, const __nv_bfloat16* __restrict__ Blo,
    float* __restrict__ C,
    __nv_bfloat16* __restrict__ Chi, __nv_bfloat16* __restrict__ Clo)
{
    extern __shared__ __align__(128) char smem[];
    const uint32_t sb = smem_u32(smem);

    const int tid    = threadIdx.x;
    const int lane   = tid & 31;
    const int wid    = tid >> 5;
    const int warp_m = wid & 1;
    const int warp_n = wid >> 1;
    const int bm     = blockIdx.y * 128;
    const int bn     = blockIdx.x * 128;

    const __nv_bfloat16* pAh = Ahi + (size_t)bm * D_;
    const __nv_bfloat16* pAl = Alo + (size_t)bm * D_;
    const __nv_bfloat16* pBh = Bhi + (size_t)bn * D_;
    const __nv_bfloat16* pBl = Blo + (size_t)bn * D_;

    float acc[4][4][4];
#pragma unroll
    for (int mt = 0; mt < 4; mt++)
#pragma unroll
        for (int nt = 0; nt < 4; nt++)
#pragma unroll
            for (int q = 0; q < 4; q++) acc[mt][nt][q] = 0.0f;

    load_stage(sb,            pAh, pAl, pBh, pBl, 0, tid); cp_commit();
    load_stage(sb + STAGE_B_, pAh, pAl, pBh, pBl, 1, tid); cp_commit();

    const uint32_t a_lane = (lane & 15) * T_STRIDE_ + (lane >> 4) * 16
                          + warp_m * 64 * T_STRIDE_;
    const uint32_t b_lane = (lane & 7) * T_STRIDE_ + ((lane >> 3) & 1) * 16
                          + warp_n * 32 * T_STRIDE_;

    for (int c = 0; c < NCHUNK_; c++) {
        cp_wait1();
        __syncthreads();
        const uint32_t base = sb + (c & 1) * STAGE_B_;

#pragma unroll
        for (int s = 0; s < 2; s++) {
            const uint32_t abase = base + s * 32 + a_lane;
            const uint32_t bbase = base + 2 * TILE_B_ + s * 32 + b_lane;
            uint32_t ah[4][4], al[4][4], bh[4][2], bl[4][2];
#pragma unroll
            for (int mt = 0; mt < 4; mt++) {
                ldsm_x4(ah[mt], abase + mt * 16 * T_STRIDE_);
                ldsm_x4(al[mt], abase + TILE_B_ + mt * 16 * T_STRIDE_);
            }
#pragma unroll
            for (int nt = 0; nt < 4; nt++) {
                ldsm_x2(bh[nt], bbase + nt * 8 * T_STRIDE_);
                ldsm_x2(bl[nt], bbase + TILE_B_ + nt * 8 * T_STRIDE_);
            }
#pragma unroll
            for (int mt = 0; mt < 4; mt++)
#pragma unroll
                for (int nt = 0; nt < 4; nt++) {
                    mma16816(acc[mt][nt], ah[mt], bh[nt]);
                    mma16816(acc[mt][nt], ah[mt], bl[nt]);
                    mma16816(acc[mt][nt], al[mt], bh[nt]);
                }
        }
        __syncthreads();
        if (c + 2 < NCHUNK_)
            load_stage(base, pAh, pAl, pBh, pBl, c + 2, tid);
        cp_commit();
    }

    const int gid = lane >> 2, tig = lane & 3;
#pragma unroll
    for (int mt = 0; mt < 4; mt++) {
        const int row0 = bm + warp_m * 64 + mt * 16 + gid;
        const int row1 = row0 + 8;
        const int s0 = row0 & (S_ - 1);
        const int s1 = row1 & (S_ - 1);
#pragma unroll
        for (int nt = 0; nt < 4; nt++) {
            const int col  = bn + warp_n * 32 + nt * 8 + tig * 2;
            float c0 = acc[mt][nt][0], c1 = acc[mt][nt][1];
            float c2 = acc[mt][nt][2], c3 = acc[mt][nt][3];
            if (MODE == 1) {
                const int pr = (col & (DH_ - 1)) >> 1;
                float2 csa = g_rope[s0 * (DH_ / 2) + pr];
                float2 csb = g_rope[s1 * (DH_ / 2) + pr];
                float e0 = c0, o0 = c1, e1 = c2, o1 = c3;
                c0 = e0 * csa.x - o0 * csa.y;
                c1 = e0 * csa.y + o0 * csa.x;
                c2 = e1 * csb.x - o1 * csb.y;
                c3 = e1 * csb.y + o1 * csb.x;
            }
            if (MODE == 0) {
                *(float2*)(C + (size_t)row0 * D_ + col) = make_float2(c0, c1);
                *(float2*)(C + (size_t)row1 * D_ + col) = make_float2(c2, c3);
            } else {
                uint32_t h01, l01, h23, l23;
                split2(c0, c1, h01, l01);
                split2(c2, c3, h23, l23);
                *(uint32_t*)(Chi + (size_t)row0 * D_ + col) = h01;
                *(uint32_t*)(Clo + (size_t)row0 * D_ + col) = l01;
                *(uint32_t*)(Chi + (size_t)row1 * D_ + col) = h23;
                *(uint32_t*)(Clo + (size_t)row1 * D_ + col) = l23;
            }
        }
    }
}

// ---------------------------------------------------------------------------
// Flash attention on mma.sync bf16.
// CTA = 128 q rows of one (b,h); 8 warps x 16 rows; key tiles of 64.
// S = QhiKhi + QhiKlo + QloKhi (fp32 acc); softmax fp32;
// O += PhiVhi + PloVhi + PhiVlo (P split in registers from S fragments).
// ---------------------------------------------------------------------------
#define FL_STRIDE 272                    // smem row stride (136 bf16)
#define FL_QTILE  (128 * FL_STRIDE)      // 34816
#define FL_KTILE  (64 * FL_STRIDE)       // 17408
#define FL_STAGE  (4 * FL_KTILE)         // 69632
#define FL_SMEM   (2 * FL_QTILE + 2 * FL_STAGE)  // 208896

__device__ __forceinline__ void flash_load_kv(
    uint32_t base, const __nv_bfloat16* Kh, const __nv_bfloat16* Kl,
    const __nv_bfloat16* Vh, const __nv_bfloat16* Vl, int kt, int tid)
{
    const __nv_bfloat16* srcs[4] = {
        Kh + (size_t)kt * 64 * D_, Kl + (size_t)kt * 64 * D_,
        Vh + (size_t)kt * 64 * D_, Vl + (size_t)kt * 64 * D_ };
#pragma unroll
    for (int t = 0; t < 4; t++) {
#pragma unroll
        for (int v = 0; v < 4; v++) {
            int idx = tid + v * 256;      // 0..1023
            int row = idx >> 4;           // 0..63
            int seg = idx & 15;
            cp16(base + t * FL_KTILE + row * FL_STRIDE + seg * 16,
                 srcs[t] + (size_t)row * D_ + seg * 8);
        }
    }
}

__global__ __launch_bounds__(256, 1) void flash_mma()
{
    extern __shared__ __align__(128) char fsm[];
    const uint32_t sb  = smem_u32(fsm);
    const uint32_t sQh = sb;
    const uint32_t sQl = sb + FL_QTILE;
    const uint32_t sKV = sb + 2 * FL_QTILE;

    const int tid  = threadIdx.x;
    const int lane = tid & 31;
    const int w    = tid >> 5;
    const int gid  = lane >> 2, tig = lane & 3;
    const int bh   = blockIdx.y;
    const int b    = bh >> 4;
    const int h    = bh & 15;
    const int qt   = (int)gridDim.x - 1 - (int)blockIdx.x;   // heavy first
    const int q0   = qt * 128;
    const int nkt  = 2 * qt + 2;

    const __nv_bfloat16* Qh = g_Qhi + ((size_t)(b * S_ + q0)) * D_ + h * DH_;
    const __nv_bfloat16* Ql = g_Qlo + ((size_t)(b * S_ + q0)) * D_ + h * DH_;
    const __nv_bfloat16* Kh = g_Khi + ((size_t)b * S_) * D_ + h * DH_;
    const __nv_bfloat16* Kl = g_Klo + ((size_t)b * S_) * D_ + h * DH_;
    const __nv_bfloat16* Vh = g_Vhi + ((size_t)b * S_) * D_ + h * DH_;
    const __nv_bfloat16* Vl = g_Vlo + ((size_t)b * S_) * D_ + h * DH_;

    // Q tiles + stage 0 (group 0), stage 1 (group 1)
#pragma unroll
    for (int v = 0; v < 8; v++) {
        int idx = tid + v * 256;          // 0..2047
        int row = idx >> 4;
        int seg = idx & 15;
        cp16(sQh + row * FL_STRIDE + seg * 16, Qh + (size_t)row * D_ + seg * 8);
        cp16(sQl + row * FL_STRIDE + seg * 16, Ql + (size_t)row * D_ + seg * 8);
    }
    flash_load_kv(sKV, Kh, Kl, Vh, Vl, 0, tid);
    cp_commit();
    flash_load_kv(sKV + FL_STAGE, Kh, Kl, Vh, Vl, 1, tid);
    cp_commit();

    float accO[16][4];
#pragma unroll
    for (int nt = 0; nt < 16; nt++)
#pragma unroll
        for (int q = 0; q < 4; q++) accO[nt][q] = 0.0f;
    float m0 = -INFINITY, m1 = -INFINITY, l0 = 0.0f, l1 = 0.0f;

    const float scale = 0.08838834764831845f;  // 1/sqrt(128)
    const int rq0 = q0 + w * 16 + gid;
    const int rq1 = rq0 + 8;

    const uint32_t a_lane = (w * 16 + (lane & 15)) * FL_STRIDE + (lane >> 4) * 16;
    const uint32_t kb_lane = ((lane & 7) + (lane >> 4) * 8) * FL_STRIDE
                           + ((lane >> 3) & 1) * 16;
    const uint32_t v_lane = (lane & 15) * FL_STRIDE + (lane >> 4) * 16;

    for (int kt = 0; kt < nkt; kt++) {
        cp_wait1();
        __syncthreads();
        const uint32_t kbh = sKV + (kt & 1) * FL_STAGE;
        const uint32_t kbl = kbh + FL_KTILE;
        const uint32_t vbh = kbh + 2 * FL_KTILE;
        const uint32_t vbl = kbh + 3 * FL_KTILE;

        // ---- S = Q @ K^T (3-term split) ----
        float sf[8][4];
#pragma unroll
        for (int nt = 0; nt < 8; nt++)
#pragma unroll
            for (int q = 0; q < 4; q++) sf[nt][q] = 0.0f;

#pragma unroll
        for (int ks = 0; ks < 8; ks++) {
            uint32_t ah[4], al[4];
            ldsm_x4(ah, sQh + a_lane + ks * 32);
            ldsm_x4(al, sQl + a_lane + ks * 32);
#pragma unroll
            for (int ntp = 0; ntp < 4; ntp++) {
                uint32_t bh4[4], bl4[4];
                ldsm_x4(bh4, kbh + ntp * 16 * FL_STRIDE + kb_lane + ks * 32);
                ldsm_x4(bl4, kbl + ntp * 16 * FL_STRIDE + kb_lane + ks * 32);
                mma16816v(sf[2 * ntp],     ah, bh4[0], bh4[1]);
                mma16816v(sf[2 * ntp],     ah, bl4[0], bl4[1]);
                mma16816v(sf[2 * ntp],     al, bh4[0], bh4[1]);
                mma16816v(sf[2 * ntp + 1], ah, bh4[2], bh4[3]);
                mma16816v(sf[2 * ntp + 1], ah, bl4[2], bl4[3]);
                mma16816v(sf[2 * ntp + 1], al, bh4[2], bh4[3]);
            }
        }

        // ---- scale + causal mask ----
        const bool msk = (kt >= nkt - 2);
#pragma unroll
        for (int nt = 0; nt < 8; nt++) {
            const int col = kt * 64 + nt * 8 + 2 * tig;
            sf[nt][0] *= scale; sf[nt][1] *= scale;
            sf[nt][2] *= scale; sf[nt][3] *= scale;
            if (msk) {
                if (col     > rq0) sf[nt][0] = -INFINITY;
                if (col + 1 > rq0) sf[nt][1] = -INFINITY;
                if (col     > rq1) sf[nt][2] = -INFINITY;
                if (col + 1 > rq1) sf[nt][3] = -INFINITY;
            }
        }

        // ---- online softmax (rows rq0, rq1; reduce over quad lanes) ----
        float mx0 = -INFINITY, mx1 = -INFINITY;
#pragma unroll
        for (int nt = 0; nt < 8; nt++) {
            mx0 = fmaxf(mx0, fmaxf(sf[nt][0], sf[nt][1]));
            mx1 = fmaxf(mx1, fmaxf(sf[nt][2], sf[nt][3]));
        }
        mx0 = fmaxf(mx0, __shfl_xor_sync(0xffffffffu, mx0, 1));
        mx0 = fmaxf(mx0, __shfl_xor_sync(0xffffffffu, mx0, 2));
        mx1 = fmaxf(mx1, __shfl_xor_sync(0xffffffffu, mx1, 1));
        mx1 = fmaxf(mx1, __shfl_xor_sync(0xffffffffu, mx1, 2));

        const float mn0 = fmaxf(m0, mx0), mn1 = fmaxf(m1, mx1);
        const float cr0 = __expf(m0 - mn0), cr1 = __expf(m1 - mn1);

        float sum0 = 0.0f, sum1 = 0.0f;
#pragma unroll
        for (int nt = 0; nt < 8; nt++) {
            sf[nt][0] = __expf(sf[nt][0] - mn0);
            sf[nt][1] = __expf(sf[nt][1] - mn0);
            sf[nt][2] = __expf(sf[nt][2] - mn1);
            sf[nt][3] = __expf(sf[nt][3] - mn1);
            sum0 += sf[nt][0] + sf[nt][1];
            sum1 += sf[nt][2] + sf[nt][3];
        }
        sum0 += __shfl_xor_sync(0xffffffffu, sum0, 1);
        sum0 += __shfl_xor_sync(0xffffffffu, sum0, 2);
        sum1 += __shfl_xor_sync(0xffffffffu, sum1, 1);
        sum1 += __shfl_xor_sync(0xffffffffu, sum1, 2);
        l0 = l0 * cr0 + sum0; m0 = mn0;
        l1 = l1 * cr1 + sum1; m1 = mn1;

#pragma unroll
        for (int nt = 0; nt < 16; nt++) {
            accO[nt][0] *= cr0; accO[nt][1] *= cr0;
            accO[nt][2] *= cr1; accO[nt][3] *= cr1;
        }

        // ---- pack P hi/lo A-fragments (k-steps of 16 keys) ----
        uint32_t pah[4][4], pal[4][4];
#pragma unroll
        for (int j = 0; j < 4; j++) {
            split2(sf[2 * j][0],     sf[2 * j][1],     pah[j][0], pal[j][0]);
            split2(sf[2 * j][2],     sf[2 * j][3],     pah[j][1], pal[j][1]);
            split2(sf[2 * j + 1][0], sf[2 * j + 1][1], pah[j][2], pal[j][2]);
            split2(sf[2 * j + 1][2], sf[2 * j + 1][3], pah[j][3], pal[j][3]);
        }

        // ---- O += P @ V (3-term split), V via ldmatrix trans ----
#pragma unroll
        for (int j = 0; j < 4; j++) {
#pragma unroll
            for (int ntp = 0; ntp < 8; ntp++) {
                uint32_t vh4[4], vl4[4];
                const uint32_t va = 16 * j * FL_STRIDE + ntp * 32 + v_lane;
                ldsm_x4t(vh4, vbh + va);
                ldsm_x4t(vl4, vbl + va);
                mma16816v(accO[2 * ntp],     pah[j], vh4[0], vh4[1]);
                mma16816v(accO[2 * ntp],     pal[j], vh4[0], vh4[1]);
                mma16816v(accO[2 * ntp],     pah[j], vl4[0], vl4[1]);
                mma16816v(accO[2 * ntp + 1], pah[j], vh4[2], vh4[3]);
                mma16816v(accO[2 * ntp + 1], pal[j], vh4[2], vh4[3]);
                mma16816v(accO[2 * ntp + 1], pah[j], vl4[2], vl4[3]);
            }
        }

        __syncthreads();   // all warps done reading this stage
        if (kt + 2 < nkt)
            flash_load_kv(kbh, Kh, Kl, Vh, Vl, kt + 2, tid);
        cp_commit();
    }

    // ---- epilogue: normalize, split to bf16 hi/lo ----
    const float inv0 = 1.0f / l0, inv1 = 1.0f / l1;
    __nv_bfloat16* Oh = g_Ohi + ((size_t)(b * S_ + q0 + w * 16)) * D_ + h * DH_;
    __nv_bfloat16* Ol = g_Olo + ((size_t)(b * S_ + q0 + w * 16)) * D_ + h * DH_;
#pragma unroll
    for (int nt = 0; nt < 16; nt++) {
        const int col = nt * 8 + 2 * tig;
        uint32_t h01, l01, h23, l23;
        split2(accO[nt][0] * inv0, accO[nt][1] * inv0, h01, l01);
        split2(accO[nt][2] * inv1, accO[nt][3] * inv1, h23, l23);
        *(uint32_t*)(Oh + (size_t)gid * D_ + col)       = h01;
        *(uint32_t*)(Ol + (size_t)gid * D_ + col)       = l01;
        *(uint32_t*)(Oh + (size_t)(gid + 8) * D_ + col) = h23;
        *(uint32_t*)(Ol + (size_t)(gid + 8) * D_ + col) = l23;
    }
}

// ---------------------------------------------------------------------------
// Launch
// ---------------------------------------------------------------------------
extern "C" void kernel_launch(void* const* d_in, const int* in_sizes, int n_in,
                              void* d_out, int out_size)
{
    const float* x   = (const float*)d_in[0];
    const int*   pos = (const int*)  d_in[1];
    const float* Wq  = (const float*)d_in[2];
    const float* Wk  = (const float*)d_in[3];
    const float* Wv  = (const float*)d_in[4];
    const float* Wo  = (const float*)d_in[5];
    float*       out = (float*)d_out;

    __nv_bfloat16 *xhi, *xlo, *whi, *wlo;
    __nv_bfloat16 *qhi, *qlo, *khi, *klo, *vhi, *vlo, *ohi, *olo;
    cudaGetSymbolAddress((void**)&xhi, g_xhi);
    cudaGetSymbolAddress((void**)&xlo, g_xlo);
    cudaGetSymbolAddress((void**)&whi, g_Whi);
    cudaGetSymbolAddress((void**)&wlo, g_Wlo);
    cudaGetSymbolAddress((void**)&qhi, g_Qhi);
    cudaGetSymbolAddress((void**)&qlo, g_Qlo);
    cudaGetSymbolAddress((void**)&khi, g_Khi);
    cudaGetSymbolAddress((void**)&klo, g_Klo);
    cudaGetSymbolAddress((void**)&vhi, g_Vhi);
    cudaGetSymbolAddress((void**)&vlo, g_Vlo);
    cudaGetSymbolAddress((void**)&ohi, g_Ohi);
    cudaGetSymbolAddress((void**)&olo, g_Olo);

    cudaFuncSetAttribute(gemm_mma<0>, cudaFuncAttributeMaxDynamicSharedMemorySize, GEMM_SMEM);
    cudaFuncSetAttribute(gemm_mma<1>, cudaFuncAttributeMaxDynamicSharedMemorySize, GEMM_SMEM);
    cudaFuncSetAttribute(gemm_mma<2>, cudaFuncAttributeMaxDynamicSharedMemorySize, GEMM_SMEM);
    cudaFuncSetAttribute(flash_mma,   cudaFuncAttributeMaxDynamicSharedMemorySize, FL_SMEM);

    rope_table_kernel<<<(S_ * (DH_ / 2) + 255) / 256, 256>>>(pos);

    const int nx4 = M_ * D_ / 4;
    const int nw4 = D_ * D_ / 4;
    split_kernel<<<(nx4 + 255) / 256, 256>>>(x, xhi, xlo, nx4);
    split_kernel<<<(nw4 + 255) / 256, 256>>>(Wq, whi + 0 * (size_t)D_ * D_, wlo + 0 * (size_t)D_ * D_, nw4);
    split_kernel<<<(nw4 + 255) / 256, 256>>>(Wk, whi + 1 * (size_t)D_ * D_, wlo + 1 * (size_t)D_ * D_, nw4);
    split_kernel<<<(nw4 + 255) / 256, 256>>>(Wv, whi + 2 * (size_t)D_ * D_, wlo + 2 * (size_t)D_ * D_, nw4);
    split_kernel<<<(nw4 + 255) / 256, 256>>>(Wo, whi + 3 * (size_t)D_ * D_, wlo + 3 * (size_t)D_ * D_, nw4);

    dim3 gg(D_ / 128, M_ / 128);  // (16, 32)
    gemm_mma<1><<<gg, 256, GEMM_SMEM>>>(xhi, xlo, whi + 0 * (size_t)D_ * D_, wlo + 0 * (size_t)D_ * D_,
                                        nullptr, qhi, qlo);
    gemm_mma<1><<<gg, 256, GEMM_SMEM>>>(xhi, xlo, whi + 1 * (size_t)D_ * D_, wlo + 1 * (size_t)D_ * D_,
                                        nullptr, khi, klo);
    gemm_mma<2><<<gg, 256, GEMM_SMEM>>>(xhi, xlo, whi + 2 * (size_t)D_ * D_, wlo + 2 * (size_t)D_ * D_,
                                        nullptr, vhi, vlo);

    flash_mma<<<dim3(S_ / 128, B_ * H_), 256, FL_SMEM>>>();

    gemm_mma<0><<<gg, 256, GEMM_SMEM>>>(ohi, olo, whi + 3 * (size_t)D_ * D_, wlo + 3 * (size_t)D_ * D_,
                                        out, nullptr, nullptr);
}

// round 5
// speedup vs baseline: 2.5182x; 1.0132x over previous
#include <cuda_runtime.h>
#include <cuda_bf16.h>
#include <math.h>
#include <stdint.h>

// Problem constants
#define B_  2
#define S_  2048
#define D_  2048
#define H_  16
#define DH_ 128
#define M_  (B_*S_)   // 4096

// ---------------------------------------------------------------------------
// Scratch (no cudaMalloc allowed)
// ---------------------------------------------------------------------------
__device__ __align__(16) float2 g_rope[S_ * (DH_ / 2)];

__device__ __align__(16) __nv_bfloat16 g_xhi[(size_t)M_ * D_];
__device__ __align__(16) __nv_bfloat16 g_xlo[(size_t)M_ * D_];
__device__ __align__(16) __nv_bfloat16 g_Whi[(size_t)4 * D_ * D_];
__device__ __align__(16) __nv_bfloat16 g_Wlo[(size_t)4 * D_ * D_];
__device__ __align__(16) __nv_bfloat16 g_Qhi[(size_t)M_ * D_];
__device__ __align__(16) __nv_bfloat16 g_Qlo[(size_t)M_ * D_];
__device__ __align__(16) __nv_bfloat16 g_Khi[(size_t)M_ * D_];
__device__ __align__(16) __nv_bfloat16 g_Klo[(size_t)M_ * D_];
__device__ __align__(16) __nv_bfloat16 g_Vhi[(size_t)M_ * D_];
__device__ __align__(16) __nv_bfloat16 g_Vlo[(size_t)M_ * D_];
__device__ __align__(16) __nv_bfloat16 g_Ohi[(size_t)M_ * D_];
__device__ __align__(16) __nv_bfloat16 g_Olo[(size_t)M_ * D_];

// ---------------------------------------------------------------------------
// PTX helpers (compute_103-safe: sm_80-era instructions only)
// ---------------------------------------------------------------------------
__device__ __forceinline__ uint32_t smem_u32(const void* p) {
    uint32_t a;
    asm("{ .reg .u64 t; cvta.to.shared.u64 t, %1; cvt.u32.u64 %0, t; }"
        : "=r"(a) : "l"(p));
    return a;
}

__device__ __forceinline__ void cp16(uint32_t dst, const void* src) {
    asm volatile("cp.async.cg.shared.global [%0], [%1], 16;" :: "r"(dst), "l"(src));
}
__device__ __forceinline__ void cp_commit() { asm volatile("cp.async.commit_group;" ::: "memory"); }
__device__ __forceinline__ void cp_wait1()  { asm volatile("cp.async.wait_group 1;" ::: "memory"); }
__device__ __forceinline__ void cp_wait2()  { asm volatile("cp.async.wait_group 2;" ::: "memory"); }

__device__ __forceinline__ void ldsm_x4(uint32_t (&r)[4], uint32_t addr) {
    asm volatile("ldmatrix.sync.aligned.m8n8.x4.shared.b16 {%0,%1,%2,%3}, [%4];"
                 : "=r"(r[0]), "=r"(r[1]), "=r"(r[2]), "=r"(r[3]) : "r"(addr));
}
__device__ __forceinline__ void ldsm_x2(uint32_t (&r)[2], uint32_t addr) {
    asm volatile("ldmatrix.sync.aligned.m8n8.x2.shared.b16 {%0,%1}, [%2];"
                 : "=r"(r[0]), "=r"(r[1]) : "r"(addr));
}
__device__ __forceinline__ void ldsm_x4t(uint32_t (&r)[4], uint32_t addr) {
    asm volatile("ldmatrix.sync.aligned.m8n8.x4.trans.shared.b16 {%0,%1,%2,%3}, [%4];"
                 : "=r"(r[0]), "=r"(r[1]), "=r"(r[2]), "=r"(r[3]) : "r"(addr));
}

__device__ __forceinline__ void mma16816(float (&c)[4], const uint32_t (&a)[4],
                                         const uint32_t (&b)[2]) {
    asm volatile(
        "mma.sync.aligned.m16n8k16.row.col.f32.bf16.bf16.f32 "
        "{%0,%1,%2,%3}, {%4,%5,%6,%7}, {%8,%9}, {%0,%1,%2,%3};"
        : "+f"(c[0]), "+f"(c[1]), "+f"(c[2]), "+f"(c[3])
        : "r"(a[0]), "r"(a[1]), "r"(a[2]), "r"(a[3]), "r"(b[0]), "r"(b[1]));
}
__device__ __forceinline__ void mma16816v(float (&c)[4], const uint32_t (&a)[4],
                                          uint32_t b0, uint32_t b1) {
    asm volatile(
        "mma.sync.aligned.m16n8k16.row.col.f32.bf16.bf16.f32 "
        "{%0,%1,%2,%3}, {%4,%5,%6,%7}, {%8,%9}, {%0,%1,%2,%3};"
        : "+f"(c[0]), "+f"(c[1]), "+f"(c[2]), "+f"(c[3])
        : "r"(a[0]), "r"(a[1]), "r"(a[2]), "r"(a[3]), "r"(b0), "r"(b1));
}

__device__ __forceinline__ void split2(float a, float b, uint32_t &hi, uint32_t &lo) {
    __nv_bfloat16 ha = __float2bfloat16_rn(a), hb = __float2bfloat16_rn(b);
    float ra = a - __bfloat162float(ha), rb = b - __bfloat162float(hb);
    __nv_bfloat162 th = __halves2bfloat162(ha, hb);
    __nv_bfloat162 tl = __floats2bfloat162_rn(ra, rb);
    hi = *reinterpret_cast<uint32_t*>(&th);
    lo = *reinterpret_cast<uint32_t*>(&tl);
}

// ---------------------------------------------------------------------------
// RoPE cos/sin table
// ---------------------------------------------------------------------------
__global__ void rope_table_kernel(const int* __restrict__ pos)
{
    int idx = blockIdx.x * blockDim.x + threadIdx.x;
    if (idx >= S_ * (DH_ / 2)) return;
    int s = idx / (DH_ / 2);
    int i = idx % (DH_ / 2);
    float p    = (float)pos[s];
    float freq = powf(1.0f / 10000.0f, (2.0f * (float)i) / (float)DH_);
    float ang  = p * freq;
    g_rope[idx] = make_float2(cosf(ang), sinf(ang));
}

// ---------------------------------------------------------------------------
// fp32 -> bf16 hi/lo splits
// ---------------------------------------------------------------------------
__global__ void split_kernel(const float* __restrict__ src,
                             __nv_bfloat16* __restrict__ hi,
                             __nv_bfloat16* __restrict__ lo, int n4)
{
    int i = blockIdx.x * blockDim.x + threadIdx.x;
    if (i >= n4) return;
    float4 v = ((const float4*)src)[i];
    uint32_t h01, l01, h23, l23;
    split2(v.x, v.y, h01, l01);
    split2(v.z, v.w, h23, l23);
    ((uint32_t*)hi)[2 * i]     = h01;
    ((uint32_t*)hi)[2 * i + 1] = h23;
    ((uint32_t*)lo)[2 * i]     = l01;
    ((uint32_t*)lo)[2 * i + 1] = l23;
}

// Fused split for the 4 weight matrices (blockIdx.y selects the weight)
__global__ void split4_kernel(const float* __restrict__ s0, const float* __restrict__ s1,
                              const float* __restrict__ s2, const float* __restrict__ s3,
                              __nv_bfloat16* __restrict__ hi,
                              __nv_bfloat16* __restrict__ lo, int n4)
{
    int i = blockIdx.x * blockDim.x + threadIdx.x;
    if (i >= n4) return;
    const int y = blockIdx.y;
    const float* src = (y == 0) ? s0 : (y == 1) ? s1 : (y == 2) ? s2 : s3;
    const size_t off = (size_t)y * ((size_t)D_ * D_ / 2);   // in uint32 units
    float4 v = ((const float4*)src)[i];
    uint32_t h01, l01, h23, l23;
    split2(v.x, v.y, h01, l01);
    split2(v.z, v.w, h23, l23);
    ((uint32_t*)hi)[off + 2 * i]     = h01;
    ((uint32_t*)hi)[off + 2 * i + 1] = h23;
    ((uint32_t*)lo)[off + 2 * i]     = l01;
    ((uint32_t*)lo)[off + 2 * i + 1] = l23;
}

// ---------------------------------------------------------------------------
// bf16x3 GEMM via mma.sync:  C = (Ahi+Alo)[M,K] @ (Bhi+Blo)[N,K]^T
// CTA tile 256x128, 512 threads (16 warps = 4m x 4n, warp tile 64x32),
// BK=32, 3-stage cp.async pipeline.
// MODE: 0 = fp32 out, 1 = rope + bf16-split out, 2 = bf16-split out
// ---------------------------------------------------------------------------
#define BK_       32
#define NCHUNK_   (D_ / BK_)            // 64
#define T_STRIDE_ 80
#define A_TILE_   (256 * T_STRIDE_)      // 20480
#define B_TILE_   (128 * T_STRIDE_)      // 10240
#define STAGE_B_  (2 * A_TILE_ + 2 * B_TILE_)  // 61440
#define NSTAGE_   3
#define GEMM_SMEM (NSTAGE_ * STAGE_B_)   // 184320

__device__ __forceinline__ void load_stage(
    uint32_t base, const __nv_bfloat16* __restrict__ pAh,
    const __nv_bfloat16* __restrict__ pAl,
    const __nv_bfloat16* __restrict__ pBh,
    const __nv_bfloat16* __restrict__ pBl, int c, int tid)
{
    // A tiles: 256 rows x 4 segs = 1024 cp16 each
#pragma unroll
    for (int v = 0; v < 2; v++) {
        int idx = tid + v * 512;
        int row = idx >> 2;
        int seg = idx & 3;
        const size_t go = (size_t)row * D_ + c * BK_ + seg * 8;
        const uint32_t so = row * T_STRIDE_ + seg * 16;
        cp16(base + so,            pAh + go);
        cp16(base + A_TILE_ + so,  pAl + go);
    }
    // B tiles: 128 rows x 4 segs = 512 cp16 each
    {
        int row = tid >> 2;
        int seg = tid & 3;
        const size_t go = (size_t)row * D_ + c * BK_ + seg * 8;
        const uint32_t so = row * T_STRIDE_ + seg * 16;
        cp16(base + 2 * A_TILE_ + so,            pBh + go);
        cp16(base + 2 * A_TILE_ + B_TILE_ + so,  pBl + go);
    }
}

template <int MODE>
__global__ __launch_bounds__(512) void gemm_mma(
    const __nv_bfloat16* __restrict__ Ahi, const __nv_bfloat16* __restrict__ Alo,
    const __nv_bfloat16* __restrict__ Bhi, const __nv_bfloat16* __restrict__ Blo,
    float* __restrict__ C,
    __nv_bfloat16* __restrict__ Chi, __nv_bfloat16* __restrict__ Clo)
{
    extern __shared__ __align__(128) char smem[];
    const uint32_t sb = smem_u32(smem);

    const int tid    = threadIdx.x;
    const int lane   = tid & 31;
    const int wid    = tid >> 5;
    const int warp_m = wid & 3;      // 4 x 64 rows
    const int warp_n = wid >> 2;     // 4 x 32 cols
    const int bm     = blockIdx.y * 256;
    const int bn     = blockIdx.x * 128;

    const __nv_bfloat16* pAh = Ahi + (size_t)bm * D_;
    const __nv_bfloat16* pAl = Alo + (size_t)bm * D_;
    const __nv_bfloat16* pBh = Bhi + (size_t)bn * D_;
    const __nv_bfloat16* pBl = Blo + (size_t)bn * D_;

    float acc[4][4][4];
#pragma unroll
    for (int mt = 0; mt < 4; mt++)
#pragma unroll
        for (int nt = 0; nt < 4; nt++)
#pragma unroll
            for (int q = 0; q < 4; q++) acc[mt][nt][q] = 0.0f;

    load_stage(sb,                pAh, pAl, pBh, pBl, 0, tid); cp_commit();
    load_stage(sb + STAGE_B_,     pAh, pAl, pBh, pBl, 1, tid); cp_commit();
    load_stage(sb + 2 * STAGE_B_, pAh, pAl, pBh, pBl, 2, tid); cp_commit();

    const uint32_t a_lane = (lane & 15) * T_STRIDE_ + (lane >> 4) * 16
                          + warp_m * 64 * T_STRIDE_;
    const uint32_t b_lane = (lane & 7) * T_STRIDE_ + ((lane >> 3) & 1) * 16
                          + warp_n * 32 * T_STRIDE_;

    int stage = 0;
    for (int c = 0; c < NCHUNK_; c++) {
        cp_wait2();
        __syncthreads();
        const uint32_t base = sb + stage * STAGE_B_;

#pragma unroll
        for (int s = 0; s < 2; s++) {
            const uint32_t abase = base + s * 32 + a_lane;
            const uint32_t bbase = base + 2 * A_TILE_ + s * 32 + b_lane;
            uint32_t ah[4][4], al[4][4], bh[4][2], bl[4][2];
#pragma unroll
            for (int mt = 0; mt < 4; mt++) {
                ldsm_x4(ah[mt], abase + mt * 16 * T_STRIDE_);
                ldsm_x4(al[mt], abase + A_TILE_ + mt * 16 * T_STRIDE_);
            }
#pragma unroll
            for (int nt = 0; nt < 4; nt++) {
                ldsm_x2(bh[nt], bbase + nt * 8 * T_STRIDE_);
                ldsm_x2(bl[nt], bbase + B_TILE_ + nt * 8 * T_STRIDE_);
            }
#pragma unroll
            for (int mt = 0; mt < 4; mt++)
#pragma unroll
                for (int nt = 0; nt < 4; nt++) {
                    mma16816(acc[mt][nt], ah[mt], bh[nt]);
                    mma16816(acc[mt][nt], ah[mt], bl[nt]);
                    mma16816(acc[mt][nt], al[mt], bh[nt]);
                }
        }
        __syncthreads();
        if (c + 3 < NCHUNK_)
            load_stage(base, pAh, pAl, pBh, pBl, c + 3, tid);
        cp_commit();
        stage = (stage == 2) ? 0 : stage + 1;
    }

    const int gid = lane >> 2, tig = lane & 3;
#pragma unroll
    for (int mt = 0; mt < 4; mt++) {
        const int row0 = bm + warp_m * 64 + mt * 16 + gid;
        const int row1 = row0 + 8;
        const int s0 = row0 & (S_ - 1);
        const int s1 = row1 & (S_ - 1);
#pragma unroll
        for (int nt = 0; nt < 4; nt++) {
            const int col  = bn + warp_n * 32 + nt * 8 + tig * 2;
            float c0 = acc[mt][nt][0], c1 = acc[mt][nt][1];
            float c2 = acc[mt][nt][2], c3 = acc[mt][nt][3];
            if (MODE == 1) {
                const int pr = (col & (DH_ - 1)) >> 1;
                float2 csa = g_rope[s0 * (DH_ / 2) + pr];
                float2 csb = g_rope[s1 * (DH_ / 2) + pr];
                float e0 = c0, o0 = c1, e1 = c2, o1 = c3;
                c0 = e0 * csa.x - o0 * csa.y;
                c1 = e0 * csa.y + o0 * csa.x;
                c2 = e1 * csb.x - o1 * csb.y;
                c3 = e1 * csb.y + o1 * csb.x;
            }
            if (MODE == 0) {
                *(float2*)(C + (size_t)row0 * D_ + col) = make_float2(c0, c1);
                *(float2*)(C + (size_t)row1 * D_ + col) = make_float2(c2, c3);
            } else {
                uint32_t h01, l01, h23, l23;
                split2(c0, c1, h01, l01);
                split2(c2, c3, h23, l23);
                *(uint32_t*)(Chi + (size_t)row0 * D_ + col) = h01;
                *(uint32_t*)(Clo + (size_t)row0 * D_ + col) = l01;
                *(uint32_t*)(Chi + (size_t)row1 * D_ + col) = h23;
                *(uint32_t*)(Clo + (size_t)row1 * D_ + col) = l23;
            }
        }
    }
}

// ---------------------------------------------------------------------------
// Flash attention on mma.sync bf16.
// CTA = 256 q rows of one (b,h); 512 threads = 16 warps x 16 rows;
// key tiles of 32, double-buffered cp.async.
// ---------------------------------------------------------------------------
#define FL_STRIDE 272                    // smem row stride (136 bf16)
#define FL_QTILE  (256 * FL_STRIDE)      // 69632
#define FL_KTILE  (32 * FL_STRIDE)       // 8704
#define FL_STAGE  (4 * FL_KTILE)         // 34816
#define FL_SMEM   (2 * FL_QTILE + 2 * FL_STAGE)  // 208896

__device__ __forceinline__ void flash_load_kv(
    uint32_t base, const __nv_bfloat16* Kh, const __nv_bfloat16* Kl,
    const __nv_bfloat16* Vh, const __nv_bfloat16* Vl, int kt, int tid)
{
    const int row = tid >> 4;             // 0..31
    const int seg = tid & 15;
    const size_t go = ((size_t)kt * 32 + row) * D_ + seg * 8;
    const uint32_t so = row * FL_STRIDE + seg * 16;
    cp16(base + so,                 Kh + go);
    cp16(base + FL_KTILE + so,      Kl + go);
    cp16(base + 2 * FL_KTILE + so,  Vh + go);
    cp16(base + 3 * FL_KTILE + so,  Vl + go);
}

__global__ __launch_bounds__(512) void flash_mma()
{
    extern __shared__ __align__(128) char fsm[];
    const uint32_t sb  = smem_u32(fsm);
    const uint32_t sQh = sb;
    const uint32_t sQl = sb + FL_QTILE;
    const uint32_t sKV = sb + 2 * FL_QTILE;

    const int tid  = threadIdx.x;
    const int lane = tid & 31;
    const int w    = tid >> 5;            // 0..15
    const int gid  = lane >> 2, tig = lane & 3;
    const int bh   = blockIdx.y;
    const int b    = bh >> 4;
    const int h    = bh & 15;
    const int qt   = (int)gridDim.x - 1 - (int)blockIdx.x;   // heavy first
    const int q0   = qt * 256;
    const int nkt  = 8 * (qt + 1);

    const __nv_bfloat16* Qh = g_Qhi + ((size_t)(b * S_ + q0)) * D_ + h * DH_;
    const __nv_bfloat16* Ql = g_Qlo + ((size_t)(b * S_ + q0)) * D_ + h * DH_;
    const __nv_bfloat16* Kh = g_Khi + ((size_t)b * S_) * D_ + h * DH_;
    const __nv_bfloat16* Kl = g_Klo + ((size_t)b * S_) * D_ + h * DH_;
    const __nv_bfloat16* Vh = g_Vhi + ((size_t)b * S_) * D_ + h * DH_;
    const __nv_bfloat16* Vl = g_Vlo + ((size_t)b * S_) * D_ + h * DH_;

    // Q tiles (256 rows x 128 cols, hi+lo) + first two KV stages
#pragma unroll
    for (int v = 0; v < 8; v++) {
        int idx = tid + v * 512;          // 0..4095
        int row = idx >> 4;               // 0..255
        int seg = idx & 15;
        const size_t go = (size_t)row * D_ + seg * 8;
        const uint32_t so = row * FL_STRIDE + seg * 16;
        cp16(sQh + so, Qh + go);
        cp16(sQl + so, Ql + go);
    }
    flash_load_kv(sKV, Kh, Kl, Vh, Vl, 0, tid);
    cp_commit();
    flash_load_kv(sKV + FL_STAGE, Kh, Kl, Vh, Vl, 1, tid);
    cp_commit();

    float accO[16][4];
#pragma unroll
    for (int nt = 0; nt < 16; nt++)
#pragma unroll
        for (int q = 0; q < 4; q++) accO[nt][q] = 0.0f;
    float m0 = -INFINITY, m1 = -INFINITY, l0 = 0.0f, l1 = 0.0f;

    const float scale = 0.08838834764831845f;  // 1/sqrt(128)
    const int rq0 = q0 + w * 16 + gid;
    const int rq1 = rq0 + 8;

    const uint32_t a_lane = (w * 16 + (lane & 15)) * FL_STRIDE + (lane >> 4) * 16;
    const uint32_t kb_lane = ((lane & 7) + (lane >> 4) * 8) * FL_STRIDE
                           + ((lane >> 3) & 1) * 16;
    const uint32_t v_lane = (lane & 15) * FL_STRIDE + (lane >> 4) * 16;

    for (int kt = 0; kt < nkt; kt++) {
        cp_wait1();
        __syncthreads();
        const uint32_t kbh = sKV + (kt & 1) * FL_STAGE;
        const uint32_t kbl = kbh + FL_KTILE;
        const uint32_t vbh = kbh + 2 * FL_KTILE;
        const uint32_t vbl = kbh + 3 * FL_KTILE;

        // ---- S = Q @ K^T (3-term split), 32 keys ----
        float sf[4][4];
#pragma unroll
        for (int nt = 0; nt < 4; nt++)
#pragma unroll
            for (int q = 0; q < 4; q++) sf[nt][q] = 0.0f;

#pragma unroll
        for (int ks = 0; ks < 8; ks++) {
            uint32_t ah[4], al[4];
            ldsm_x4(ah, sQh + a_lane + ks * 32);
            ldsm_x4(al, sQl + a_lane + ks * 32);
#pragma unroll
            for (int ntp = 0; ntp < 2; ntp++) {
                uint32_t bh4[4], bl4[4];
                ldsm_x4(bh4, kbh + ntp * 16 * FL_STRIDE + kb_lane + ks * 32);
                ldsm_x4(bl4, kbl + ntp * 16 * FL_STRIDE + kb_lane + ks * 32);
                mma16816v(sf[2 * ntp],     ah, bh4[0], bh4[1]);
                mma16816v(sf[2 * ntp],     ah, bl4[0], bl4[1]);
                mma16816v(sf[2 * ntp],     al, bh4[0], bh4[1]);
                mma16816v(sf[2 * ntp + 1], ah, bh4[2], bh4[3]);
                mma16816v(sf[2 * ntp + 1], ah, bl4[2], bl4[3]);
                mma16816v(sf[2 * ntp + 1], al, bh4[2], bh4[3]);
            }
        }

        // ---- scale + causal mask ----
        const bool msk = (kt >= nkt - 8);
#pragma unroll
        for (int nt = 0; nt < 4; nt++) {
            const int col = kt * 32 + nt * 8 + 2 * tig;
            sf[nt][0] *= scale; sf[nt][1] *= scale;
            sf[nt][2] *= scale; sf[nt][3] *= scale;
            if (msk) {
                if (col     > rq0) sf[nt][0] = -INFINITY;
                if (col + 1 > rq0) sf[nt][1] = -INFINITY;
                if (col     > rq1) sf[nt][2] = -INFINITY;
                if (col + 1 > rq1) sf[nt][3] = -INFINITY;
            }
        }

        // ---- online softmax (rows rq0, rq1; reduce over quad lanes) ----
        float mx0 = -INFINITY, mx1 = -INFINITY;
#pragma unroll
        for (int nt = 0; nt < 4; nt++) {
            mx0 = fmaxf(mx0, fmaxf(sf[nt][0], sf[nt][1]));
            mx1 = fmaxf(mx1, fmaxf(sf[nt][2], sf[nt][3]));
        }
        mx0 = fmaxf(mx0, __shfl_xor_sync(0xffffffffu, mx0, 1));
        mx0 = fmaxf(mx0, __shfl_xor_sync(0xffffffffu, mx0, 2));
        mx1 = fmaxf(mx1, __shfl_xor_sync(0xffffffffu, mx1, 1));
        mx1 = fmaxf(mx1, __shfl_xor_sync(0xffffffffu, mx1, 2));

        const float mn0 = fmaxf(m0, mx0), mn1 = fmaxf(m1, mx1);
        const float cr0 = __expf(m0 - mn0), cr1 = __expf(m1 - mn1);

        float sum0 = 0.0f, sum1 = 0.0f;
#pragma unroll
        for (int nt = 0; nt < 4; nt++) {
            sf[nt][0] = __expf(sf[nt][0] - mn0);
            sf[nt][1] = __expf(sf[nt][1] - mn0);
            sf[nt][2] = __expf(sf[nt][2] - mn1);
            sf[nt][3] = __expf(sf[nt][3] - mn1);
            sum0 += sf[nt][0] + sf[nt][1];
            sum1 += sf[nt][2] + sf[nt][3];
        }
        sum0 += __shfl_xor_sync(0xffffffffu, sum0, 1);
        sum0 += __shfl_xor_sync(0xffffffffu, sum0, 2);
        sum1 += __shfl_xor_sync(0xffffffffu, sum1, 1);
        sum1 += __shfl_xor_sync(0xffffffffu, sum1, 2);
        l0 = l0 * cr0 + sum0; m0 = mn0;
        l1 = l1 * cr1 + sum1; m1 = mn1;

#pragma unroll
        for (int nt = 0; nt < 16; nt++) {
            accO[nt][0] *= cr0; accO[nt][1] *= cr0;
            accO[nt][2] *= cr1; accO[nt][3] *= cr1;
        }

        // ---- pack P hi/lo A-fragments (2 k-steps of 16 keys) ----
        uint32_t pah[2][4], pal[2][4];
#pragma unroll
        for (int j = 0; j < 2; j++) {
            split2(sf[2 * j][0],     sf[2 * j][1],     pah[j][0], pal[j][0]);
            split2(sf[2 * j][2],     sf[2 * j][3],     pah[j][1], pal[j][1]);
            split2(sf[2 * j + 1][0], sf[2 * j + 1][1], pah[j][2], pal[j][2]);
            split2(sf[2 * j + 1][2], sf[2 * j + 1][3], pah[j][3], pal[j][3]);
        }

        // ---- O += P @ V (3-term split), V via ldmatrix trans ----
#pragma unroll
        for (int j = 0; j < 2; j++) {
#pragma unroll
            for (int ntp = 0; ntp < 8; ntp++) {
                uint32_t vh4[4], vl4[4];
                const uint32_t va = 16 * j * FL_STRIDE + ntp * 32 + v_lane;
                ldsm_x4t(vh4, vbh + va);
                ldsm_x4t(vl4, vbl + va);
                mma16816v(accO[2 * ntp],     pah[j], vh4[0], vh4[1]);
                mma16816v(accO[2 * ntp],     pal[j], vh4[0], vh4[1]);
                mma16816v(accO[2 * ntp],     pah[j], vl4[0], vl4[1]);
                mma16816v(accO[2 * ntp + 1], pah[j], vh4[2], vh4[3]);
                mma16816v(accO[2 * ntp + 1], pal[j], vh4[2], vh4[3]);
                mma16816v(accO[2 * ntp + 1], pah[j], vl4[2], vl4[3]);
            }
        }

        __syncthreads();   // all warps done reading this stage
        if (kt + 2 < nkt)
            flash_load_kv(kbh, Kh, Kl, Vh, Vl, kt + 2, tid);
        cp_commit();
    }

    // ---- epilogue: normalize, split to bf16 hi/lo ----
    const float inv0 = 1.0f / l0, inv1 = 1.0f / l1;
    __nv_bfloat16* Oh = g_Ohi + ((size_t)(b * S_ + q0 + w * 16)) * D_ + h * DH_;
    __nv_bfloat16* Ol = g_Olo + ((size_t)(b * S_ + q0 + w * 16)) * D_ + h * DH_;
#pragma unroll
    for (int nt = 0; nt < 16; nt++) {
        const int col = nt * 8 + 2 * tig;
        uint32_t h01, l01, h23, l23;
        split2(accO[nt][0] * inv0, accO[nt][1] * inv0, h01, l01);
        split2(accO[nt][2] * inv1, accO[nt][3] * inv1, h23, l23);
        *(uint32_t*)(Oh + (size_t)gid * D_ + col)       = h01;
        *(uint32_t*)(Ol + (size_t)gid * D_ + col)       = l01;
        *(uint32_t*)(Oh + (size_t)(gid + 8) * D_ + col) = h23;
        *(uint32_t*)(Ol + (size_t)(gid + 8) * D_ + col) = l23;
    }
}

// ---------------------------------------------------------------------------
// Launch
// ---------------------------------------------------------------------------
extern "C" void kernel_launch(void* const* d_in, const int* in_sizes, int n_in,
                              void* d_out, int out_size)
{
    const float* x   = (const float*)d_in[0];
    const int*   pos = (const int*)  d_in[1];
    const float* Wq  = (const float*)d_in[2];
    const float* Wk  = (const float*)d_in[3];
    const float* Wv  = (const float*)d_in[4];
    const float* Wo  = (const float*)d_in[5];
    float*       out = (float*)d_out;

    __nv_bfloat16 *xhi, *xlo, *whi, *wlo;
    __nv_bfloat16 *qhi, *qlo, *khi, *klo, *vhi, *vlo, *ohi, *olo;
    cudaGetSymbolAddress((void**)&xhi, g_xhi);
    cudaGetSymbolAddress((void**)&xlo, g_xlo);
    cudaGetSymbolAddress((void**)&whi, g_Whi);
    cudaGetSymbolAddress((void**)&wlo, g_Wlo);
    cudaGetSymbolAddress((void**)&qhi, g_Qhi);
    cudaGetSymbolAddress((void**)&qlo, g_Qlo);
    cudaGetSymbolAddress((void**)&khi, g_Khi);
    cudaGetSymbolAddress((void**)&klo, g_Klo);
    cudaGetSymbolAddress((void**)&vhi, g_Vhi);
    cudaGetSymbolAddress((void**)&vlo, g_Vlo);
    cudaGetSymbolAddress((void**)&ohi, g_Ohi);
    cudaGetSymbolAddress((void**)&olo, g_Olo);

    cudaFuncSetAttribute(gemm_mma<0>, cudaFuncAttributeMaxDynamicSharedMemorySize, GEMM_SMEM);
    cudaFuncSetAttribute(gemm_mma<1>, cudaFuncAttributeMaxDynamicSharedMemorySize, GEMM_SMEM);
    cudaFuncSetAttribute(gemm_mma<2>, cudaFuncAttributeMaxDynamicSharedMemorySize, GEMM_SMEM);
    cudaFuncSetAttribute(flash_mma,   cudaFuncAttributeMaxDynamicSharedMemorySize, FL_SMEM);

    const int nx4 = M_ * D_ / 4;
    const int nw4 = D_ * D_ / 4;

    // Launch order chosen so ncu (-s 5 -c 1) captures gemm_mma<2> (V projection).
    rope_table_kernel<<<(S_ * (DH_ / 2) + 255) / 256, 256>>>(pos);
    split_kernel<<<(nx4 + 255) / 256, 256>>>(x, xhi, xlo, nx4);
    split4_kernel<<<dim3((nw4 + 255) / 256, 4), 256>>>(Wq, Wk, Wv, Wo, whi, wlo, nw4);

    dim3 gg(D_ / 128, M_ / 256);  // (16, 16)
    gemm_mma<1><<<gg, 512, GEMM_SMEM>>>(xhi, xlo, whi + 0 * (size_t)D_ * D_, wlo + 0 * (size_t)D_ * D_,
                                        nullptr, qhi, qlo);
    gemm_mma<1><<<gg, 512, GEMM_SMEM>>>(xhi, xlo, whi + 1 * (size_t)D_ * D_, wlo + 1 * (size_t)D_ * D_,
                                        nullptr, khi, klo);
    gemm_mma<2><<<gg, 512, GEMM_SMEM>>>(xhi, xlo, whi + 2 * (size_t)D_ * D_, wlo + 2 * (size_t)D_ * D_,
                                        nullptr, vhi, vlo);

    flash_mma<<<dim3(S_ / 256, B_ * H_), 512, FL_SMEM>>>();

    gemm_mma<0><<<gg, 512, GEMM_SMEM>>>(ohi, olo, whi + 3 * (size_t)D_ * D_, wlo + 3 * (size_t)D_ * D_,
                                        out, nullptr, nullptr);
}

// round 6
// speedup vs baseline: 2.5781x; 1.0238x over previous
#include <cuda_runtime.h>
#include <cuda_bf16.h>
#include <math.h>
#include <stdint.h>

// Problem constants
#define B_  2
#define S_  2048
#define D_  2048
#define H_  16
#define DH_ 128
#define M_  (B_*S_)   // 4096

// ---------------------------------------------------------------------------
// Scratch (no cudaMalloc allowed)
// ---------------------------------------------------------------------------
__device__ __align__(16) float2 g_rope[S_ * (DH_ / 2)];

__device__ __align__(16) __nv_bfloat16 g_xhi[(size_t)M_ * D_];
__device__ __align__(16) __nv_bfloat16 g_xlo[(size_t)M_ * D_];
__device__ __align__(16) __nv_bfloat16 g_Whi[(size_t)4 * D_ * D_];
__device__ __align__(16) __nv_bfloat16 g_Wlo[(size_t)4 * D_ * D_];
__device__ __align__(16) __nv_bfloat16 g_Qhi[(size_t)M_ * D_];
__device__ __align__(16) __nv_bfloat16 g_Qlo[(size_t)M_ * D_];
__device__ __align__(16) __nv_bfloat16 g_Khi[(size_t)M_ * D_];
__device__ __align__(16) __nv_bfloat16 g_Klo[(size_t)M_ * D_];
__device__ __align__(16) __nv_bfloat16 g_Vhi[(size_t)M_ * D_];
__device__ __align__(16) __nv_bfloat16 g_Vlo[(size_t)M_ * D_];
__device__ __align__(16) __nv_bfloat16 g_Ohi[(size_t)M_ * D_];
__device__ __align__(16) __nv_bfloat16 g_Olo[(size_t)M_ * D_];

// ---------------------------------------------------------------------------
// PTX helpers (compute_103-safe: sm_80-era instructions only)
// ---------------------------------------------------------------------------
__device__ __forceinline__ uint32_t smem_u32(const void* p) {
    uint32_t a;
    asm("{ .reg .u64 t; cvta.to.shared.u64 t, %1; cvt.u32.u64 %0, t; }"
        : "=r"(a) : "l"(p));
    return a;
}

__device__ __forceinline__ void cp16(uint32_t dst, const void* src) {
    asm volatile("cp.async.cg.shared.global [%0], [%1], 16;" :: "r"(dst), "l"(src));
}
__device__ __forceinline__ void cp_commit() { asm volatile("cp.async.commit_group;" ::: "memory"); }
__device__ __forceinline__ void cp_wait1()  { asm volatile("cp.async.wait_group 1;" ::: "memory"); }

__device__ __forceinline__ void ldsm_x4(uint32_t (&r)[4], uint32_t addr) {
    asm volatile("ldmatrix.sync.aligned.m8n8.x4.shared.b16 {%0,%1,%2,%3}, [%4];"
                 : "=r"(r[0]), "=r"(r[1]), "=r"(r[2]), "=r"(r[3]) : "r"(addr));
}
__device__ __forceinline__ void ldsm_x2(uint32_t (&r)[2], uint32_t addr) {
    asm volatile("ldmatrix.sync.aligned.m8n8.x2.shared.b16 {%0,%1}, [%2];"
                 : "=r"(r[0]), "=r"(r[1]) : "r"(addr));
}
__device__ __forceinline__ void ldsm_x4t(uint32_t (&r)[4], uint32_t addr) {
    asm volatile("ldmatrix.sync.aligned.m8n8.x4.trans.shared.b16 {%0,%1,%2,%3}, [%4];"
                 : "=r"(r[0]), "=r"(r[1]), "=r"(r[2]), "=r"(r[3]) : "r"(addr));
}

__device__ __forceinline__ void mma16816(float (&c)[4], const uint32_t (&a)[4],
                                         const uint32_t (&b)[2]) {
    asm volatile(
        "mma.sync.aligned.m16n8k16.row.col.f32.bf16.bf16.f32 "
        "{%0,%1,%2,%3}, {%4,%5,%6,%7}, {%8,%9}, {%0,%1,%2,%3};"
        : "+f"(c[0]), "+f"(c[1]), "+f"(c[2]), "+f"(c[3])
        : "r"(a[0]), "r"(a[1]), "r"(a[2]), "r"(a[3]), "r"(b[0]), "r"(b[1]));
}
__device__ __forceinline__ void mma16816v(float (&c)[4], const uint32_t (&a)[4],
                                          uint32_t b0, uint32_t b1) {
    asm volatile(
        "mma.sync.aligned.m16n8k16.row.col.f32.bf16.bf16.f32 "
        "{%0,%1,%2,%3}, {%4,%5,%6,%7}, {%8,%9}, {%0,%1,%2,%3};"
        : "+f"(c[0]), "+f"(c[1]), "+f"(c[2]), "+f"(c[3])
        : "r"(a[0]), "r"(a[1]), "r"(a[2]), "r"(a[3]), "r"(b0), "r"(b1));
}

__device__ __forceinline__ void split2(float a, float b, uint32_t &hi, uint32_t &lo) {
    __nv_bfloat16 ha = __float2bfloat16_rn(a), hb = __float2bfloat16_rn(b);
    float ra = a - __bfloat162float(ha), rb = b - __bfloat162float(hb);
    __nv_bfloat162 th = __halves2bfloat162(ha, hb);
    __nv_bfloat162 tl = __floats2bfloat162_rn(ra, rb);
    hi = *reinterpret_cast<uint32_t*>(&th);
    lo = *reinterpret_cast<uint32_t*>(&tl);
}

// ---------------------------------------------------------------------------
// RoPE cos/sin table
// ---------------------------------------------------------------------------
__global__ void rope_table_kernel(const int* __restrict__ pos)
{
    int idx = blockIdx.x * blockDim.x + threadIdx.x;
    if (idx >= S_ * (DH_ / 2)) return;
    int s = idx / (DH_ / 2);
    int i = idx % (DH_ / 2);
    float p    = (float)pos[s];
    float freq = powf(1.0f / 10000.0f, (2.0f * (float)i) / (float)DH_);
    float ang  = p * freq;
    g_rope[idx] = make_float2(cosf(ang), sinf(ang));
}

// ---------------------------------------------------------------------------
// fp32 -> bf16 hi/lo splits
// ---------------------------------------------------------------------------
__global__ void split_kernel(const float* __restrict__ src,
                             __nv_bfloat16* __restrict__ hi,
                             __nv_bfloat16* __restrict__ lo, int n4)
{
    int i = blockIdx.x * blockDim.x + threadIdx.x;
    if (i >= n4) return;
    float4 v = ((const float4*)src)[i];
    uint32_t h01, l01, h23, l23;
    split2(v.x, v.y, h01, l01);
    split2(v.z, v.w, h23, l23);
    ((uint32_t*)hi)[2 * i]     = h01;
    ((uint32_t*)hi)[2 * i + 1] = h23;
    ((uint32_t*)lo)[2 * i]     = l01;
    ((uint32_t*)lo)[2 * i + 1] = l23;
}

__global__ void split4_kernel(const float* __restrict__ s0, const float* __restrict__ s1,
                              const float* __restrict__ s2, const float* __restrict__ s3,
                              __nv_bfloat16* __restrict__ hi,
                              __nv_bfloat16* __restrict__ lo, int n4)
{
    int i = blockIdx.x * blockDim.x + threadIdx.x;
    if (i >= n4) return;
    const int y = blockIdx.y;
    const float* src = (y == 0) ? s0 : (y == 1) ? s1 : (y == 2) ? s2 : s3;
    const size_t off = (size_t)y * ((size_t)D_ * D_ / 2);   // in uint32 units
    float4 v = ((const float4*)src)[i];
    uint32_t h01, l01, h23, l23;
    split2(v.x, v.y, h01, l01);
    split2(v.z, v.w, h23, l23);
    ((uint32_t*)hi)[off + 2 * i]     = h01;
    ((uint32_t*)hi)[off + 2 * i + 1] = h23;
    ((uint32_t*)lo)[off + 2 * i]     = l01;
    ((uint32_t*)lo)[off + 2 * i + 1] = l23;
}

// ---------------------------------------------------------------------------
// bf16x3 GEMM via mma.sync:  C = (Ahi+Alo)[M,K] @ (Bhi+Blo)[N,K]^T
// CTA tile 256x128, 512 threads (16 warps = 4m x 4n, warp tile 64x32),
// BK=32, 3-stage single-barrier cp.async pipeline (prefetch BEFORE compute).
// MODE: 0 = fp32 out, 1 = rope + bf16-split out, 2 = bf16-split out
// ---------------------------------------------------------------------------
#define BK_       32
#define NCHUNK_   (D_ / BK_)            // 64
#define T_STRIDE_ 80
#define A_TILE_   (256 * T_STRIDE_)      // 20480
#define B_TILE_   (128 * T_STRIDE_)      // 10240
#define STAGE_B_  (2 * A_TILE_ + 2 * B_TILE_)  // 61440
#define NSTAGE_   3
#define GEMM_SMEM (NSTAGE_ * STAGE_B_)   // 184320

__device__ __forceinline__ void load_stage(
    uint32_t base, const __nv_bfloat16* __restrict__ pAh,
    const __nv_bfloat16* __restrict__ pAl,
    const __nv_bfloat16* __restrict__ pBh,
    const __nv_bfloat16* __restrict__ pBl, int c, int tid)
{
#pragma unroll
    for (int v = 0; v < 2; v++) {
        int idx = tid + v * 512;
        int row = idx >> 2;
        int seg = idx & 3;
        const size_t go = (size_t)row * D_ + c * BK_ + seg * 8;
        const uint32_t so = row * T_STRIDE_ + seg * 16;
        cp16(base + so,            pAh + go);
        cp16(base + A_TILE_ + so,  pAl + go);
    }
    {
        int row = tid >> 2;
        int seg = tid & 3;
        const size_t go = (size_t)row * D_ + c * BK_ + seg * 8;
        const uint32_t so = row * T_STRIDE_ + seg * 16;
        cp16(base + 2 * A_TILE_ + so,            pBh + go);
        cp16(base + 2 * A_TILE_ + B_TILE_ + so,  pBl + go);
    }
}

template <int MODE>
__global__ __launch_bounds__(512) void gemm_mma(
    const __nv_bfloat16* __restrict__ Ahi, const __nv_bfloat16* __restrict__ Alo,
    const __nv_bfloat16* __restrict__ Bhi, const __nv_bfloat16* __restrict__ Blo,
    float* __restrict__ C,
    __nv_bfloat16* __restrict__ Chi, __nv_bfloat16* __restrict__ Clo)
{
    extern __shared__ __align__(128) char smem[];
    const uint32_t sb = smem_u32(smem);

    const int tid    = threadIdx.x;
    const int lane   = tid & 31;
    const int wid    = tid >> 5;
    const int warp_m = wid & 3;      // 4 x 64 rows
    const int warp_n = wid >> 2;     // 4 x 32 cols
    const int bm     = blockIdx.y * 256;
    const int bn     = blockIdx.x * 128;

    const __nv_bfloat16* pAh = Ahi + (size_t)bm * D_;
    const __nv_bfloat16* pAl = Alo + (size_t)bm * D_;
    const __nv_bfloat16* pBh = Bhi + (size_t)bn * D_;
    const __nv_bfloat16* pBl = Blo + (size_t)bn * D_;

    float acc[4][4][4];
#pragma unroll
    for (int mt = 0; mt < 4; mt++)
#pragma unroll
        for (int nt = 0; nt < 4; nt++)
#pragma unroll
            for (int q = 0; q < 4; q++) acc[mt][nt][q] = 0.0f;

    load_stage(sb,            pAh, pAl, pBh, pBl, 0, tid); cp_commit();
    load_stage(sb + STAGE_B_, pAh, pAl, pBh, pBl, 1, tid); cp_commit();

    const uint32_t a_lane = (lane & 15) * T_STRIDE_ + (lane >> 4) * 16
                          + warp_m * 64 * T_STRIDE_;
    const uint32_t b_lane = (lane & 7) * T_STRIDE_ + ((lane >> 3) & 1) * 16
                          + warp_n * 32 * T_STRIDE_;

    for (int c = 0; c < NCHUNK_; c++) {
        cp_wait1();            // chunk c resident
        __syncthreads();       // everyone done with stage (c-1)%3 (= (c+2)%3)

        // Prefetch chunk c+2 into the stage freed last iteration — overlaps
        // fully with this chunk's compute. Single barrier per iteration.
        if (c + 2 < NCHUNK_) {
            int ps = (c + 2) % NSTAGE_;
            load_stage(sb + ps * STAGE_B_, pAh, pAl, pBh, pBl, c + 2, tid);
        }
        cp_commit();

        const uint32_t base = sb + (c % NSTAGE_) * STAGE_B_;
#pragma unroll
        for (int s = 0; s < 2; s++) {
            const uint32_t abase = base + s * 32 + a_lane;
            const uint32_t bbase = base + 2 * A_TILE_ + s * 32 + b_lane;
            uint32_t ah[4][4], al[4][4], bh[4][2], bl[4][2];
#pragma unroll
            for (int mt = 0; mt < 4; mt++) {
                ldsm_x4(ah[mt], abase + mt * 16 * T_STRIDE_);
                ldsm_x4(al[mt], abase + A_TILE_ + mt * 16 * T_STRIDE_);
            }
#pragma unroll
            for (int nt = 0; nt < 4; nt++) {
                ldsm_x2(bh[nt], bbase + nt * 8 * T_STRIDE_);
                ldsm_x2(bl[nt], bbase + B_TILE_ + nt * 8 * T_STRIDE_);
            }
            // Term-outermost: 16 independent MMAs between reuses of each acc.
#pragma unroll
            for (int mt = 0; mt < 4; mt++)
#pragma unroll
                for (int nt = 0; nt < 4; nt++)
                    mma16816(acc[mt][nt], ah[mt], bh[nt]);
#pragma unroll
            for (int mt = 0; mt < 4; mt++)
#pragma unroll
                for (int nt = 0; nt < 4; nt++)
                    mma16816(acc[mt][nt], ah[mt], bl[nt]);
#pragma unroll
            for (int mt = 0; mt < 4; mt++)
#pragma unroll
                for (int nt = 0; nt < 4; nt++)
                    mma16816(acc[mt][nt], al[mt], bh[nt]);
        }
    }

    const int gid = lane >> 2, tig = lane & 3;
#pragma unroll
    for (int mt = 0; mt < 4; mt++) {
        const int row0 = bm + warp_m * 64 + mt * 16 + gid;
        const int row1 = row0 + 8;
        const int s0 = row0 & (S_ - 1);
        const int s1 = row1 & (S_ - 1);
#pragma unroll
        for (int nt = 0; nt < 4; nt++) {
            const int col  = bn + warp_n * 32 + nt * 8 + tig * 2;
            float c0 = acc[mt][nt][0], c1 = acc[mt][nt][1];
            float c2 = acc[mt][nt][2], c3 = acc[mt][nt][3];
            if (MODE == 1) {
                const int pr = (col & (DH_ - 1)) >> 1;
                float2 csa = g_rope[s0 * (DH_ / 2) + pr];
                float2 csb = g_rope[s1 * (DH_ / 2) + pr];
                float e0 = c0, o0 = c1, e1 = c2, o1 = c3;
                c0 = e0 * csa.x - o0 * csa.y;
                c1 = e0 * csa.y + o0 * csa.x;
                c2 = e1 * csb.x - o1 * csb.y;
                c3 = e1 * csb.y + o1 * csb.x;
            }
            if (MODE == 0) {
                *(float2*)(C + (size_t)row0 * D_ + col) = make_float2(c0, c1);
                *(float2*)(C + (size_t)row1 * D_ + col) = make_float2(c2, c3);
            } else {
                uint32_t h01, l01, h23, l23;
                split2(c0, c1, h01, l01);
                split2(c2, c3, h23, l23);
                *(uint32_t*)(Chi + (size_t)row0 * D_ + col) = h01;
                *(uint32_t*)(Clo + (size_t)row0 * D_ + col) = l01;
                *(uint32_t*)(Chi + (size_t)row1 * D_ + col) = h23;
                *(uint32_t*)(Clo + (size_t)row1 * D_ + col) = l23;
            }
        }
    }
}

// ---------------------------------------------------------------------------
// Flash attention on mma.sync bf16 (unchanged from R5).
// CTA = 256 q rows of one (b,h); 512 threads = 16 warps x 16 rows;
// key tiles of 32, double-buffered cp.async.
// ---------------------------------------------------------------------------
#define FL_STRIDE 272
#define FL_QTILE  (256 * FL_STRIDE)
#define FL_KTILE  (32 * FL_STRIDE)
#define FL_STAGE  (4 * FL_KTILE)
#define FL_SMEM   (2 * FL_QTILE + 2 * FL_STAGE)

__device__ __forceinline__ void flash_load_kv(
    uint32_t base, const __nv_bfloat16* Kh, const __nv_bfloat16* Kl,
    const __nv_bfloat16* Vh, const __nv_bfloat16* Vl, int kt, int tid)
{
    const int row = tid >> 4;
    const int seg = tid & 15;
    const size_t go = ((size_t)kt * 32 + row) * D_ + seg * 8;
    const uint32_t so = row * FL_STRIDE + seg * 16;
    cp16(base + so,                 Kh + go);
    cp16(base + FL_KTILE + so,      Kl + go);
    cp16(base + 2 * FL_KTILE + so,  Vh + go);
    cp16(base + 3 * FL_KTILE + so,  Vl + go);
}

__global__ __launch_bounds__(512) void flash_mma()
{
    extern __shared__ __align__(128) char fsm[];
    const uint32_t sb  = smem_u32(fsm);
    const uint32_t sQh = sb;
    const uint32_t sQl = sb + FL_QTILE;
    const uint32_t sKV = sb + 2 * FL_QTILE;

    const int tid  = threadIdx.x;
    const int lane = tid & 31;
    const int w    = tid >> 5;
    const int gid  = lane >> 2, tig = lane & 3;
    const int bh   = blockIdx.y;
    const int b    = bh >> 4;
    const int h    = bh & 15;
    const int qt   = (int)gridDim.x - 1 - (int)blockIdx.x;
    const int q0   = qt * 256;
    const int nkt  = 8 * (qt + 1);

    const __nv_bfloat16* Qh = g_Qhi + ((size_t)(b * S_ + q0)) * D_ + h * DH_;
    const __nv_bfloat16* Ql = g_Qlo + ((size_t)(b * S_ + q0)) * D_ + h * DH_;
    const __nv_bfloat16* Kh = g_Khi + ((size_t)b * S_) * D_ + h * DH_;
    const __nv_bfloat16* Kl = g_Klo + ((size_t)b * S_) * D_ + h * DH_;
    const __nv_bfloat16* Vh = g_Vhi + ((size_t)b * S_) * D_ + h * DH_;
    const __nv_bfloat16* Vl = g_Vlo + ((size_t)b * S_) * D_ + h * DH_;

#pragma unroll
    for (int v = 0; v < 8; v++) {
        int idx = tid + v * 512;
        int row = idx >> 4;
        int seg = idx & 15;
        const size_t go = (size_t)row * D_ + seg * 8;
        const uint32_t so = row * FL_STRIDE + seg * 16;
        cp16(sQh + so, Qh + go);
        cp16(sQl + so, Ql + go);
    }
    flash_load_kv(sKV, Kh, Kl, Vh, Vl, 0, tid);
    cp_commit();
    flash_load_kv(sKV + FL_STAGE, Kh, Kl, Vh, Vl, 1, tid);
    cp_commit();

    float accO[16][4];
#pragma unroll
    for (int nt = 0; nt < 16; nt++)
#pragma unroll
        for (int q = 0; q < 4; q++) accO[nt][q] = 0.0f;
    float m0 = -INFINITY, m1 = -INFINITY, l0 = 0.0f, l1 = 0.0f;

    const float scale = 0.08838834764831845f;
    const int rq0 = q0 + w * 16 + gid;
    const int rq1 = rq0 + 8;

    const uint32_t a_lane = (w * 16 + (lane & 15)) * FL_STRIDE + (lane >> 4) * 16;
    const uint32_t kb_lane = ((lane & 7) + (lane >> 4) * 8) * FL_STRIDE
                           + ((lane >> 3) & 1) * 16;
    const uint32_t v_lane = (lane & 15) * FL_STRIDE + (lane >> 4) * 16;

    for (int kt = 0; kt < nkt; kt++) {
        cp_wait1();
        __syncthreads();
        const uint32_t kbh = sKV + (kt & 1) * FL_STAGE;
        const uint32_t kbl = kbh + FL_KTILE;
        const uint32_t vbh = kbh + 2 * FL_KTILE;
        const uint32_t vbl = kbh + 3 * FL_KTILE;

        float sf[4][4];
#pragma unroll
        for (int nt = 0; nt < 4; nt++)
#pragma unroll
            for (int q = 0; q < 4; q++) sf[nt][q] = 0.0f;

#pragma unroll
        for (int ks = 0; ks < 8; ks++) {
            uint32_t ah[4], al[4];
            ldsm_x4(ah, sQh + a_lane + ks * 32);
            ldsm_x4(al, sQl + a_lane + ks * 32);
#pragma unroll
            for (int ntp = 0; ntp < 2; ntp++) {
                uint32_t bh4[4], bl4[4];
                ldsm_x4(bh4, kbh + ntp * 16 * FL_STRIDE + kb_lane + ks * 32);
                ldsm_x4(bl4, kbl + ntp * 16 * FL_STRIDE + kb_lane + ks * 32);
                mma16816v(sf[2 * ntp],     ah, bh4[0], bh4[1]);
                mma16816v(sf[2 * ntp],     ah, bl4[0], bl4[1]);
                mma16816v(sf[2 * ntp],     al, bh4[0], bh4[1]);
                mma16816v(sf[2 * ntp + 1], ah, bh4[2], bh4[3]);
                mma16816v(sf[2 * ntp + 1], ah, bl4[2], bl4[3]);
                mma16816v(sf[2 * ntp + 1], al, bh4[2], bh4[3]);
            }
        }

        const bool msk = (kt >= nkt - 8);
#pragma unroll
        for (int nt = 0; nt < 4; nt++) {
            const int col = kt * 32 + nt * 8 + 2 * tig;
            sf[nt][0] *= scale; sf[nt][1] *= scale;
            sf[nt][2] *= scale; sf[nt][3] *= scale;
            if (msk) {
                if (col     > rq0) sf[nt][0] = -INFINITY;
                if (col + 1 > rq0) sf[nt][1] = -INFINITY;
                if (col     > rq1) sf[nt][2] = -INFINITY;
                if (col + 1 > rq1) sf[nt][3] = -INFINITY;
            }
        }

        float mx0 = -INFINITY, mx1 = -INFINITY;
#pragma unroll
        for (int nt = 0; nt < 4; nt++) {
            mx0 = fmaxf(mx0, fmaxf(sf[nt][0], sf[nt][1]));
            mx1 = fmaxf(mx1, fmaxf(sf[nt][2], sf[nt][3]));
        }
        mx0 = fmaxf(mx0, __shfl_xor_sync(0xffffffffu, mx0, 1));
        mx0 = fmaxf(mx0, __shfl_xor_sync(0xffffffffu, mx0, 2));
        mx1 = fmaxf(mx1, __shfl_xor_sync(0xffffffffu, mx1, 1));
        mx1 = fmaxf(mx1, __shfl_xor_sync(0xffffffffu, mx1, 2));

        const float mn0 = fmaxf(m0, mx0), mn1 = fmaxf(m1, mx1);
        const float cr0 = __expf(m0 - mn0), cr1 = __expf(m1 - mn1);

        float sum0 = 0.0f, sum1 = 0.0f;
#pragma unroll
        for (int nt = 0; nt < 4; nt++) {
            sf[nt][0] = __expf(sf[nt][0] - mn0);
            sf[nt][1] = __expf(sf[nt][1] - mn0);
            sf[nt][2] = __expf(sf[nt][2] - mn1);
            sf[nt][3] = __expf(sf[nt][3] - mn1);
            sum0 += sf[nt][0] + sf[nt][1];
            sum1 += sf[nt][2] + sf[nt][3];
        }
        sum0 += __shfl_xor_sync(0xffffffffu, sum0, 1);
        sum0 += __shfl_xor_sync(0xffffffffu, sum0, 2);
        sum1 += __shfl_xor_sync(0xffffffffu, sum1, 1);
        sum1 += __shfl_xor_sync(0xffffffffu, sum1, 2);
        l0 = l0 * cr0 + sum0; m0 = mn0;
        l1 = l1 * cr1 + sum1; m1 = mn1;

#pragma unroll
        for (int nt = 0; nt < 16; nt++) {
            accO[nt][0] *= cr0; accO[nt][1] *= cr0;
            accO[nt][2] *= cr1; accO[nt][3] *= cr1;
        }

        uint32_t pah[2][4], pal[2][4];
#pragma unroll
        for (int j = 0; j < 2; j++) {
            split2(sf[2 * j][0],     sf[2 * j][1],     pah[j][0], pal[j][0]);
            split2(sf[2 * j][2],     sf[2 * j][3],     pah[j][1], pal[j][1]);
            split2(sf[2 * j + 1][0], sf[2 * j + 1][1], pah[j][2], pal[j][2]);
            split2(sf[2 * j + 1][2], sf[2 * j + 1][3], pah[j][3], pal[j][3]);
        }

#pragma unroll
        for (int j = 0; j < 2; j++) {
#pragma unroll
            for (int ntp = 0; ntp < 8; ntp++) {
                uint32_t vh4[4], vl4[4];
                const uint32_t va = 16 * j * FL_STRIDE + ntp * 32 + v_lane;
                ldsm_x4t(vh4, vbh + va);
                ldsm_x4t(vl4, vbl + va);
                mma16816v(accO[2 * ntp],     pah[j], vh4[0], vh4[1]);
                mma16816v(accO[2 * ntp],     pal[j], vh4[0], vh4[1]);
                mma16816v(accO[2 * ntp],     pah[j], vl4[0], vl4[1]);
                mma16816v(accO[2 * ntp + 1], pah[j], vh4[2], vh4[3]);
                mma16816v(accO[2 * ntp + 1], pal[j], vh4[2], vh4[3]);
                mma16816v(accO[2 * ntp + 1], pah[j], vl4[2], vl4[3]);
            }
        }

        __syncthreads();
        if (kt + 2 < nkt)
            flash_load_kv(kbh, Kh, Kl, Vh, Vl, kt + 2, tid);
        cp_commit();
    }

    const float inv0 = 1.0f / l0, inv1 = 1.0f / l1;
    __nv_bfloat16* Oh = g_Ohi + ((size_t)(b * S_ + q0 + w * 16)) * D_ + h * DH_;
    __nv_bfloat16* Ol = g_Olo + ((size_t)(b * S_ + q0 + w * 16)) * D_ + h * DH_;
#pragma unroll
    for (int nt = 0; nt < 16; nt++) {
        const int col = nt * 8 + 2 * tig;
        uint32_t h01, l01, h23, l23;
        split2(accO[nt][0] * inv0, accO[nt][1] * inv0, h01, l01);
        split2(accO[nt][2] * inv1, accO[nt][3] * inv1, h23, l23);
        *(uint32_t*)(Oh + (size_t)gid * D_ + col)       = h01;
        *(uint32_t*)(Ol + (size_t)gid * D_ + col)       = l01;
        *(uint32_t*)(Oh + (size_t)(gid + 8) * D_ + col) = h23;
        *(uint32_t*)(Ol + (size_t)(gid + 8) * D_ + col) = l23;
    }
}

// ---------------------------------------------------------------------------
// Launch
// ---------------------------------------------------------------------------
extern "C" void kernel_launch(void* const* d_in, const int* in_sizes, int n_in,
                              void* d_out, int out_size)
{
    const float* x   = (const float*)d_in[0];
    const int*   pos = (const int*)  d_in[1];
    const float* Wq  = (const float*)d_in[2];
    const float* Wk  = (const float*)d_in[3];
    const float* Wv  = (const float*)d_in[4];
    const float* Wo  = (const float*)d_in[5];
    float*       out = (float*)d_out;

    __nv_bfloat16 *xhi, *xlo, *whi, *wlo;
    __nv_bfloat16 *qhi, *qlo, *khi, *klo, *vhi, *vlo, *ohi, *olo;
    cudaGetSymbolAddress((void**)&xhi, g_xhi);
    cudaGetSymbolAddress((void**)&xlo, g_xlo);
    cudaGetSymbolAddress((void**)&whi, g_Whi);
    cudaGetSymbolAddress((void**)&wlo, g_Wlo);
    cudaGetSymbolAddress((void**)&qhi, g_Qhi);
    cudaGetSymbolAddress((void**)&qlo, g_Qlo);
    cudaGetSymbolAddress((void**)&khi, g_Khi);
    cudaGetSymbolAddress((void**)&klo, g_Klo);
    cudaGetSymbolAddress((void**)&vhi, g_Vhi);
    cudaGetSymbolAddress((void**)&vlo, g_Vlo);
    cudaGetSymbolAddress((void**)&ohi, g_Ohi);
    cudaGetSymbolAddress((void**)&olo, g_Olo);

    cudaFuncSetAttribute(gemm_mma<0>, cudaFuncAttributeMaxDynamicSharedMemorySize, GEMM_SMEM);
    cudaFuncSetAttribute(gemm_mma<1>, cudaFuncAttributeMaxDynamicSharedMemorySize, GEMM_SMEM);
    cudaFuncSetAttribute(gemm_mma<2>, cudaFuncAttributeMaxDynamicSharedMemorySize, GEMM_SMEM);
    cudaFuncSetAttribute(flash_mma,   cudaFuncAttributeMaxDynamicSharedMemorySize, FL_SMEM);

    const int nx4 = M_ * D_ / 4;
    const int nw4 = D_ * D_ / 4;

    rope_table_kernel<<<(S_ * (DH_ / 2) + 255) / 256, 256>>>(pos);
    split_kernel<<<(nx4 + 255) / 256, 256>>>(x, xhi, xlo, nx4);
    split4_kernel<<<dim3((nw4 + 255) / 256, 4), 256>>>(Wq, Wk, Wv, Wo, whi, wlo, nw4);

    dim3 gg(D_ / 128, M_ / 256);  // (16, 16)
    gemm_mma<1><<<gg, 512, GEMM_SMEM>>>(xhi, xlo, whi + 0 * (size_t)D_ * D_, wlo + 0 * (size_t)D_ * D_,
                                        nullptr, qhi, qlo);
    gemm_mma<1><<<gg, 512, GEMM_SMEM>>>(xhi, xlo, whi + 1 * (size_t)D_ * D_, wlo + 1 * (size_t)D_ * D_,
                                        nullptr, khi, klo);
    gemm_mma<2><<<gg, 512, GEMM_SMEM>>>(xhi, xlo, whi + 2 * (size_t)D_ * D_, wlo + 2 * (size_t)D_ * D_,
                                        nullptr, vhi, vlo);

    flash_mma<<<dim3(S_ / 256, B_ * H_), 512, FL_SMEM>>>();

    gemm_mma<0><<<gg, 512, GEMM_SMEM>>>(ohi, olo, whi + 3 * (size_t)D_ * D_, wlo + 3 * (size_t)D_ * D_,
                                        out, nullptr, nullptr);
}

// round 8
// speedup vs baseline: 2.8109x; 1.0903x over previous
#include <cuda_runtime.h>
#include <cuda_bf16.h>
#include <math.h>
#include <stdint.h>

// Problem constants
#define B_  2
#define S_  2048
#define D_  2048
#define H_  16
#define DH_ 128
#define M_  (B_*S_)   // 4096

// ---------------------------------------------------------------------------
// Scratch (no cudaMalloc allowed)
// ---------------------------------------------------------------------------
__device__ __align__(16) float2 g_rope[S_ * (DH_ / 2)];

__device__ __align__(16) __nv_bfloat16 g_xhi[(size_t)M_ * D_];
__device__ __align__(16) __nv_bfloat16 g_xlo[(size_t)M_ * D_];
__device__ __align__(16) __nv_bfloat16 g_Whi[(size_t)4 * D_ * D_];
__device__ __align__(16) __nv_bfloat16 g_Wlo[(size_t)4 * D_ * D_];
__device__ __align__(16) __nv_bfloat16 g_Qhi[(size_t)M_ * D_];
__device__ __align__(16) __nv_bfloat16 g_Qlo[(size_t)M_ * D_];
__device__ __align__(16) __nv_bfloat16 g_Khi[(size_t)M_ * D_];
__device__ __align__(16) __nv_bfloat16 g_Klo[(size_t)M_ * D_];
__device__ __align__(16) __nv_bfloat16 g_Vhi[(size_t)M_ * D_];
__device__ __align__(16) __nv_bfloat16 g_Vlo[(size_t)M_ * D_];
__device__ __align__(16) __nv_bfloat16 g_Ohi[(size_t)M_ * D_];
__device__ __align__(16) __nv_bfloat16 g_Olo[(size_t)M_ * D_];

// ---------------------------------------------------------------------------
// PTX helpers (compute_103-safe: sm_80-era instructions only)
// ---------------------------------------------------------------------------
__device__ __forceinline__ uint32_t smem_u32(const void* p) {
    uint32_t a;
    asm("{ .reg .u64 t; cvta.to.shared.u64 t, %1; cvt.u32.u64 %0, t; }"
        : "=r"(a) : "l"(p));
    return a;
}

__device__ __forceinline__ void cp16(uint32_t dst, const void* src) {
    asm volatile("cp.async.cg.shared.global [%0], [%1], 16;" :: "r"(dst), "l"(src));
}
__device__ __forceinline__ void cp_commit() { asm volatile("cp.async.commit_group;" ::: "memory"); }
__device__ __forceinline__ void cp_wait0()  { asm volatile("cp.async.wait_group 0;" ::: "memory"); }
__device__ __forceinline__ void cp_wait1()  { asm volatile("cp.async.wait_group 1;" ::: "memory"); }

__device__ __forceinline__ void ldsm_x4(uint32_t (&r)[4], uint32_t addr) {
    asm volatile("ldmatrix.sync.aligned.m8n8.x4.shared.b16 {%0,%1,%2,%3}, [%4];"
                 : "=r"(r[0]), "=r"(r[1]), "=r"(r[2]), "=r"(r[3]) : "r"(addr));
}
__device__ __forceinline__ void ldsm_x2(uint32_t (&r)[2], uint32_t addr) {
    asm volatile("ldmatrix.sync.aligned.m8n8.x2.shared.b16 {%0,%1}, [%2];"
                 : "=r"(r[0]), "=r"(r[1]) : "r"(addr));
}
__device__ __forceinline__ void ldsm_x4t(uint32_t (&r)[4], uint32_t addr) {
    asm volatile("ldmatrix.sync.aligned.m8n8.x4.trans.shared.b16 {%0,%1,%2,%3}, [%4];"
                 : "=r"(r[0]), "=r"(r[1]), "=r"(r[2]), "=r"(r[3]) : "r"(addr));
}

__device__ __forceinline__ void mma16816(float (&c)[4], const uint32_t (&a)[4],
                                         const uint32_t (&b)[2]) {
    asm volatile(
        "mma.sync.aligned.m16n8k16.row.col.f32.bf16.bf16.f32 "
        "{%0,%1,%2,%3}, {%4,%5,%6,%7}, {%8,%9}, {%0,%1,%2,%3};"
        : "+f"(c[0]), "+f"(c[1]), "+f"(c[2]), "+f"(c[3])
        : "r"(a[0]), "r"(a[1]), "r"(a[2]), "r"(a[3]), "r"(b[0]), "r"(b[1]));
}
__device__ __forceinline__ void mma16816v(float (&c)[4], const uint32_t (&a)[4],
                                          uint32_t b0, uint32_t b1) {
    asm volatile(
        "mma.sync.aligned.m16n8k16.row.col.f32.bf16.bf16.f32 "
        "{%0,%1,%2,%3}, {%4,%5,%6,%7}, {%8,%9}, {%0,%1,%2,%3};"
        : "+f"(c[0]), "+f"(c[1]), "+f"(c[2]), "+f"(c[3])
        : "r"(a[0]), "r"(a[1]), "r"(a[2]), "r"(a[3]), "r"(b0), "r"(b1));
}

__device__ __forceinline__ void split2(float a, float b, uint32_t &hi, uint32_t &lo) {
    __nv_bfloat16 ha = __float2bfloat16_rn(a), hb = __float2bfloat16_rn(b);
    float ra = a - __bfloat162float(ha), rb = b - __bfloat162float(hb);
    __nv_bfloat162 th = __halves2bfloat162(ha, hb);
    __nv_bfloat162 tl = __floats2bfloat162_rn(ra, rb);
    hi = *reinterpret_cast<uint32_t*>(&th);
    lo = *reinterpret_cast<uint32_t*>(&tl);
}

// ---------------------------------------------------------------------------
// RoPE cos/sin table
// ---------------------------------------------------------------------------
__global__ void rope_table_kernel(const int* __restrict__ pos)
{
    int idx = blockIdx.x * blockDim.x + threadIdx.x;
    if (idx >= S_ * (DH_ / 2)) return;
    int s = idx / (DH_ / 2);
    int i = idx % (DH_ / 2);
    float p    = (float)pos[s];
    float freq = powf(1.0f / 10000.0f, (2.0f * (float)i) / (float)DH_);
    float ang  = p * freq;
    g_rope[idx] = make_float2(cosf(ang), sinf(ang));
}

// ---------------------------------------------------------------------------
// fp32 -> bf16 hi/lo splits
// ---------------------------------------------------------------------------
__global__ void split_kernel(const float* __restrict__ src,
                             __nv_bfloat16* __restrict__ hi,
                             __nv_bfloat16* __restrict__ lo, int n4)
{
    int i = blockIdx.x * blockDim.x + threadIdx.x;
    if (i >= n4) return;
    float4 v = ((const float4*)src)[i];
    uint32_t h01, l01, h23, l23;
    split2(v.x, v.y, h01, l01);
    split2(v.z, v.w, h23, l23);
    ((uint32_t*)hi)[2 * i]     = h01;
    ((uint32_t*)hi)[2 * i + 1] = h23;
    ((uint32_t*)lo)[2 * i]     = l01;
    ((uint32_t*)lo)[2 * i + 1] = l23;
}

__global__ void split4_kernel(const float* __restrict__ s0, const float* __restrict__ s1,
                              const float* __restrict__ s2, const float* __restrict__ s3,
                              __nv_bfloat16* __restrict__ hi,
                              __nv_bfloat16* __restrict__ lo, int n4)
{
    int i = blockIdx.x * blockDim.x + threadIdx.x;
    if (i >= n4) return;
    const int y = blockIdx.y;
    const float* src = (y == 0) ? s0 : (y == 1) ? s1 : (y == 2) ? s2 : s3;
    const size_t off = (size_t)y * ((size_t)D_ * D_ / 2);   // in uint32 units
    float4 v = ((const float4*)src)[i];
    uint32_t h01, l01, h23, l23;
    split2(v.x, v.y, h01, l01);
    split2(v.z, v.w, h23, l23);
    ((uint32_t*)hi)[off + 2 * i]     = h01;
    ((uint32_t*)hi)[off + 2 * i + 1] = h23;
    ((uint32_t*)lo)[off + 2 * i]     = l01;
    ((uint32_t*)lo)[off + 2 * i + 1] = l23;
}

// ---------------------------------------------------------------------------
// bf16x3 GEMM core: 128x128 CTA tile, 256 threads (8 warps = 2m x 4n,
// warp tile 64x32), BK=32, 2-stage pipeline, 2 CTAs/SM for cross-CTA overlap.
// ---------------------------------------------------------------------------
#define BK_       32
#define NCHUNK_   (D_ / BK_)            // 64
#define T_STRIDE_ 80
#define G_TILE_   (128 * T_STRIDE_)      // 10240
#define STAGE_B_  (4 * G_TILE_)          // 40960: [Ah|Al|Bh|Bl]
#define GEMM_SMEM (2 * STAGE_B_)         // 81920

__device__ __forceinline__ void load_stage(
    uint32_t base, const __nv_bfloat16* __restrict__ pAh,
    const __nv_bfloat16* __restrict__ pAl,
    const __nv_bfloat16* __restrict__ pBh,
    const __nv_bfloat16* __restrict__ pBl, int c, int tid)
{
#pragma unroll
    for (int v = 0; v < 2; v++) {
        int idx = tid + v * 256;          // 0..511
        int row = idx >> 2;               // 0..127
        int seg = idx & 3;
        const size_t go = (size_t)row * D_ + c * BK_ + seg * 8;
        const uint32_t so = row * T_STRIDE_ + seg * 16;
        cp16(base + so,                pAh + go);
        cp16(base + G_TILE_ + so,      pAl + go);
        cp16(base + 2 * G_TILE_ + so,  pBh + go);
        cp16(base + 3 * G_TILE_ + so,  pBl + go);
    }
}

// Compute the 128x128 bf16x3 GEMM tile into acc[4][4][4].
__device__ __forceinline__ void gemm_tile_core(
    uint32_t sb, const __nv_bfloat16* pAh, const __nv_bfloat16* pAl,
    const __nv_bfloat16* pBh, const __nv_bfloat16* pBl,
    float (&acc)[4][4][4], int tid)
{
    const int lane   = tid & 31;
    const int wid    = tid >> 5;
    const int warp_m = wid & 1;      // 2 x 64 rows
    const int warp_n = wid >> 1;     // 4 x 32 cols

#pragma unroll
    for (int mt = 0; mt < 4; mt++)
#pragma unroll
        for (int nt = 0; nt < 4; nt++)
#pragma unroll
            for (int q = 0; q < 4; q++) acc[mt][nt][q] = 0.0f;

    load_stage(sb, pAh, pAl, pBh, pBl, 0, tid);
    cp_commit();

    const uint32_t a_lane = (lane & 15) * T_STRIDE_ + (lane >> 4) * 16
                          + warp_m * 64 * T_STRIDE_;
    const uint32_t b_lane = (lane & 7) * T_STRIDE_ + ((lane >> 3) & 1) * 16
                          + warp_n * 32 * T_STRIDE_;

    for (int c = 0; c < NCHUNK_; c++) {
        cp_wait0();            // chunk c resident
        __syncthreads();       // everyone done reading the other stage

        if (c + 1 < NCHUNK_)   // prefetch overlaps this chunk's compute
            load_stage(sb + ((c + 1) & 1) * STAGE_B_, pAh, pAl, pBh, pBl, c + 1, tid);
        cp_commit();

        const uint32_t base = sb + (c & 1) * STAGE_B_;
#pragma unroll
        for (int s = 0; s < 2; s++) {
            const uint32_t abase = base + s * 32 + a_lane;
            const uint32_t bbase = base + 2 * G_TILE_ + s * 32 + b_lane;
            uint32_t ah[4][4], al[4][4], bh[4][2], bl[4][2];
#pragma unroll
            for (int mt = 0; mt < 4; mt++) {
                ldsm_x4(ah[mt], abase + mt * 16 * T_STRIDE_);
                ldsm_x4(al[mt], abase + G_TILE_ + mt * 16 * T_STRIDE_);
            }
#pragma unroll
            for (int nt = 0; nt < 4; nt++) {
                ldsm_x2(bh[nt], bbase + nt * 8 * T_STRIDE_);
                ldsm_x2(bl[nt], bbase + G_TILE_ + nt * 8 * T_STRIDE_);
            }
#pragma unroll
            for (int mt = 0; mt < 4; mt++)
#pragma unroll
                for (int nt = 0; nt < 4; nt++)
                    mma16816(acc[mt][nt], ah[mt], bh[nt]);
#pragma unroll
            for (int mt = 0; mt < 4; mt++)
#pragma unroll
                for (int nt = 0; nt < 4; nt++)
                    mma16816(acc[mt][nt], ah[mt], bl[nt]);
#pragma unroll
            for (int mt = 0; mt < 4; mt++)
#pragma unroll
                for (int nt = 0; nt < 4; nt++)
                    mma16816(acc[mt][nt], al[mt], bh[nt]);
        }
        __syncthreads();       // done reading this stage before next prefetch targets it
    }
}

// Fused Q/K/V projection: blockIdx.x = which*16 + nblock; Q,K get RoPE.
__global__ __launch_bounds__(256, 2) void gemm_qkv(
    const __nv_bfloat16* __restrict__ xhi, const __nv_bfloat16* __restrict__ xlo,
    const __nv_bfloat16* __restrict__ whi, const __nv_bfloat16* __restrict__ wlo,
    __nv_bfloat16* __restrict__ qhi, __nv_bfloat16* __restrict__ qlo,
    __nv_bfloat16* __restrict__ khi, __nv_bfloat16* __restrict__ klo,
    __nv_bfloat16* __restrict__ vhi, __nv_bfloat16* __restrict__ vlo)
{
    extern __shared__ __align__(128) char smem[];
    const uint32_t sb = smem_u32(smem);
    const int tid   = threadIdx.x;
    const int which = blockIdx.x >> 4;          // 0=Q 1=K 2=V
    const int bn    = (blockIdx.x & 15) * 128;
    const int bm    = blockIdx.y * 128;

    const __nv_bfloat16* pAh = xhi + (size_t)bm * D_;
    const __nv_bfloat16* pAl = xlo + (size_t)bm * D_;
    const __nv_bfloat16* pBh = whi + (size_t)which * D_ * D_ + (size_t)bn * D_;
    const __nv_bfloat16* pBl = wlo + (size_t)which * D_ * D_ + (size_t)bn * D_;

    float acc[4][4][4];
    gemm_tile_core(sb, pAh, pAl, pBh, pBl, acc, tid);

    __nv_bfloat16* Chi = (which == 0) ? qhi : (which == 1) ? khi : vhi;
    __nv_bfloat16* Clo = (which == 0) ? qlo : (which == 1) ? klo : vlo;
    const bool rope = (which < 2);

    const int lane = tid & 31;
    const int wid  = tid >> 5;
    const int warp_m = wid & 1, warp_n = wid >> 1;
    const int gid = lane >> 2, tig = lane & 3;
#pragma unroll
    for (int mt = 0; mt < 4; mt++) {
        const int row0 = bm + warp_m * 64 + mt * 16 + gid;
        const int row1 = row0 + 8;
        const int s0 = row0 & (S_ - 1);
        const int s1 = row1 & (S_ - 1);
#pragma unroll
        for (int nt = 0; nt < 4; nt++) {
            const int col  = bn + warp_n * 32 + nt * 8 + tig * 2;
            float c0 = acc[mt][nt][0], c1 = acc[mt][nt][1];
            float c2 = acc[mt][nt][2], c3 = acc[mt][nt][3];
            if (rope) {
                const int pr = (col & (DH_ - 1)) >> 1;
                float2 csa = g_rope[s0 * (DH_ / 2) + pr];
                float2 csb = g_rope[s1 * (DH_ / 2) + pr];
                float e0 = c0, o0 = c1, e1 = c2, o1 = c3;
                c0 = e0 * csa.x - o0 * csa.y;
                c1 = e0 * csa.y + o0 * csa.x;
                c2 = e1 * csb.x - o1 * csb.y;
                c3 = e1 * csb.y + o1 * csb.x;
            }
            uint32_t h01, l01, h23, l23;
            split2(c0, c1, h01, l01);
            split2(c2, c3, h23, l23);
            *(uint32_t*)(Chi + (size_t)row0 * D_ + col) = h01;
            *(uint32_t*)(Clo + (size_t)row0 * D_ + col) = l01;
            *(uint32_t*)(Chi + (size_t)row1 * D_ + col) = h23;
            *(uint32_t*)(Clo + (size_t)row1 * D_ + col) = l23;
        }
    }
}

// Output projection: fp32 out.
__global__ __launch_bounds__(256, 2) void gemm_out(
    const __nv_bfloat16* __restrict__ Ahi, const __nv_bfloat16* __restrict__ Alo,
    const __nv_bfloat16* __restrict__ Bhi, const __nv_bfloat16* __restrict__ Blo,
    float* __restrict__ C)
{
    extern __shared__ __align__(128) char smem[];
    const uint32_t sb = smem_u32(smem);
    const int tid = threadIdx.x;
    const int bn  = blockIdx.x * 128;
    const int bm  = blockIdx.y * 128;

    const __nv_bfloat16* pAh = Ahi + (size_t)bm * D_;
    const __nv_bfloat16* pAl = Alo + (size_t)bm * D_;
    const __nv_bfloat16* pBh = Bhi + (size_t)bn * D_;
    const __nv_bfloat16* pBl = Blo + (size_t)bn * D_;

    float acc[4][4][4];
    gemm_tile_core(sb, pAh, pAl, pBh, pBl, acc, tid);

    const int lane = tid & 31;
    const int wid  = tid >> 5;
    const int warp_m = wid & 1, warp_n = wid >> 1;
    const int gid = lane >> 2, tig = lane & 3;
#pragma unroll
    for (int mt = 0; mt < 4; mt++) {
        const int row0 = bm + warp_m * 64 + mt * 16 + gid;
        const int row1 = row0 + 8;
#pragma unroll
        for (int nt = 0; nt < 4; nt++) {
            const int col = bn + warp_n * 32 + nt * 8 + tig * 2;
            *(float2*)(C + (size_t)row0 * D_ + col) = make_float2(acc[mt][nt][0], acc[mt][nt][1]);
            *(float2*)(C + (size_t)row1 * D_ + col) = make_float2(acc[mt][nt][2], acc[mt][nt][3]);
        }
    }
}

// ---------------------------------------------------------------------------
// Flash attention on mma.sync bf16 (unchanged from R6).
// ---------------------------------------------------------------------------
#define FL_STRIDE 272
#define FL_QTILE  (256 * FL_STRIDE)
#define FL_KTILE  (32 * FL_STRIDE)
#define FL_STAGE  (4 * FL_KTILE)
#define FL_SMEM   (2 * FL_QTILE + 2 * FL_STAGE)

__device__ __forceinline__ void flash_load_kv(
    uint32_t base, const __nv_bfloat16* Kh, const __nv_bfloat16* Kl,
    const __nv_bfloat16* Vh, const __nv_bfloat16* Vl, int kt, int tid)
{
    const int row = tid >> 4;
    const int seg = tid & 15;
    const size_t go = ((size_t)kt * 32 + row) * D_ + seg * 8;
    const uint32_t so = row * FL_STRIDE + seg * 16;
    cp16(base + so,                 Kh + go);
    cp16(base + FL_KTILE + so,      Kl + go);
    cp16(base + 2 * FL_KTILE + so,  Vh + go);
    cp16(base + 3 * FL_KTILE + so,  Vl + go);
}

__global__ __launch_bounds__(512) void flash_mma()
{
    extern __shared__ __align__(128) char fsm[];
    const uint32_t sb  = smem_u32(fsm);
    const uint32_t sQh = sb;
    const uint32_t sQl = sb + FL_QTILE;
    const uint32_t sKV = sb + 2 * FL_QTILE;

    const int tid  = threadIdx.x;
    const int lane = tid & 31;
    const int w    = tid >> 5;
    const int gid  = lane >> 2, tig = lane & 3;
    const int bh   = blockIdx.y;
    const int b    = bh >> 4;
    const int h    = bh & 15;
    const int qt   = (int)gridDim.x - 1 - (int)blockIdx.x;
    const int q0   = qt * 256;
    const int nkt  = 8 * (qt + 1);

    const __nv_bfloat16* Qh = g_Qhi + ((size_t)(b * S_ + q0)) * D_ + h * DH_;
    const __nv_bfloat16* Ql = g_Qlo + ((size_t)(b * S_ + q0)) * D_ + h * DH_;
    const __nv_bfloat16* Kh = g_Khi + ((size_t)b * S_) * D_ + h * DH_;
    const __nv_bfloat16* Kl = g_Klo + ((size_t)b * S_) * D_ + h * DH_;
    const __nv_bfloat16* Vh = g_Vhi + ((size_t)b * S_) * D_ + h * DH_;
    const __nv_bfloat16* Vl = g_Vlo + ((size_t)b * S_) * D_ + h * DH_;

#pragma unroll
    for (int v = 0; v < 8; v++) {
        int idx = tid + v * 512;
        int row = idx >> 4;
        int seg = idx & 15;
        const size_t go = (size_t)row * D_ + seg * 8;
        const uint32_t so = row * FL_STRIDE + seg * 16;
        cp16(sQh + so, Qh + go);
        cp16(sQl + so, Ql + go);
    }
    flash_load_kv(sKV, Kh, Kl, Vh, Vl, 0, tid);
    cp_commit();
    flash_load_kv(sKV + FL_STAGE, Kh, Kl, Vh, Vl, 1, tid);
    cp_commit();

    float accO[16][4];
#pragma unroll
    for (int nt = 0; nt < 16; nt++)
#pragma unroll
        for (int q = 0; q < 4; q++) accO[nt][q] = 0.0f;
    float m0 = -INFINITY, m1 = -INFINITY, l0 = 0.0f, l1 = 0.0f;

    const float scale = 0.08838834764831845f;
    const int rq0 = q0 + w * 16 + gid;
    const int rq1 = rq0 + 8;

    const uint32_t a_lane = (w * 16 + (lane & 15)) * FL_STRIDE + (lane >> 4) * 16;
    const uint32_t kb_lane = ((lane & 7) + (lane >> 4) * 8) * FL_STRIDE
                           + ((lane >> 3) & 1) * 16;
    const uint32_t v_lane = (lane & 15) * FL_STRIDE + (lane >> 4) * 16;

    for (int kt = 0; kt < nkt; kt++) {
        cp_wait1();
        __syncthreads();
        const uint32_t kbh = sKV + (kt & 1) * FL_STAGE;
        const uint32_t kbl = kbh + FL_KTILE;
        const uint32_t vbh = kbh + 2 * FL_KTILE;
        const uint32_t vbl = kbh + 3 * FL_KTILE;

        float sf[4][4];
#pragma unroll
        for (int nt = 0; nt < 4; nt++)
#pragma unroll
            for (int q = 0; q < 4; q++) sf[nt][q] = 0.0f;

#pragma unroll
        for (int ks = 0; ks < 8; ks++) {
            uint32_t ah[4], al[4];
            ldsm_x4(ah, sQh + a_lane + ks * 32);
            ldsm_x4(al, sQl + a_lane + ks * 32);
#pragma unroll
            for (int ntp = 0; ntp < 2; ntp++) {
                uint32_t bh4[4], bl4[4];
                ldsm_x4(bh4, kbh + ntp * 16 * FL_STRIDE + kb_lane + ks * 32);
                ldsm_x4(bl4, kbl + ntp * 16 * FL_STRIDE + kb_lane + ks * 32);
                mma16816v(sf[2 * ntp],     ah, bh4[0], bh4[1]);
                mma16816v(sf[2 * ntp],     ah, bl4[0], bl4[1]);
                mma16816v(sf[2 * ntp],     al, bh4[0], bh4[1]);
                mma16816v(sf[2 * ntp + 1], ah, bh4[2], bh4[3]);
                mma16816v(sf[2 * ntp + 1], ah, bl4[2], bl4[3]);
                mma16816v(sf[2 * ntp + 1], al, bh4[2], bh4[3]);
            }
        }

        const bool msk = (kt >= nkt - 8);
#pragma unroll
        for (int nt = 0; nt < 4; nt++) {
            const int col = kt * 32 + nt * 8 + 2 * tig;
            sf[nt][0] *= scale; sf[nt][1] *= scale;
            sf[nt][2] *= scale; sf[nt][3] *= scale;
            if (msk) {
                if (col     > rq0) sf[nt][0] = -INFINITY;
                if (col + 1 > rq0) sf[nt][1] = -INFINITY;
                if (col     > rq1) sf[nt][2] = -INFINITY;
                if (col + 1 > rq1) sf[nt][3] = -INFINITY;
            }
        }

        float mx0 = -INFINITY, mx1 = -INFINITY;
#pragma unroll
        for (int nt = 0; nt < 4; nt++) {
            mx0 = fmaxf(mx0, fmaxf(sf[nt][0], sf[nt][1]));
            mx1 = fmaxf(mx1, fmaxf(sf[nt][2], sf[nt][3]));
        }
        mx0 = fmaxf(mx0, __shfl_xor_sync(0xffffffffu, mx0, 1));
        mx0 = fmaxf(mx0, __shfl_xor_sync(0xffffffffu, mx0, 2));
        mx1 = fmaxf(mx1, __shfl_xor_sync(0xffffffffu, mx1, 1));
        mx1 = fmaxf(mx1, __shfl_xor_sync(0xffffffffu, mx1, 2));

        const float mn0 = fmaxf(m0, mx0), mn1 = fmaxf(m1, mx1);
        const float cr0 = __expf(m0 - mn0), cr1 = __expf(m1 - mn1);

        float sum0 = 0.0f, sum1 = 0.0f;
#pragma unroll
        for (int nt = 0; nt < 4; nt++) {
            sf[nt][0] = __expf(sf[nt][0] - mn0);
            sf[nt][1] = __expf(sf[nt][1] - mn0);
            sf[nt][2] = __expf(sf[nt][2] - mn1);
            sf[nt][3] = __expf(sf[nt][3] - mn1);
            sum0 += sf[nt][0] + sf[nt][1];
            sum1 += sf[nt][2] + sf[nt][3];
        }
        sum0 += __shfl_xor_sync(0xffffffffu, sum0, 1);
        sum0 += __shfl_xor_sync(0xffffffffu, sum0, 2);
        sum1 += __shfl_xor_sync(0xffffffffu, sum1, 1);
        sum1 += __shfl_xor_sync(0xffffffffu, sum1, 2);
        l0 = l0 * cr0 + sum0; m0 = mn0;
        l1 = l1 * cr1 + sum1; m1 = mn1;

#pragma unroll
        for (int nt = 0; nt < 16; nt++) {
            accO[nt][0] *= cr0; accO[nt][1] *= cr0;
            accO[nt][2] *= cr1; accO[nt][3] *= cr1;
        }

        uint32_t pah[2][4], pal[2][4];
#pragma unroll
        for (int j = 0; j < 2; j++) {
            split2(sf[2 * j][0],     sf[2 * j][1],     pah[j][0], pal[j][0]);
            split2(sf[2 * j][2],     sf[2 * j][3],     pah[j][1], pal[j][1]);
            split2(sf[2 * j + 1][0], sf[2 * j + 1][1], pah[j][2], pal[j][2]);
            split2(sf[2 * j + 1][2], sf[2 * j + 1][3], pah[j][3], pal[j][3]);
        }

#pragma unroll
        for (int j = 0; j < 2; j++) {
#pragma unroll
            for (int ntp = 0; ntp < 8; ntp++) {
                uint32_t vh4[4], vl4[4];
                const uint32_t va = 16 * j * FL_STRIDE + ntp * 32 + v_lane;
                ldsm_x4t(vh4, vbh + va);
                ldsm_x4t(vl4, vbl + va);
                mma16816v(accO[2 * ntp],     pah[j], vh4[0], vh4[1]);
                mma16816v(accO[2 * ntp],     pal[j], vh4[0], vh4[1]);
                mma16816v(accO[2 * ntp],     pah[j], vl4[0], vl4[1]);
                mma16816v(accO[2 * ntp + 1], pah[j], vh4[2], vh4[3]);
                mma16816v(accO[2 * ntp + 1], pal[j], vh4[2], vh4[3]);
                mma16816v(accO[2 * ntp + 1], pah[j], vl4[2], vl4[3]);
            }
        }

        __syncthreads();
        if (kt + 2 < nkt)
            flash_load_kv(kbh, Kh, Kl, Vh, Vl, kt + 2, tid);
        cp_commit();
    }

    const float inv0 = 1.0f / l0, inv1 = 1.0f / l1;
    __nv_bfloat16* Oh = g_Ohi + ((size_t)(b * S_ + q0 + w * 16)) * D_ + h * DH_;
    __nv_bfloat16* Ol = g_Olo + ((size_t)(b * S_ + q0 + w * 16)) * D_ + h * DH_;
#pragma unroll
    for (int nt = 0; nt < 16; nt++) {
        const int col = nt * 8 + 2 * tig;
        uint32_t h01, l01, h23, l23;
        split2(accO[nt][0] * inv0, accO[nt][1] * inv0, h01, l01);
        split2(accO[nt][2] * inv1, accO[nt][3] * inv1, h23, l23);
        *(uint32_t*)(Oh + (size_t)gid * D_ + col)       = h01;
        *(uint32_t*)(Ol + (size_t)gid * D_ + col)       = l01;
        *(uint32_t*)(Oh + (size_t)(gid + 8) * D_ + col) = h23;
        *(uint32_t*)(Ol + (size_t)(gid + 8) * D_ + col) = l23;
    }
}

// ---------------------------------------------------------------------------
// Launch
// ---------------------------------------------------------------------------
extern "C" void kernel_launch(void* const* d_in, const int* in_sizes, int n_in,
                              void* d_out, int out_size)
{
    const float* x   = (const float*)d_in[0];
    const int*   pos = (const int*)  d_in[1];
    const float* Wq  = (const float*)d_in[2];
    const float* Wk  = (const float*)d_in[3];
    const float* Wv  = (const float*)d_in[4];
    const float* Wo  = (const float*)d_in[5];
    float*       out = (float*)d_out;

    __nv_bfloat16 *xhi, *xlo, *whi, *wlo;
    __nv_bfloat16 *qhi, *qlo, *khi, *klo, *vhi, *vlo, *ohi, *olo;
    cudaGetSymbolAddress((void**)&xhi, g_xhi);
    cudaGetSymbolAddress((void**)&xlo, g_xlo);
    cudaGetSymbolAddress((void**)&whi, g_Whi);
    cudaGetSymbolAddress((void**)&wlo, g_Wlo);
    cudaGetSymbolAddress((void**)&qhi, g_Qhi);
    cudaGetSymbolAddress((void**)&qlo, g_Qlo);
    cudaGetSymbolAddress((void**)&khi, g_Khi);
    cudaGetSymbolAddress((void**)&klo, g_Klo);
    cudaGetSymbolAddress((void**)&vhi, g_Vhi);
    cudaGetSymbolAddress((void**)&vlo, g_Vlo);
    cudaGetSymbolAddress((void**)&ohi, g_Ohi);
    cudaGetSymbolAddress((void**)&olo, g_Olo);

    cudaFuncSetAttribute(gemm_qkv, cudaFuncAttributeMaxDynamicSharedMemorySize, GEMM_SMEM);
    cudaFuncSetAttribute(gemm_out, cudaFuncAttributeMaxDynamicSharedMemorySize, GEMM_SMEM);
    cudaFuncSetAttribute(flash_mma, cudaFuncAttributeMaxDynamicSharedMemorySize, FL_SMEM);

    const int nx4 = M_ * D_ / 4;
    const int nw4 = D_ * D_ / 4;

    rope_table_kernel<<<(S_ * (DH_ / 2) + 255) / 256, 256>>>(pos);
    split_kernel<<<(nx4 + 255) / 256, 256>>>(x, xhi, xlo, nx4);
    split4_kernel<<<dim3((nw4 + 255) / 256, 4), 256>>>(Wq, Wk, Wv, Wo, whi, wlo, nw4);

    gemm_qkv<<<dim3(48, 32), 256, GEMM_SMEM>>>(xhi, xlo, whi, wlo,
                                               qhi, qlo, khi, klo, vhi, vlo);

    flash_mma<<<dim3(S_ / 256, B_ * H_), 512, FL_SMEM>>>();

    gemm_out<<<dim3(16, 32), 256, GEMM_SMEM>>>(ohi, olo,
                                               whi + 3 * (size_t)D_ * D_,
                                               wlo + 3 * (size_t)D_ * D_, out);
}

// round 12
// speedup vs baseline: 2.8698x; 1.0210x over previous
#include <cuda_runtime.h>
#include <cuda_bf16.h>
#include <math.h>
#include <stdint.h>

// Problem constants
#define B_  2
#define S_  2048
#define D_  2048
#define H_  16
#define DH_ 128
#define M_  (B_*S_)   // 4096

// ---------------------------------------------------------------------------
// Scratch (no cudaMalloc allowed)
// ---------------------------------------------------------------------------
__device__ __align__(16) float2 g_rope[S_ * (DH_ / 2)];

__device__ __align__(16) __nv_bfloat16 g_xhi[(size_t)M_ * D_];
__device__ __align__(16) __nv_bfloat16 g_xlo[(size_t)M_ * D_];
__device__ __align__(16) __nv_bfloat16 g_Whi[(size_t)4 * D_ * D_];
__device__ __align__(16) __nv_bfloat16 g_Wlo[(size_t)4 * D_ * D_];
__device__ __align__(16) __nv_bfloat16 g_Qhi[(size_t)M_ * D_];
__device__ __align__(16) __nv_bfloat16 g_Qlo[(size_t)M_ * D_];
__device__ __align__(16) __nv_bfloat16 g_Khi[(size_t)M_ * D_];
__device__ __align__(16) __nv_bfloat16 g_Klo[(size_t)M_ * D_];
__device__ __align__(16) __nv_bfloat16 g_Vhi[(size_t)M_ * D_];
__device__ __align__(16) __nv_bfloat16 g_Vlo[(size_t)M_ * D_];
__device__ __align__(16) __nv_bfloat16 g_Ohi[(size_t)M_ * D_];
__device__ __align__(16) __nv_bfloat16 g_Olo[(size_t)M_ * D_];

// ---------------------------------------------------------------------------
// PTX helpers (compute_103-safe: sm_80-era instructions only)
// ---------------------------------------------------------------------------
__device__ __forceinline__ uint32_t smem_u32(const void* p) {
    uint32_t a;
    asm("{ .reg .u64 t; cvta.to.shared.u64 t, %1; cvt.u32.u64 %0, t; }"
        : "=r"(a) : "l"(p));
    return a;
}

__device__ __forceinline__ void cp16(uint32_t dst, const void* src) {
    asm volatile("cp.async.cg.shared.global [%0], [%1], 16;" :: "r"(dst), "l"(src));
}
__device__ __forceinline__ void cp_commit() { asm volatile("cp.async.commit_group;" ::: "memory"); }
__device__ __forceinline__ void cp_wait0()  { asm volatile("cp.async.wait_group 0;" ::: "memory"); }
__device__ __forceinline__ void cp_wait1()  { asm volatile("cp.async.wait_group 1;" ::: "memory"); }

__device__ __forceinline__ void ldsm_x4(uint32_t (&r)[4], uint32_t addr) {
    asm volatile("ldmatrix.sync.aligned.m8n8.x4.shared.b16 {%0,%1,%2,%3}, [%4];"
                 : "=r"(r[0]), "=r"(r[1]), "=r"(r[2]), "=r"(r[3]) : "r"(addr));
}
__device__ __forceinline__ void ldsm_x2(uint32_t (&r)[2], uint32_t addr) {
    asm volatile("ldmatrix.sync.aligned.m8n8.x2.shared.b16 {%0,%1}, [%2];"
                 : "=r"(r[0]), "=r"(r[1]) : "r"(addr));
}
__device__ __forceinline__ void ldsm_x4t(uint32_t (&r)[4], uint32_t addr) {
    asm volatile("ldmatrix.sync.aligned.m8n8.x4.trans.shared.b16 {%0,%1,%2,%3}, [%4];"
                 : "=r"(r[0]), "=r"(r[1]), "=r"(r[2]), "=r"(r[3]) : "r"(addr));
}

__device__ __forceinline__ void mma16816(float (&c)[4], const uint32_t (&a)[4],
                                         const uint32_t (&b)[2]) {
    asm volatile(
        "mma.sync.aligned.m16n8k16.row.col.f32.bf16.bf16.f32 "
        "{%0,%1,%2,%3}, {%4,%5,%6,%7}, {%8,%9}, {%0,%1,%2,%3};"
        : "+f"(c[0]), "+f"(c[1]), "+f"(c[2]), "+f"(c[3])
        : "r"(a[0]), "r"(a[1]), "r"(a[2]), "r"(a[3]), "r"(b[0]), "r"(b[1]));
}
__device__ __forceinline__ void mma16816v(float (&c)[4], const uint32_t (&a)[4],
                                          uint32_t b0, uint32_t b1) {
    asm volatile(
        "mma.sync.aligned.m16n8k16.row.col.f32.bf16.bf16.f32 "
        "{%0,%1,%2,%3}, {%4,%5,%6,%7}, {%8,%9}, {%0,%1,%2,%3};"
        : "+f"(c[0]), "+f"(c[1]), "+f"(c[2]), "+f"(c[3])
        : "r"(a[0]), "r"(a[1]), "r"(a[2]), "r"(a[3]), "r"(b0), "r"(b1));
}

__device__ __forceinline__ void split2(float a, float b, uint32_t &hi, uint32_t &lo) {
    __nv_bfloat16 ha = __float2bfloat16_rn(a), hb = __float2bfloat16_rn(b);
    float ra = a - __bfloat162float(ha), rb = b - __bfloat162float(hb);
    __nv_bfloat162 th = __halves2bfloat162(ha, hb);
    __nv_bfloat162 tl = __floats2bfloat162_rn(ra, rb);
    hi = *reinterpret_cast<uint32_t*>(&th);
    lo = *reinterpret_cast<uint32_t*>(&tl);
}

// ---------------------------------------------------------------------------
// RoPE cos/sin table
// ---------------------------------------------------------------------------
__global__ void rope_table_kernel(const int* __restrict__ pos)
{
    int idx = blockIdx.x * blockDim.x + threadIdx.x;
    if (idx >= S_ * (DH_ / 2)) return;
    int s = idx / (DH_ / 2);
    int i = idx % (DH_ / 2);
    float p    = (float)pos[s];
    float freq = powf(1.0f / 10000.0f, (2.0f * (float)i) / (float)DH_);
    float ang  = p * freq;
    g_rope[idx] = make_float2(cosf(ang), sinf(ang));
}

// ---------------------------------------------------------------------------
// fp32 -> bf16 hi/lo splits
// ---------------------------------------------------------------------------
__global__ void split_kernel(const float* __restrict__ src,
                             __nv_bfloat16* __restrict__ hi,
                             __nv_bfloat16* __restrict__ lo, int n4)
{
    int i = blockIdx.x * blockDim.x + threadIdx.x;
    if (i >= n4) return;
    float4 v = ((const float4*)src)[i];
    uint32_t h01, l01, h23, l23;
    split2(v.x, v.y, h01, l01);
    split2(v.z, v.w, h23, l23);
    ((uint32_t*)hi)[2 * i]     = h01;
    ((uint32_t*)hi)[2 * i + 1] = h23;
    ((uint32_t*)lo)[2 * i]     = l01;
    ((uint32_t*)lo)[2 * i + 1] = l23;
}

__global__ void split4_kernel(const float* __restrict__ s0, const float* __restrict__ s1,
                              const float* __restrict__ s2, const float* __restrict__ s3,
                              __nv_bfloat16* __restrict__ hi,
                              __nv_bfloat16* __restrict__ lo, int n4)
{
    int i = blockIdx.x * blockDim.x + threadIdx.x;
    if (i >= n4) return;
    const int y = blockIdx.y;
    const float* src = (y == 0) ? s0 : (y == 1) ? s1 : (y == 2) ? s2 : s3;
    const size_t off = (size_t)y * ((size_t)D_ * D_ / 2);   // in uint32 units
    float4 v = ((const float4*)src)[i];
    uint32_t h01, l01, h23, l23;
    split2(v.x, v.y, h01, l01);
    split2(v.z, v.w, h23, l23);
    ((uint32_t*)hi)[off + 2 * i]     = h01;
    ((uint32_t*)hi)[off + 2 * i + 1] = h23;
    ((uint32_t*)lo)[off + 2 * i]     = l01;
    ((uint32_t*)lo)[off + 2 * i + 1] = l23;
}

// ---------------------------------------------------------------------------
// bf16x3 GEMM core (R8 proven structure): 128x128 CTA tile, 256 threads
// (8 warps = 2m x 4n, warp tile 64x32), BK=32, 2-stage pipeline,
// wait -> sync -> prefetch -> compute -> sync. 2 CTAs/SM.
// ---------------------------------------------------------------------------
#define BK_       32
#define NCHUNK_   (D_ / BK_)            // 64
#define T_STRIDE_ 80
#define G_TILE_   (128 * T_STRIDE_)      // 10240
#define STAGE_B_  (4 * G_TILE_)          // 40960: [Ah|Al|Bh|Bl]
#define GEMM_SMEM (2 * STAGE_B_)         // 81920

__device__ __forceinline__ void load_stage(
    uint32_t base, const __nv_bfloat16* __restrict__ pAh,
    const __nv_bfloat16* __restrict__ pAl,
    const __nv_bfloat16* __restrict__ pBh,
    const __nv_bfloat16* __restrict__ pBl, int c, int tid)
{
#pragma unroll
    for (int v = 0; v < 2; v++) {
        int idx = tid + v * 256;          // 0..511
        int row = idx >> 2;               // 0..127
        int seg = idx & 3;
        const size_t go = (size_t)row * D_ + c * BK_ + seg * 8;
        const uint32_t so = row * T_STRIDE_ + seg * 16;
        cp16(base + so,                pAh + go);
        cp16(base + G_TILE_ + so,      pAl + go);
        cp16(base + 2 * G_TILE_ + so,  pBh + go);
        cp16(base + 3 * G_TILE_ + so,  pBl + go);
    }
}

__device__ __forceinline__ void gemm_tile_core(
    uint32_t sb, const __nv_bfloat16* pAh, const __nv_bfloat16* pAl,
    const __nv_bfloat16* pBh, const __nv_bfloat16* pBl,
    float (&acc)[4][4][4], int tid)
{
    const int lane   = tid & 31;
    const int wid    = tid >> 5;
    const int warp_m = wid & 1;      // 2 x 64 rows
    const int warp_n = wid >> 1;     // 4 x 32 cols

#pragma unroll
    for (int mt = 0; mt < 4; mt++)
#pragma unroll
        for (int nt = 0; nt < 4; nt++)
#pragma unroll
            for (int q = 0; q < 4; q++) acc[mt][nt][q] = 0.0f;

    load_stage(sb, pAh, pAl, pBh, pBl, 0, tid);
    cp_commit();

    const uint32_t a_lane = (lane & 15) * T_STRIDE_ + (lane >> 4) * 16
                          + warp_m * 64 * T_STRIDE_;
    const uint32_t b_lane = (lane & 7) * T_STRIDE_ + ((lane >> 3) & 1) * 16
                          + warp_n * 32 * T_STRIDE_;

    for (int c = 0; c < NCHUNK_; c++) {
        cp_wait0();            // own loads of chunk c done
        __syncthreads();       // ALL threads' chunk-c loads visible; all done
                               // reading the other stage

        if (c + 1 < NCHUNK_)   // prefetch overlaps this chunk's compute
            load_stage(sb + ((c + 1) & 1) * STAGE_B_, pAh, pAl, pBh, pBl, c + 1, tid);
        cp_commit();

        const uint32_t base = sb + (c & 1) * STAGE_B_;
#pragma unroll
        for (int s = 0; s < 2; s++) {
            const uint32_t abase = base + s * 32 + a_lane;
            const uint32_t bbase = base + 2 * G_TILE_ + s * 32 + b_lane;
            uint32_t ah[4][4], al[4][4], bh[4][2], bl[4][2];
#pragma unroll
            for (int mt = 0; mt < 4; mt++) {
                ldsm_x4(ah[mt], abase + mt * 16 * T_STRIDE_);
                ldsm_x4(al[mt], abase + G_TILE_ + mt * 16 * T_STRIDE_);
            }
#pragma unroll
            for (int nt = 0; nt < 4; nt++) {
                ldsm_x2(bh[nt], bbase + nt * 8 * T_STRIDE_);
                ldsm_x2(bl[nt], bbase + G_TILE_ + nt * 8 * T_STRIDE_);
            }
#pragma unroll
            for (int mt = 0; mt < 4; mt++)
#pragma unroll
                for (int nt = 0; nt < 4; nt++)
                    mma16816(acc[mt][nt], ah[mt], bh[nt]);
#pragma unroll
            for (int mt = 0; mt < 4; mt++)
#pragma unroll
                for (int nt = 0; nt < 4; nt++)
                    mma16816(acc[mt][nt], ah[mt], bl[nt]);
#pragma unroll
            for (int mt = 0; mt < 4; mt++)
#pragma unroll
                for (int nt = 0; nt < 4; nt++)
                    mma16816(acc[mt][nt], al[mt], bh[nt]);
        }
        __syncthreads();       // done reading this stage before next prefetch targets it
    }
}

// Fused Q/K/V projection: blockIdx.x = which*16 + nblock; Q,K get RoPE.
__global__ __launch_bounds__(256, 2) void gemm_qkv(
    const __nv_bfloat16* __restrict__ xhi, const __nv_bfloat16* __restrict__ xlo,
    const __nv_bfloat16* __restrict__ whi, const __nv_bfloat16* __restrict__ wlo,
    __nv_bfloat16* __restrict__ qhi, __nv_bfloat16* __restrict__ qlo,
    __nv_bfloat16* __restrict__ khi, __nv_bfloat16* __restrict__ klo,
    __nv_bfloat16* __restrict__ vhi, __nv_bfloat16* __restrict__ vlo)
{
    extern __shared__ __align__(128) char smem[];
    const uint32_t sb = smem_u32(smem);
    const int tid   = threadIdx.x;
    const int which = blockIdx.x >> 4;          // 0=Q 1=K 2=V
    const int bn    = (blockIdx.x & 15) * 128;
    const int bm    = blockIdx.y * 128;

    const __nv_bfloat16* pAh = xhi + (size_t)bm * D_;
    const __nv_bfloat16* pAl = xlo + (size_t)bm * D_;
    const __nv_bfloat16* pBh = whi + (size_t)which * D_ * D_ + (size_t)bn * D_;
    const __nv_bfloat16* pBl = wlo + (size_t)which * D_ * D_ + (size_t)bn * D_;

    float acc[4][4][4];
    gemm_tile_core(sb, pAh, pAl, pBh, pBl, acc, tid);

    __nv_bfloat16* Chi = (which == 0) ? qhi : (which == 1) ? khi : vhi;
    __nv_bfloat16* Clo = (which == 0) ? qlo : (which == 1) ? klo : vlo;
    const bool rope = (which < 2);

    const int lane = tid & 31;
    const int wid  = tid >> 5;
    const int warp_m = wid & 1, warp_n = wid >> 1;
    const int gid = lane >> 2, tig = lane & 3;
#pragma unroll
    for (int mt = 0; mt < 4; mt++) {
        const int row0 = bm + warp_m * 64 + mt * 16 + gid;
        const int row1 = row0 + 8;
        const int s0 = row0 & (S_ - 1);
        const int s1 = row1 & (S_ - 1);
#pragma unroll
        for (int nt = 0; nt < 4; nt++) {
            const int col  = bn + warp_n * 32 + nt * 8 + tig * 2;
            float c0 = acc[mt][nt][0], c1 = acc[mt][nt][1];
            float c2 = acc[mt][nt][2], c3 = acc[mt][nt][3];
            if (rope) {
                const int pr = (col & (DH_ - 1)) >> 1;
                float2 csa = g_rope[s0 * (DH_ / 2) + pr];
                float2 csb = g_rope[s1 * (DH_ / 2) + pr];
                float e0 = c0, o0 = c1, e1 = c2, o1 = c3;
                c0 = e0 * csa.x - o0 * csa.y;
                c1 = e0 * csa.y + o0 * csa.x;
                c2 = e1 * csb.x - o1 * csb.y;
                c3 = e1 * csb.y + o1 * csb.x;
            }
            uint32_t h01, l01, h23, l23;
            split2(c0, c1, h01, l01);
            split2(c2, c3, h23, l23);
            *(uint32_t*)(Chi + (size_t)row0 * D_ + col) = h01;
            *(uint32_t*)(Clo + (size_t)row0 * D_ + col) = l01;
            *(uint32_t*)(Chi + (size_t)row1 * D_ + col) = h23;
            *(uint32_t*)(Clo + (size_t)row1 * D_ + col) = l23;
        }
    }
}

// Output projection: fp32 out.
__global__ __launch_bounds__(256, 2) void gemm_out(
    const __nv_bfloat16* __restrict__ Ahi, const __nv_bfloat16* __restrict__ Alo,
    const __nv_bfloat16* __restrict__ Bhi, const __nv_bfloat16* __restrict__ Blo,
    float* __restrict__ C)
{
    extern __shared__ __align__(128) char smem[];
    const uint32_t sb = smem_u32(smem);
    const int tid = threadIdx.x;
    const int bn  = blockIdx.x * 128;
    const int bm  = blockIdx.y * 128;

    const __nv_bfloat16* pAh = Ahi + (size_t)bm * D_;
    const __nv_bfloat16* pAl = Alo + (size_t)bm * D_;
    const __nv_bfloat16* pBh = Bhi + (size_t)bn * D_;
    const __nv_bfloat16* pBl = Blo + (size_t)bn * D_;

    float acc[4][4][4];
    gemm_tile_core(sb, pAh, pAl, pBh, pBl, acc, tid);

    const int lane = tid & 31;
    const int wid  = tid >> 5;
    const int warp_m = wid & 1, warp_n = wid >> 1;
    const int gid = lane >> 2, tig = lane & 3;
#pragma unroll
    for (int mt = 0; mt < 4; mt++) {
        const int row0 = bm + warp_m * 64 + mt * 16 + gid;
        const int row1 = row0 + 8;
#pragma unroll
        for (int nt = 0; nt < 4; nt++) {
            const int col = bn + warp_n * 32 + nt * 8 + tig * 2;
            *(float2*)(C + (size_t)row0 * D_ + col) = make_float2(acc[mt][nt][0], acc[mt][nt][1]);
            *(float2*)(C + (size_t)row1 * D_ + col) = make_float2(acc[mt][nt][2], acc[mt][nt][3]);
        }
    }
}

// ---------------------------------------------------------------------------
// Flash attention on mma.sync bf16, 2 CTAs/SM version.
// CTA = 128 q rows of one (b,h); 256 threads = 8 warps x 16 rows;
// key tiles of 16, double-buffered cp.async (wait -> sync order preserved).
// Rescale skipped when no row's max changed (warp-uniform vote).
// ---------------------------------------------------------------------------
#define FL_STRIDE 272
#define FL_QTILE  (128 * FL_STRIDE)      // 34816
#define FL_KTILE  (16 * FL_STRIDE)       // 4352
#define FL_STAGE  (4 * FL_KTILE)         // 17408
#define FL_SMEM   (2 * FL_QTILE + 2 * FL_STAGE)  // 104448

__device__ __forceinline__ void flash_load_kv(
    uint32_t base, const __nv_bfloat16* Kh, const __nv_bfloat16* Kl,
    const __nv_bfloat16* Vh, const __nv_bfloat16* Vl, int kt, int tid)
{
    const int row = tid >> 4;             // 0..15
    const int seg = tid & 15;
    const size_t go = ((size_t)kt * 16 + row) * D_ + seg * 8;
    const uint32_t so = row * FL_STRIDE + seg * 16;
    cp16(base + so,                 Kh + go);
    cp16(base + FL_KTILE + so,      Kl + go);
    cp16(base + 2 * FL_KTILE + so,  Vh + go);
    cp16(base + 3 * FL_KTILE + so,  Vl + go);
}

__global__ __launch_bounds__(256, 2) void flash_mma()
{
    extern __shared__ __align__(128) char fsm[];
    const uint32_t sb  = smem_u32(fsm);
    const uint32_t sQh = sb;
    const uint32_t sQl = sb + FL_QTILE;
    const uint32_t sKV = sb + 2 * FL_QTILE;

    const int tid  = threadIdx.x;
    const int lane = tid & 31;
    const int w    = tid >> 5;            // 0..7
    const int gid  = lane >> 2, tig = lane & 3;
    const int bh   = blockIdx.y;
    const int b    = bh >> 4;
    const int h    = bh & 15;
    const int qt   = (int)gridDim.x - 1 - (int)blockIdx.x;   // heavy first
    const int q0   = qt * 128;
    const int nkt  = 8 * (qt + 1);

    const __nv_bfloat16* Qh = g_Qhi + ((size_t)(b * S_ + q0)) * D_ + h * DH_;
    const __nv_bfloat16* Ql = g_Qlo + ((size_t)(b * S_ + q0)) * D_ + h * DH_;
    const __nv_bfloat16* Kh = g_Khi + ((size_t)b * S_) * D_ + h * DH_;
    const __nv_bfloat16* Kl = g_Klo + ((size_t)b * S_) * D_ + h * DH_;
    const __nv_bfloat16* Vh = g_Vhi + ((size_t)b * S_) * D_ + h * DH_;
    const __nv_bfloat16* Vl = g_Vlo + ((size_t)b * S_) * D_ + h * DH_;

    // Q tiles (128 rows x 128 cols, hi+lo) + first two KV stages
#pragma unroll
    for (int v = 0; v < 8; v++) {
        int idx = tid + v * 256;          // 0..2047
        int row = idx >> 4;               // 0..127
        int seg = idx & 15;
        const size_t go = (size_t)row * D_ + seg * 8;
        const uint32_t so = row * FL_STRIDE + seg * 16;
        cp16(sQh + so, Qh + go);
        cp16(sQl + so, Ql + go);
    }
    flash_load_kv(sKV, Kh, Kl, Vh, Vl, 0, tid);
    cp_commit();
    flash_load_kv(sKV + FL_STAGE, Kh, Kl, Vh, Vl, 1, tid);
    cp_commit();

    float accO[16][4];
#pragma unroll
    for (int nt = 0; nt < 16; nt++)
#pragma unroll
        for (int q = 0; q < 4; q++) accO[nt][q] = 0.0f;
    float m0 = -INFINITY, m1 = -INFINITY, l0 = 0.0f, l1 = 0.0f;

    const float scale = 0.08838834764831845f;  // 1/sqrt(128)
    const int rq0 = q0 + w * 16 + gid;
    const int rq1 = rq0 + 8;

    const uint32_t a_lane = (w * 16 + (lane & 15)) * FL_STRIDE + (lane >> 4) * 16;
    const uint32_t kb_lane = ((lane & 7) + (lane >> 4) * 8) * FL_STRIDE
                           + ((lane >> 3) & 1) * 16;
    const uint32_t v_lane = (lane & 15) * FL_STRIDE + (lane >> 4) * 16;

    for (int kt = 0; kt < nkt; kt++) {
        cp_wait1();
        __syncthreads();
        const uint32_t kbh = sKV + (kt & 1) * FL_STAGE;
        const uint32_t kbl = kbh + FL_KTILE;
        const uint32_t vbh = kbh + 2 * FL_KTILE;
        const uint32_t vbl = kbh + 3 * FL_KTILE;

        // ---- S = Q @ K^T (3-term split), 16 keys ----
        float sf[2][4];
#pragma unroll
        for (int nt = 0; nt < 2; nt++)
#pragma unroll
            for (int q = 0; q < 4; q++) sf[nt][q] = 0.0f;

#pragma unroll
        for (int ks = 0; ks < 8; ks++) {
            uint32_t ah[4], al[4], bh4[4], bl4[4];
            ldsm_x4(ah, sQh + a_lane + ks * 32);
            ldsm_x4(al, sQl + a_lane + ks * 32);
            ldsm_x4(bh4, kbh + kb_lane + ks * 32);
            ldsm_x4(bl4, kbl + kb_lane + ks * 32);
            mma16816v(sf[0], ah, bh4[0], bh4[1]);
            mma16816v(sf[0], ah, bl4[0], bl4[1]);
            mma16816v(sf[0], al, bh4[0], bh4[1]);
            mma16816v(sf[1], ah, bh4[2], bh4[3]);
            mma16816v(sf[1], ah, bl4[2], bl4[3]);
            mma16816v(sf[1], al, bh4[2], bh4[3]);
        }

        // ---- scale + causal mask ----
        const bool msk = (kt >= nkt - 8);
#pragma unroll
        for (int nt = 0; nt < 2; nt++) {
            const int col = kt * 16 + nt * 8 + 2 * tig;
            sf[nt][0] *= scale; sf[nt][1] *= scale;
            sf[nt][2] *= scale; sf[nt][3] *= scale;
            if (msk) {
                if (col     > rq0) sf[nt][0] = -INFINITY;
                if (col + 1 > rq0) sf[nt][1] = -INFINITY;
                if (col     > rq1) sf[nt][2] = -INFINITY;
                if (col + 1 > rq1) sf[nt][3] = -INFINITY;
            }
        }

        // ---- online softmax (rows rq0, rq1; reduce over quad lanes) ----
        float mx0 = fmaxf(fmaxf(sf[0][0], sf[0][1]), fmaxf(sf[1][0], sf[1][1]));
        float mx1 = fmaxf(fmaxf(sf[0][2], sf[0][3]), fmaxf(sf[1][2], sf[1][3]));
        mx0 = fmaxf(mx0, __shfl_xor_sync(0xffffffffu, mx0, 1));
        mx0 = fmaxf(mx0, __shfl_xor_sync(0xffffffffu, mx0, 2));
        mx1 = fmaxf(mx1, __shfl_xor_sync(0xffffffffu, mx1, 1));
        mx1 = fmaxf(mx1, __shfl_xor_sync(0xffffffffu, mx1, 2));

        const bool upd = (mx0 > m0) || (mx1 > m1);
        const float mn0 = fmaxf(m0, mx0), mn1 = fmaxf(m1, mx1);
        const float cr0 = __expf(m0 - mn0), cr1 = __expf(m1 - mn1);

        float sum0 = 0.0f, sum1 = 0.0f;
#pragma unroll
        for (int nt = 0; nt < 2; nt++) {
            sf[nt][0] = __expf(sf[nt][0] - mn0);
            sf[nt][1] = __expf(sf[nt][1] - mn0);
            sf[nt][2] = __expf(sf[nt][2] - mn1);
            sf[nt][3] = __expf(sf[nt][3] - mn1);
            sum0 += sf[nt][0] + sf[nt][1];
            sum1 += sf[nt][2] + sf[nt][3];
        }
        sum0 += __shfl_xor_sync(0xffffffffu, sum0, 1);
        sum0 += __shfl_xor_sync(0xffffffffu, sum0, 2);
        sum1 += __shfl_xor_sync(0xffffffffu, sum1, 1);
        sum1 += __shfl_xor_sync(0xffffffffu, sum1, 2);
        l0 = l0 * cr0 + sum0; m0 = mn0;
        l1 = l1 * cr1 + sum1; m1 = mn1;

        // Skip the accO rescale when no row in this warp saw a new max.
        if (__any_sync(0xffffffffu, upd)) {
#pragma unroll
            for (int nt = 0; nt < 16; nt++) {
                accO[nt][0] *= cr0; accO[nt][1] *= cr0;
                accO[nt][2] *= cr1; accO[nt][3] *= cr1;
            }
        }

        // ---- pack P hi/lo A-fragment (one k-step of 16 keys) ----
        uint32_t pah[4], pal[4];
        split2(sf[0][0], sf[0][1], pah[0], pal[0]);
        split2(sf[0][2], sf[0][3], pah[1], pal[1]);
        split2(sf[1][0], sf[1][1], pah[2], pal[2]);
        split2(sf[1][2], sf[1][3], pah[3], pal[3]);

        // ---- O += P @ V (3-term split), V via ldmatrix trans ----
#pragma unroll
        for (int ntp = 0; ntp < 8; ntp++) {
            uint32_t vh4[4], vl4[4];
            const uint32_t va = ntp * 32 + v_lane;
            ldsm_x4t(vh4, vbh + va);
            ldsm_x4t(vl4, vbl + va);
            mma16816v(accO[2 * ntp],     pah, vh4[0], vh4[1]);
            mma16816v(accO[2 * ntp],     pal, vh4[0], vh4[1]);
            mma16816v(accO[2 * ntp],     pah, vl4[0], vl4[1]);
            mma16816v(accO[2 * ntp + 1], pah, vh4[2], vh4[3]);
            mma16816v(accO[2 * ntp + 1], pal, vh4[2], vh4[3]);
            mma16816v(accO[2 * ntp + 1], pah, vl4[2], vl4[3]);
        }

        __syncthreads();   // all warps done reading this stage
        if (kt + 2 < nkt)
            flash_load_kv(kbh, Kh, Kl, Vh, Vl, kt + 2, tid);
        cp_commit();
    }

    // ---- epilogue: normalize, split to bf16 hi/lo ----
    const float inv0 = 1.0f / l0, inv1 = 1.0f / l1;
    __nv_bfloat16* Oh = g_Ohi + ((size_t)(b * S_ + q0 + w * 16)) * D_ + h * DH_;
    __nv_bfloat16* Ol = g_Olo + ((size_t)(b * S_ + q0 + w * 16)) * D_ + h * DH_;
#pragma unroll
    for (int nt = 0; nt < 16; nt++) {
        const int col = nt * 8 + 2 * tig;
        uint32_t h01, l01, h23, l23;
        split2(accO[nt][0] * inv0, accO[nt][1] * inv0, h01, l01);
        split2(accO[nt][2] * inv1, accO[nt][3] * inv1, h23, l23);
        *(uint32_t*)(Oh + (size_t)gid * D_ + col)       = h01;
        *(uint32_t*)(Ol + (size_t)gid * D_ + col)       = l01;
        *(uint32_t*)(Oh + (size_t)(gid + 8) * D_ + col) = h23;
        *(uint32_t*)(Ol + (size_t)(gid + 8) * D_ + col) = l23;
    }
}

// ---------------------------------------------------------------------------
// Launch
// ---------------------------------------------------------------------------
extern "C" void kernel_launch(void* const* d_in, const int* in_sizes, int n_in,
                              void* d_out, int out_size)
{
    const float* x   = (const float*)d_in[0];
    const int*   pos = (const int*)  d_in[1];
    const float* Wq  = (const float*)d_in[2];
    const float* Wk  = (const float*)d_in[3];
    const float* Wv  = (const float*)d_in[4];
    const float* Wo  = (const float*)d_in[5];
    float*       out = (float*)d_out;

    __nv_bfloat16 *xhi, *xlo, *whi, *wlo;
    __nv_bfloat16 *qhi, *qlo, *khi, *klo, *vhi, *vlo, *ohi, *olo;
    cudaGetSymbolAddress((void**)&xhi, g_xhi);
    cudaGetSymbolAddress((void**)&xlo, g_xlo);
    cudaGetSymbolAddress((void**)&whi, g_Whi);
    cudaGetSymbolAddress((void**)&wlo, g_Wlo);
    cudaGetSymbolAddress((void**)&qhi, g_Qhi);
    cudaGetSymbolAddress((void**)&qlo, g_Qlo);
    cudaGetSymbolAddress((void**)&khi, g_Khi);
    cudaGetSymbolAddress((void**)&klo, g_Klo);
    cudaGetSymbolAddress((void**)&vhi, g_Vhi);
    cudaGetSymbolAddress((void**)&vlo, g_Vlo);
    cudaGetSymbolAddress((void**)&ohi, g_Ohi);
    cudaGetSymbolAddress((void**)&olo, g_Olo);

    cudaFuncSetAttribute(gemm_qkv, cudaFuncAttributeMaxDynamicSharedMemorySize, GEMM_SMEM);
    cudaFuncSetAttribute(gemm_out, cudaFuncAttributeMaxDynamicSharedMemorySize, GEMM_SMEM);
    cudaFuncSetAttribute(flash_mma, cudaFuncAttributeMaxDynamicSharedMemorySize, FL_SMEM);

    const int nx4 = M_ * D_ / 4;
    const int nw4 = D_ * D_ / 4;

    rope_table_kernel<<<(S_ * (DH_ / 2) + 255) / 256, 256>>>(pos);
    split_kernel<<<(nx4 + 255) / 256, 256>>>(x, xhi, xlo, nx4);
    split4_kernel<<<dim3((nw4 + 255) / 256, 4), 256>>>(Wq, Wk, Wv, Wo, whi, wlo, nw4);

    gemm_qkv<<<dim3(48, 32), 256, GEMM_SMEM>>>(xhi, xlo, whi, wlo,
                                               qhi, qlo, khi, klo, vhi, vlo);

    flash_mma<<<dim3(S_ / 128, B_ * H_), 256, FL_SMEM>>>();

    gemm_out<<<dim3(16, 32), 256, GEMM_SMEM>>>(ohi, olo,
                                               whi + 3 * (size_t)D_ * D_,
                                               wlo + 3 * (size_t)D_ * D_, out);
}

// round 15
// speedup vs baseline: 3.1367x; 1.0930x over previous
#include <cuda_runtime.h>
#include <cuda_bf16.h>
#include <math.h>
#include <stdint.h>

// Problem constants
#define B_  2
#define S_  2048
#define D_  2048
#define H_  16
#define DH_ 128
#define M_  (B_*S_)   // 4096

// ---------------------------------------------------------------------------
// Scratch (no cudaMalloc allowed)
// ---------------------------------------------------------------------------
__device__ __align__(16) float2 g_rope[S_ * (DH_ / 2)];

__device__ __align__(16) __nv_bfloat16 g_xhi[(size_t)M_ * D_];
__device__ __align__(16) __nv_bfloat16 g_xlo[(size_t)M_ * D_];
__device__ __align__(16) __nv_bfloat16 g_Whi[(size_t)4 * D_ * D_];
__device__ __align__(16) __nv_bfloat16 g_Wlo[(size_t)4 * D_ * D_];
__device__ __align__(16) __nv_bfloat16 g_Qhi[(size_t)M_ * D_];
__device__ __align__(16) __nv_bfloat16 g_Qlo[(size_t)M_ * D_];
__device__ __align__(16) __nv_bfloat16 g_Khi[(size_t)M_ * D_];
__device__ __align__(16) __nv_bfloat16 g_Klo[(size_t)M_ * D_];
__device__ __align__(16) __nv_bfloat16 g_Vhi[(size_t)M_ * D_];
__device__ __align__(16) __nv_bfloat16 g_Vlo[(size_t)M_ * D_];
__device__ __align__(16) __nv_bfloat16 g_Ohi[(size_t)M_ * D_];
__device__ __align__(16) __nv_bfloat16 g_Olo[(size_t)M_ * D_];

// ---------------------------------------------------------------------------
// PTX helpers (compute_103-safe: sm_80-era instructions only)
// ---------------------------------------------------------------------------
__device__ __forceinline__ uint32_t smem_u32(const void* p) {
    uint32_t a;
    asm("{ .reg .u64 t; cvta.to.shared.u64 t, %1; cvt.u32.u64 %0, t; }"
        : "=r"(a) : "l"(p));
    return a;
}

__device__ __forceinline__ void cp16(uint32_t dst, const void* src) {
    asm volatile("cp.async.cg.shared.global [%0], [%1], 16;" :: "r"(dst), "l"(src));
}
__device__ __forceinline__ void cp_commit() { asm volatile("cp.async.commit_group;" ::: "memory"); }
__device__ __forceinline__ void cp_wait0()  { asm volatile("cp.async.wait_group 0;" ::: "memory"); }
__device__ __forceinline__ void cp_wait1()  { asm volatile("cp.async.wait_group 1;" ::: "memory"); }

__device__ __forceinline__ void ldsm_x4(uint32_t (&r)[4], uint32_t addr) {
    asm volatile("ldmatrix.sync.aligned.m8n8.x4.shared.b16 {%0,%1,%2,%3}, [%4];"
                 : "=r"(r[0]), "=r"(r[1]), "=r"(r[2]), "=r"(r[3]) : "r"(addr));
}
__device__ __forceinline__ void ldsm_x2(uint32_t (&r)[2], uint32_t addr) {
    asm volatile("ldmatrix.sync.aligned.m8n8.x2.shared.b16 {%0,%1}, [%2];"
                 : "=r"(r[0]), "=r"(r[1]) : "r"(addr));
}
__device__ __forceinline__ void ldsm_x4t(uint32_t (&r)[4], uint32_t addr) {
    asm volatile("ldmatrix.sync.aligned.m8n8.x4.trans.shared.b16 {%0,%1,%2,%3}, [%4];"
                 : "=r"(r[0]), "=r"(r[1]), "=r"(r[2]), "=r"(r[3]) : "r"(addr));
}

__device__ __forceinline__ void mma16816(float (&c)[4], const uint32_t (&a)[4],
                                         const uint32_t (&b)[2]) {
    asm volatile(
        "mma.sync.aligned.m16n8k16.row.col.f32.bf16.bf16.f32 "
        "{%0,%1,%2,%3}, {%4,%5,%6,%7}, {%8,%9}, {%0,%1,%2,%3};"
        : "+f"(c[0]), "+f"(c[1]), "+f"(c[2]), "+f"(c[3])
        : "r"(a[0]), "r"(a[1]), "r"(a[2]), "r"(a[3]), "r"(b[0]), "r"(b[1]));
}
__device__ __forceinline__ void mma16816v(float (&c)[4], const uint32_t (&a)[4],
                                          uint32_t b0, uint32_t b1) {
    asm volatile(
        "mma.sync.aligned.m16n8k16.row.col.f32.bf16.bf16.f32 "
        "{%0,%1,%2,%3}, {%4,%5,%6,%7}, {%8,%9}, {%0,%1,%2,%3};"
        : "+f"(c[0]), "+f"(c[1]), "+f"(c[2]), "+f"(c[3])
        : "r"(a[0]), "r"(a[1]), "r"(a[2]), "r"(a[3]), "r"(b0), "r"(b1));
}

__device__ __forceinline__ void split2(float a, float b, uint32_t &hi, uint32_t &lo) {
    __nv_bfloat16 ha = __float2bfloat16_rn(a), hb = __float2bfloat16_rn(b);
    float ra = a - __bfloat162float(ha), rb = b - __bfloat162float(hb);
    __nv_bfloat162 th = __halves2bfloat162(ha, hb);
    __nv_bfloat162 tl = __floats2bfloat162_rn(ra, rb);
    hi = *reinterpret_cast<uint32_t*>(&th);
    lo = *reinterpret_cast<uint32_t*>(&tl);
}

// ---------------------------------------------------------------------------
// RoPE cos/sin table
// ---------------------------------------------------------------------------
__global__ void rope_table_kernel(const int* __restrict__ pos)
{
    int idx = blockIdx.x * blockDim.x + threadIdx.x;
    if (idx >= S_ * (DH_ / 2)) return;
    int s = idx / (DH_ / 2);
    int i = idx % (DH_ / 2);
    float p    = (float)pos[s];
    float freq = powf(1.0f / 10000.0f, (2.0f * (float)i) / (float)DH_);
    float ang  = p * freq;
    g_rope[idx] = make_float2(cosf(ang), sinf(ang));
}

// ---------------------------------------------------------------------------
// fp32 -> bf16 hi/lo splits
// ---------------------------------------------------------------------------
__global__ void split_kernel(const float* __restrict__ src,
                             __nv_bfloat16* __restrict__ hi,
                             __nv_bfloat16* __restrict__ lo, int n4)
{
    int i = blockIdx.x * blockDim.x + threadIdx.x;
    if (i >= n4) return;
    float4 v = ((const float4*)src)[i];
    uint32_t h01, l01, h23, l23;
    split2(v.x, v.y, h01, l01);
    split2(v.z, v.w, h23, l23);
    ((uint32_t*)hi)[2 * i]     = h01;
    ((uint32_t*)hi)[2 * i + 1] = h23;
    ((uint32_t*)lo)[2 * i]     = l01;
    ((uint32_t*)lo)[2 * i + 1] = l23;
}

__global__ void split4_kernel(const float* __restrict__ s0, const float* __restrict__ s1,
                              const float* __restrict__ s2, const float* __restrict__ s3,
                              __nv_bfloat16* __restrict__ hi,
                              __nv_bfloat16* __restrict__ lo, int n4)
{
    int i = blockIdx.x * blockDim.x + threadIdx.x;
    if (i >= n4) return;
    const int y = blockIdx.y;
    const float* src = (y == 0) ? s0 : (y == 1) ? s1 : (y == 2) ? s2 : s3;
    const size_t off = (size_t)y * ((size_t)D_ * D_ / 2);   // in uint32 units
    float4 v = ((const float4*)src)[i];
    uint32_t h01, l01, h23, l23;
    split2(v.x, v.y, h01, l01);
    split2(v.z, v.w, h23, l23);
    ((uint32_t*)hi)[off + 2 * i]     = h01;
    ((uint32_t*)hi)[off + 2 * i + 1] = h23;
    ((uint32_t*)lo)[off + 2 * i]     = l01;
    ((uint32_t*)lo)[off + 2 * i + 1] = l23;
}

// ---------------------------------------------------------------------------
// bf16x3 GEMM core: 128x128 CTA tile, 256 threads (8 warps = 2m x 4n,
// warp tile 64x32), BK=32, THREE-stage pipeline, one barrier per chunk.
// Smem rows interleave hi|lo (128B rows) with SW128-style XOR swizzle
// (seg ^ (row&7)) -> conflict-free ldmatrix, zero padding. 2 CTAs/SM.
// Per iter c: wait_group(1) proves groups <= c done (c+1, c+2 in flight);
// barrier; prefetch chunk c+2 into stage (c+2)%3 (read last as chunk c-1);
// compute chunk c.
// ---------------------------------------------------------------------------
#define BK_       32
#define NCHUNK_   (D_ / BK_)            // 64
#define AI_TILE_  (128 * 128)            // 16384: [Ah|Al] interleaved rows
#define STAGE_B_  (2 * AI_TILE_)         // 32768: [A-interleaved | B-interleaved]
#define NSTAGE_   3
#define GEMM_SMEM (NSTAGE_ * STAGE_B_)   // 98304

// seg 0..7 within a 128B row; swizzled offset
#define SWZ(row, seg) (((uint32_t)(row)) * 128u + ((((uint32_t)(seg)) ^ (((uint32_t)(row)) & 7u)) * 16u))

__device__ __forceinline__ void load_stage(
    uint32_t base, const __nv_bfloat16* __restrict__ pAh,
    const __nv_bfloat16* __restrict__ pAl,
    const __nv_bfloat16* __restrict__ pBh,
    const __nv_bfloat16* __restrict__ pBl, int c, int tid)
{
    const int seg  = tid & 7;        // fixed 16B seg per thread (logical)
    const int xseg = seg & 3;        // seg within hi or lo half
    const bool lo  = (seg >= 4);
    const __nv_bfloat16* srcA = lo ? pAl : pAh;
    const __nv_bfloat16* srcB = lo ? pBl : pBh;
#pragma unroll
    for (int v = 0; v < 4; v++) {
        int row = (tid >> 3) + v * 32;           // 0..127
        cp16(base + SWZ(row, seg),
             srcA + (size_t)row * D_ + c * BK_ + xseg * 8);
    }
#pragma unroll
    for (int v = 0; v < 4; v++) {
        int row = (tid >> 3) + v * 32;           // 0..127
        cp16(base + AI_TILE_ + SWZ(row, seg),
             srcB + (size_t)row * D_ + c * BK_ + xseg * 8);
    }
}

__device__ __forceinline__ void gemm_tile_core(
    uint32_t sb, const __nv_bfloat16* pAh, const __nv_bfloat16* pAl,
    const __nv_bfloat16* pBh, const __nv_bfloat16* pBl,
    float (&acc)[4][4][4], int tid)
{
    const int lane   = tid & 31;
    const int wid    = tid >> 5;
    const int warp_m = wid & 1;      // 2 x 64 rows
    const int warp_n = wid >> 1;     // 4 x 32 cols

#pragma unroll
    for (int mt = 0; mt < 4; mt++)
#pragma unroll
        for (int nt = 0; nt < 4; nt++)
#pragma unroll
            for (int q = 0; q < 4; q++) acc[mt][nt][q] = 0.0f;

    load_stage(sb,            pAh, pAl, pBh, pBl, 0, tid); cp_commit();
    load_stage(sb + STAGE_B_, pAh, pAl, pBh, pBl, 1, tid); cp_commit();

    // Per-lane fragment address components
    const int ar  = warp_m * 64 + (lane & 15);   // A row (+ mt*16)
    const int axr = ar & 7;                      // invariant under +mt*16
    const int ak  = lane >> 4;                   // 16B k-half select
    const int br  = warp_n * 32 + (lane & 7);    // B row (+ nt*8)
    const int bxr = lane & 7;                    // invariant under +nt*8
    const int bk  = (lane >> 3) & 1;

    for (int c = 0; c < NCHUNK_; c++) {
        cp_wait1();            // own groups <= c complete (c+1 may be in flight)
        __syncthreads();       // all threads' chunk-c writes visible; all
                               // finished reading stage (c+2)%3 (chunk c-1)

        if (c + 2 < NCHUNK_)
            load_stage(sb + ((c + 2) % NSTAGE_) * STAGE_B_,
                       pAh, pAl, pBh, pBl, c + 2, tid);
        cp_commit();           // (empty group near the tail keeps counts aligned)

        const uint32_t bA = sb + (c % NSTAGE_) * STAGE_B_;
        const uint32_t bB = bA + AI_TILE_;
#pragma unroll
        for (int s = 0; s < 2; s++) {
            uint32_t ah[4][4], al[4][4], bh[4][2], bl[4][2];
#pragma unroll
            for (int mt = 0; mt < 4; mt++) {
                const int r = ar + mt * 16;
                ldsm_x4(ah[mt], bA + r * 128 + (((2 * s + ak)     ^ axr) * 16));
                ldsm_x4(al[mt], bA + r * 128 + (((4 + 2 * s + ak) ^ axr) * 16));
            }
#pragma unroll
            for (int nt = 0; nt < 4; nt++) {
                const int r = br + nt * 8;
                ldsm_x2(bh[nt], bB + r * 128 + (((2 * s + bk)     ^ bxr) * 16));
                ldsm_x2(bl[nt], bB + r * 128 + (((4 + 2 * s + bk) ^ bxr) * 16));
            }
#pragma unroll
            for (int mt = 0; mt < 4; mt++)
#pragma unroll
                for (int nt = 0; nt < 4; nt++)
                    mma16816(acc[mt][nt], ah[mt], bh[nt]);
#pragma unroll
            for (int mt = 0; mt < 4; mt++)
#pragma unroll
                for (int nt = 0; nt < 4; nt++)
                    mma16816(acc[mt][nt], ah[mt], bl[nt]);
#pragma unroll
            for (int mt = 0; mt < 4; mt++)
#pragma unroll
                for (int nt = 0; nt < 4; nt++)
                    mma16816(acc[mt][nt], al[mt], bh[nt]);
        }
    }
}

// Fused Q/K/V projection: blockIdx.x = which*16 + nblock; Q,K get RoPE.
__global__ __launch_bounds__(256, 2) void gemm_qkv(
    const __nv_bfloat16* __restrict__ xhi, const __nv_bfloat16* __restrict__ xlo,
    const __nv_bfloat16* __restrict__ whi, const __nv_bfloat16* __restrict__ wlo,
    __nv_bfloat16* __restrict__ qhi, __nv_bfloat16* __restrict__ qlo,
    __nv_bfloat16* __restrict__ khi, __nv_bfloat16* __restrict__ klo,
    __nv_bfloat16* __restrict__ vhi, __nv_bfloat16* __restrict__ vlo)
{
    extern __shared__ __align__(128) char smem[];
    const uint32_t sb = smem_u32(smem);
    const int tid   = threadIdx.x;
    const int which = blockIdx.x >> 4;          // 0=Q 1=K 2=V
    const int bn    = (blockIdx.x & 15) * 128;
    const int bm    = blockIdx.y * 128;

    const __nv_bfloat16* pAh = xhi + (size_t)bm * D_;
    const __nv_bfloat16* pAl = xlo + (size_t)bm * D_;
    const __nv_bfloat16* pBh = whi + (size_t)which * D_ * D_ + (size_t)bn * D_;
    const __nv_bfloat16* pBl = wlo + (size_t)which * D_ * D_ + (size_t)bn * D_;

    float acc[4][4][4];
    gemm_tile_core(sb, pAh, pAl, pBh, pBl, acc, tid);

    __nv_bfloat16* Chi = (which == 0) ? qhi : (which == 1) ? khi : vhi;
    __nv_bfloat16* Clo = (which == 0) ? qlo : (which == 1) ? klo : vlo;
    const bool rope = (which < 2);

    const int lane = tid & 31;
    const int wid  = tid >> 5;
    const int warp_m = wid & 1, warp_n = wid >> 1;
    const int gid = lane >> 2, tig = lane & 3;
#pragma unroll
    for (int mt = 0; mt < 4; mt++) {
        const int row0 = bm + warp_m * 64 + mt * 16 + gid;
        const int row1 = row0 + 8;
        const int s0 = row0 & (S_ - 1);
        const int s1 = row1 & (S_ - 1);
#pragma unroll
        for (int nt = 0; nt < 4; nt++) {
            const int col  = bn + warp_n * 32 + nt * 8 + tig * 2;
            float c0 = acc[mt][nt][0], c1 = acc[mt][nt][1];
            float c2 = acc[mt][nt][2], c3 = acc[mt][nt][3];
            if (rope) {
                const int pr = (col & (DH_ - 1)) >> 1;
                float2 csa = g_rope[s0 * (DH_ / 2) + pr];
                float2 csb = g_rope[s1 * (DH_ / 2) + pr];
                float e0 = c0, o0 = c1, e1 = c2, o1 = c3;
                c0 = e0 * csa.x - o0 * csa.y;
                c1 = e0 * csa.y + o0 * csa.x;
                c2 = e1 * csb.x - o1 * csb.y;
                c3 = e1 * csb.y + o1 * csb.x;
            }
            uint32_t h01, l01, h23, l23;
            split2(c0, c1, h01, l01);
            split2(c2, c3, h23, l23);
            *(uint32_t*)(Chi + (size_t)row0 * D_ + col) = h01;
            *(uint32_t*)(Clo + (size_t)row0 * D_ + col) = l01;
            *(uint32_t*)(Chi + (size_t)row1 * D_ + col) = h23;
            *(uint32_t*)(Clo + (size_t)row1 * D_ + col) = l23;
        }
    }
}

// Output projection: fp32 out.
__global__ __launch_bounds__(256, 2) void gemm_out(
    const __nv_bfloat16* __restrict__ Ahi, const __nv_bfloat16* __restrict__ Alo,
    const __nv_bfloat16* __restrict__ Bhi, const __nv_bfloat16* __restrict__ Blo,
    float* __restrict__ C)
{
    extern __shared__ __align__(128) char smem[];
    const uint32_t sb = smem_u32(smem);
    const int tid = threadIdx.x;
    const int bn  = blockIdx.x * 128;
    const int bm  = blockIdx.y * 128;

    const __nv_bfloat16* pAh = Ahi + (size_t)bm * D_;
    const __nv_bfloat16* pAl = Alo + (size_t)bm * D_;
    const __nv_bfloat16* pBh = Bhi + (size_t)bn * D_;
    const __nv_bfloat16* pBl = Blo + (size_t)bn * D_;

    float acc[4][4][4];
    gemm_tile_core(sb, pAh, pAl, pBh, pBl, acc, tid);

    const int lane = tid & 31;
    const int wid  = tid >> 5;
    const int warp_m = wid & 1, warp_n = wid >> 1;
    const int gid = lane >> 2, tig = lane & 3;
#pragma unroll
    for (int mt = 0; mt < 4; mt++) {
        const int row0 = bm + warp_m * 64 + mt * 16 + gid;
        const int row1 = row0 + 8;
#pragma unroll
        for (int nt = 0; nt < 4; nt++) {
            const int col = bn + warp_n * 32 + nt * 8 + tig * 2;
            *(float2*)(C + (size_t)row0 * D_ + col) = make_float2(acc[mt][nt][0], acc[mt][nt][1]);
            *(float2*)(C + (size_t)row1 * D_ + col) = make_float2(acc[mt][nt][2], acc[mt][nt][3]);
        }
    }
}

// ---------------------------------------------------------------------------
// Flash attention on mma.sync bf16, 2 CTAs/SM (unchanged from R12).
// ---------------------------------------------------------------------------
#define FL_STRIDE 272
#define FL_QTILE  (128 * FL_STRIDE)      // 34816
#define FL_KTILE  (16 * FL_STRIDE)       // 4352
#define FL_STAGE  (4 * FL_KTILE)         // 17408
#define FL_SMEM   (2 * FL_QTILE + 2 * FL_STAGE)  // 104448

__device__ __forceinline__ void flash_load_kv(
    uint32_t base, const __nv_bfloat16* Kh, const __nv_bfloat16* Kl,
    const __nv_bfloat16* Vh, const __nv_bfloat16* Vl, int kt, int tid)
{
    const int row = tid >> 4;             // 0..15
    const int seg = tid & 15;
    const size_t go = ((size_t)kt * 16 + row) * D_ + seg * 8;
    const uint32_t so = row * FL_STRIDE + seg * 16;
    cp16(base + so,                 Kh + go);
    cp16(base + FL_KTILE + so,      Kl + go);
    cp16(base + 2 * FL_KTILE + so,  Vh + go);
    cp16(base + 3 * FL_KTILE + so,  Vl + go);
}

__global__ __launch_bounds__(256, 2) void flash_mma()
{
    extern __shared__ __align__(128) char fsm[];
    const uint32_t sb  = smem_u32(fsm);
    const uint32_t sQh = sb;
    const uint32_t sQl = sb + FL_QTILE;
    const uint32_t sKV = sb + 2 * FL_QTILE;

    const int tid  = threadIdx.x;
    const int lane = tid & 31;
    const int w    = tid >> 5;            // 0..7
    const int gid  = lane >> 2, tig = lane & 3;
    const int bh   = blockIdx.y;
    const int b    = bh >> 4;
    const int h    = bh & 15;
    const int qt   = (int)gridDim.x - 1 - (int)blockIdx.x;   // heavy first
    const int q0   = qt * 128;
    const int nkt  = 8 * (qt + 1);

    const __nv_bfloat16* Qh = g_Qhi + ((size_t)(b * S_ + q0)) * D_ + h * DH_;
    const __nv_bfloat16* Ql = g_Qlo + ((size_t)(b * S_ + q0)) * D_ + h * DH_;
    const __nv_bfloat16* Kh = g_Khi + ((size_t)b * S_) * D_ + h * DH_;
    const __nv_bfloat16* Kl = g_Klo + ((size_t)b * S_) * D_ + h * DH_;
    const __nv_bfloat16* Vh = g_Vhi + ((size_t)b * S_) * D_ + h * DH_;
    const __nv_bfloat16* Vl = g_Vlo + ((size_t)b * S_) * D_ + h * DH_;

#pragma unroll
    for (int v = 0; v < 8; v++) {
        int idx = tid + v * 256;          // 0..2047
        int row = idx >> 4;               // 0..127
        int seg = idx & 15;
        const size_t go = (size_t)row * D_ + seg * 8;
        const uint32_t so = row * FL_STRIDE + seg * 16;
        cp16(sQh + so, Qh + go);
        cp16(sQl + so, Ql + go);
    }
    flash_load_kv(sKV, Kh, Kl, Vh, Vl, 0, tid);
    cp_commit();
    flash_load_kv(sKV + FL_STAGE, Kh, Kl, Vh, Vl, 1, tid);
    cp_commit();

    float accO[16][4];
#pragma unroll
    for (int nt = 0; nt < 16; nt++)
#pragma unroll
        for (int q = 0; q < 4; q++) accO[nt][q] = 0.0f;
    float m0 = -INFINITY, m1 = -INFINITY, l0 = 0.0f, l1 = 0.0f;

    const float scale = 0.08838834764831845f;  // 1/sqrt(128)
    const int rq0 = q0 + w * 16 + gid;
    const int rq1 = rq0 + 8;

    const uint32_t a_lane = (w * 16 + (lane & 15)) * FL_STRIDE + (lane >> 4) * 16;
    const uint32_t kb_lane = ((lane & 7) + (lane >> 4) * 8) * FL_STRIDE
                           + ((lane >> 3) & 1) * 16;
    const uint32_t v_lane = (lane & 15) * FL_STRIDE + (lane >> 4) * 16;

    for (int kt = 0; kt < nkt; kt++) {
        cp_wait1();
        __syncthreads();
        const uint32_t kbh = sKV + (kt & 1) * FL_STAGE;
        const uint32_t kbl = kbh + FL_KTILE;
        const uint32_t vbh = kbh + 2 * FL_KTILE;
        const uint32_t vbl = kbh + 3 * FL_KTILE;

        float sf[2][4];
#pragma unroll
        for (int nt = 0; nt < 2; nt++)
#pragma unroll
            for (int q = 0; q < 4; q++) sf[nt][q] = 0.0f;

#pragma unroll
        for (int ks = 0; ks < 8; ks++) {
            uint32_t ah[4], al[4], bh4[4], bl4[4];
            ldsm_x4(ah, sQh + a_lane + ks * 32);
            ldsm_x4(al, sQl + a_lane + ks * 32);
            ldsm_x4(bh4, kbh + kb_lane + ks * 32);
            ldsm_x4(bl4, kbl + kb_lane + ks * 32);
            mma16816v(sf[0], ah, bh4[0], bh4[1]);
            mma16816v(sf[0], ah, bl4[0], bl4[1]);
            mma16816v(sf[0], al, bh4[0], bh4[1]);
            mma16816v(sf[1], ah, bh4[2], bh4[3]);
            mma16816v(sf[1], ah, bl4[2], bl4[3]);
            mma16816v(sf[1], al, bh4[2], bh4[3]);
        }

        const bool msk = (kt >= nkt - 8);
#pragma unroll
        for (int nt = 0; nt < 2; nt++) {
            const int col = kt * 16 + nt * 8 + 2 * tig;
            sf[nt][0] *= scale; sf[nt][1] *= scale;
            sf[nt][2] *= scale; sf[nt][3] *= scale;
            if (msk) {
                if (col     > rq0) sf[nt][0] = -INFINITY;
                if (col + 1 > rq0) sf[nt][1] = -INFINITY;
                if (col     > rq1) sf[nt][2] = -INFINITY;
                if (col + 1 > rq1) sf[nt][3] = -INFINITY;
            }
        }

        float mx0 = fmaxf(fmaxf(sf[0][0], sf[0][1]), fmaxf(sf[1][0], sf[1][1]));
        float mx1 = fmaxf(fmaxf(sf[0][2], sf[0][3]), fmaxf(sf[1][2], sf[1][3]));
        mx0 = fmaxf(mx0, __shfl_xor_sync(0xffffffffu, mx0, 1));
        mx0 = fmaxf(mx0, __shfl_xor_sync(0xffffffffu, mx0, 2));
        mx1 = fmaxf(mx1, __shfl_xor_sync(0xffffffffu, mx1, 1));
        mx1 = fmaxf(mx1, __shfl_xor_sync(0xffffffffu, mx1, 2));

        const bool upd = (mx0 > m0) || (mx1 > m1);
        const float mn0 = fmaxf(m0, mx0), mn1 = fmaxf(m1, mx1);
        const float cr0 = __expf(m0 - mn0), cr1 = __expf(m1 - mn1);

        float sum0 = 0.0f, sum1 = 0.0f;
#pragma unroll
        for (int nt = 0; nt < 2; nt++) {
            sf[nt][0] = __expf(sf[nt][0] - mn0);
            sf[nt][1] = __expf(sf[nt][1] - mn0);
            sf[nt][2] = __expf(sf[nt][2] - mn1);
            sf[nt][3] = __expf(sf[nt][3] - mn1);
            sum0 += sf[nt][0] + sf[nt][1];
            sum1 += sf[nt][2] + sf[nt][3];
        }
        sum0 += __shfl_xor_sync(0xffffffffu, sum0, 1);
        sum0 += __shfl_xor_sync(0xffffffffu, sum0, 2);
        sum1 += __shfl_xor_sync(0xffffffffu, sum1, 1);
        sum1 += __shfl_xor_sync(0xffffffffu, sum1, 2);
        l0 = l0 * cr0 + sum0; m0 = mn0;
        l1 = l1 * cr1 + sum1; m1 = mn1;

        if (__any_sync(0xffffffffu, upd)) {
#pragma unroll
            for (int nt = 0; nt < 16; nt++) {
                accO[nt][0] *= cr0; accO[nt][1] *= cr0;
                accO[nt][2] *= cr1; accO[nt][3] *= cr1;
            }
        }

        uint32_t pah[4], pal[4];
        split2(sf[0][0], sf[0][1], pah[0], pal[0]);
        split2(sf[0][2], sf[0][3], pah[1], pal[1]);
        split2(sf[1][0], sf[1][1], pah[2], pal[2]);
        split2(sf[1][2], sf[1][3], pah[3], pal[3]);

#pragma unroll
        for (int ntp = 0; ntp < 8; ntp++) {
            uint32_t vh4[4], vl4[4];
            const uint32_t va = ntp * 32 + v_lane;
            ldsm_x4t(vh4, vbh + va);
            ldsm_x4t(vl4, vbl + va);
            mma16816v(accO[2 * ntp],     pah, vh4[0], vh4[1]);
            mma16816v(accO[2 * ntp],     pal, vh4[0], vh4[1]);
            mma16816v(accO[2 * ntp],     pah, vl4[0], vl4[1]);
            mma16816v(accO[2 * ntp + 1], pah, vh4[2], vh4[3]);
            mma16816v(accO[2 * ntp + 1], pal, vh4[2], vh4[3]);
            mma16816v(accO[2 * ntp + 1], pah, vl4[2], vl4[3]);
        }

        __syncthreads();
        if (kt + 2 < nkt)
            flash_load_kv(kbh, Kh, Kl, Vh, Vl, kt + 2, tid);
        cp_commit();
    }

    const float inv0 = 1.0f / l0, inv1 = 1.0f / l1;
    __nv_bfloat16* Oh = g_Ohi + ((size_t)(b * S_ + q0 + w * 16)) * D_ + h * DH_;
    __nv_bfloat16* Ol = g_Olo + ((size_t)(b * S_ + q0 + w * 16)) * D_ + h * DH_;
#pragma unroll
    for (int nt = 0; nt < 16; nt++) {
        const int col = nt * 8 + 2 * tig;
        uint32_t h01, l01, h23, l23;
        split2(accO[nt][0] * inv0, accO[nt][1] * inv0, h01, l01);
        split2(accO[nt][2] * inv1, accO[nt][3] * inv1, h23, l23);
        *(uint32_t*)(Oh + (size_t)gid * D_ + col)       = h01;
        *(uint32_t*)(Ol + (size_t)gid * D_ + col)       = l01;
        *(uint32_t*)(Oh + (size_t)(gid + 8) * D_ + col) = h23;
        *(uint32_t*)(Ol + (size_t)(gid + 8) * D_ + col) = l23;
    }
}

// ---------------------------------------------------------------------------
// Launch
// ---------------------------------------------------------------------------
extern "C" void kernel_launch(void* const* d_in, const int* in_sizes, int n_in,
                              void* d_out, int out_size)
{
    const float* x   = (const float*)d_in[0];
    const int*   pos = (const int*)  d_in[1];
    const float* Wq  = (const float*)d_in[2];
    const float* Wk  = (const float*)d_in[3];
    const float* Wv  = (const float*)d_in[4];
    const float* Wo  = (const float*)d_in[5];
    float*       out = (float*)d_out;

    __nv_bfloat16 *xhi, *xlo, *whi, *wlo;
    __nv_bfloat16 *qhi, *qlo, *khi, *klo, *vhi, *vlo, *ohi, *olo;
    cudaGetSymbolAddress((void**)&xhi, g_xhi);
    cudaGetSymbolAddress((void**)&xlo, g_xlo);
    cudaGetSymbolAddress((void**)&whi, g_Whi);
    cudaGetSymbolAddress((void**)&wlo, g_Wlo);
    cudaGetSymbolAddress((void**)&qhi, g_Qhi);
    cudaGetSymbolAddress((void**)&qlo, g_Qlo);
    cudaGetSymbolAddress((void**)&khi, g_Khi);
    cudaGetSymbolAddress((void**)&klo, g_Klo);
    cudaGetSymbolAddress((void**)&vhi, g_Vhi);
    cudaGetSymbolAddress((void**)&vlo, g_Vlo);
    cudaGetSymbolAddress((void**)&ohi, g_Ohi);
    cudaGetSymbolAddress((void**)&olo, g_Olo);

    cudaFuncSetAttribute(gemm_qkv, cudaFuncAttributeMaxDynamicSharedMemorySize, GEMM_SMEM);
    cudaFuncSetAttribute(gemm_out, cudaFuncAttributeMaxDynamicSharedMemorySize, GEMM_SMEM);
    cudaFuncSetAttribute(flash_mma, cudaFuncAttributeMaxDynamicSharedMemorySize, FL_SMEM);

    const int nx4 = M_ * D_ / 4;
    const int nw4 = D_ * D_ / 4;

    rope_table_kernel<<<(S_ * (DH_ / 2) + 255) / 256, 256>>>(pos);
    split_kernel<<<(nx4 + 255) / 256, 256>>>(x, xhi, xlo, nx4);
    split4_kernel<<<dim3((nw4 + 255) / 256, 4), 256>>>(Wq, Wk, Wv, Wo, whi, wlo, nw4);

    gemm_qkv<<<dim3(48, 32), 256, GEMM_SMEM>>>(xhi, xlo, whi, wlo,
                                               qhi, qlo, khi, klo, vhi, vlo);

    flash_mma<<<dim3(S_ / 128, B_ * H_), 256, FL_SMEM>>>();

    gemm_out<<<dim3(16, 32), 256, GEMM_SMEM>>>(ohi, olo,
                                               whi + 3 * (size_t)D_ * D_,
                                               wlo + 3 * (size_t)D_ * D_, out);
}

// round 17
// speedup vs baseline: 3.1761x; 1.0126x over previous
#include <cuda_runtime.h>
#include <cuda_bf16.h>
#include <math.h>
#include <stdint.h>

// Problem constants
#define B_  2
#define S_  2048
#define D_  2048
#define H_  16
#define DH_ 128
#define M_  (B_*S_)   // 4096

// ---------------------------------------------------------------------------
// Scratch (no cudaMalloc allowed)
// ---------------------------------------------------------------------------
__device__ __align__(16) float2 g_rope[S_ * (DH_ / 2)];

__device__ __align__(16) __nv_bfloat16 g_xhi[(size_t)M_ * D_];
__device__ __align__(16) __nv_bfloat16 g_xlo[(size_t)M_ * D_];
__device__ __align__(16) __nv_bfloat16 g_Whi[(size_t)4 * D_ * D_];
__device__ __align__(16) __nv_bfloat16 g_Wlo[(size_t)4 * D_ * D_];
__device__ __align__(16) __nv_bfloat16 g_Qhi[(size_t)M_ * D_];
__device__ __align__(16) __nv_bfloat16 g_Qlo[(size_t)M_ * D_];
__device__ __align__(16) __nv_bfloat16 g_Khi[(size_t)M_ * D_];
__device__ __align__(16) __nv_bfloat16 g_Klo[(size_t)M_ * D_];
__device__ __align__(16) __nv_bfloat16 g_Vhi[(size_t)M_ * D_];
__device__ __align__(16) __nv_bfloat16 g_Vlo[(size_t)M_ * D_];
__device__ __align__(16) __nv_bfloat16 g_Ohi[(size_t)M_ * D_];
__device__ __align__(16) __nv_bfloat16 g_Olo[(size_t)M_ * D_];

// ---------------------------------------------------------------------------
// PTX helpers (compute_103-safe: sm_80-era instructions only)
// ---------------------------------------------------------------------------
__device__ __forceinline__ uint32_t smem_u32(const void* p) {
    uint32_t a;
    asm("{ .reg .u64 t; cvta.to.shared.u64 t, %1; cvt.u32.u64 %0, t; }"
        : "=r"(a) : "l"(p));
    return a;
}

__device__ __forceinline__ void cp16(uint32_t dst, const void* src) {
    asm volatile("cp.async.cg.shared.global [%0], [%1], 16;" :: "r"(dst), "l"(src));
}
__device__ __forceinline__ void cp_commit() { asm volatile("cp.async.commit_group;" ::: "memory"); }
__device__ __forceinline__ void cp_wait1()  { asm volatile("cp.async.wait_group 1;" ::: "memory"); }

__device__ __forceinline__ void ldsm_x4(uint32_t (&r)[4], uint32_t addr) {
    asm volatile("ldmatrix.sync.aligned.m8n8.x4.shared.b16 {%0,%1,%2,%3}, [%4];"
                 : "=r"(r[0]), "=r"(r[1]), "=r"(r[2]), "=r"(r[3]) : "r"(addr));
}
__device__ __forceinline__ void ldsm_x2(uint32_t (&r)[2], uint32_t addr) {
    asm volatile("ldmatrix.sync.aligned.m8n8.x2.shared.b16 {%0,%1}, [%2];"
                 : "=r"(r[0]), "=r"(r[1]) : "r"(addr));
}
__device__ __forceinline__ void ldsm_x4t(uint32_t (&r)[4], uint32_t addr) {
    asm volatile("ldmatrix.sync.aligned.m8n8.x4.trans.shared.b16 {%0,%1,%2,%3}, [%4];"
                 : "=r"(r[0]), "=r"(r[1]), "=r"(r[2]), "=r"(r[3]) : "r"(addr));
}

__device__ __forceinline__ void mma16816(float (&c)[4], const uint32_t (&a)[4],
                                         const uint32_t (&b)[2]) {
    asm volatile(
        "mma.sync.aligned.m16n8k16.row.col.f32.bf16.bf16.f32 "
        "{%0,%1,%2,%3}, {%4,%5,%6,%7}, {%8,%9}, {%0,%1,%2,%3};"
        : "+f"(c[0]), "+f"(c[1]), "+f"(c[2]), "+f"(c[3])
        : "r"(a[0]), "r"(a[1]), "r"(a[2]), "r"(a[3]), "r"(b[0]), "r"(b[1]));
}
__device__ __forceinline__ void mma16816v(float (&c)[4], const uint32_t (&a)[4],
                                          uint32_t b0, uint32_t b1) {
    asm volatile(
        "mma.sync.aligned.m16n8k16.row.col.f32.bf16.bf16.f32 "
        "{%0,%1,%2,%3}, {%4,%5,%6,%7}, {%8,%9}, {%0,%1,%2,%3};"
        : "+f"(c[0]), "+f"(c[1]), "+f"(c[2]), "+f"(c[3])
        : "r"(a[0]), "r"(a[1]), "r"(a[2]), "r"(a[3]), "r"(b0), "r"(b1));
}

__device__ __forceinline__ void split2(float a, float b, uint32_t &hi, uint32_t &lo) {
    __nv_bfloat16 ha = __float2bfloat16_rn(a), hb = __float2bfloat16_rn(b);
    float ra = a - __bfloat162float(ha), rb = b - __bfloat162float(hb);
    __nv_bfloat162 th = __halves2bfloat162(ha, hb);
    __nv_bfloat162 tl = __floats2bfloat162_rn(ra, rb);
    hi = *reinterpret_cast<uint32_t*>(&th);
    lo = *reinterpret_cast<uint32_t*>(&tl);
}

// ---------------------------------------------------------------------------
// RoPE cos/sin table
// ---------------------------------------------------------------------------
__global__ void rope_table_kernel(const int* __restrict__ pos)
{
    int idx = blockIdx.x * blockDim.x + threadIdx.x;
    if (idx >= S_ * (DH_ / 2)) return;
    int s = idx / (DH_ / 2);
    int i = idx % (DH_ / 2);
    float p    = (float)pos[s];
    float freq = powf(1.0f / 10000.0f, (2.0f * (float)i) / (float)DH_);
    float ang  = p * freq;
    g_rope[idx] = make_float2(cosf(ang), sinf(ang));
}

// ---------------------------------------------------------------------------
// fp32 -> bf16 hi/lo splits
// ---------------------------------------------------------------------------
__global__ void split_kernel(const float* __restrict__ src,
                             __nv_bfloat16* __restrict__ hi,
                             __nv_bfloat16* __restrict__ lo, int n4)
{
    int i = blockIdx.x * blockDim.x + threadIdx.x;
    if (i >= n4) return;
    float4 v = ((const float4*)src)[i];
    uint32_t h01, l01, h23, l23;
    split2(v.x, v.y, h01, l01);
    split2(v.z, v.w, h23, l23);
    ((uint32_t*)hi)[2 * i]     = h01;
    ((uint32_t*)hi)[2 * i + 1] = h23;
    ((uint32_t*)lo)[2 * i]     = l01;
    ((uint32_t*)lo)[2 * i + 1] = l23;
}

__global__ void split4_kernel(const float* __restrict__ s0, const float* __restrict__ s1,
                              const float* __restrict__ s2, const float* __restrict__ s3,
                              __nv_bfloat16* __restrict__ hi,
                              __nv_bfloat16* __restrict__ lo, int n4)
{
    int i = blockIdx.x * blockDim.x + threadIdx.x;
    if (i >= n4) return;
    const int y = blockIdx.y;
    const float* src = (y == 0) ? s0 : (y == 1) ? s1 : (y == 2) ? s2 : s3;
    const size_t off = (size_t)y * ((size_t)D_ * D_ / 2);   // in uint32 units
    float4 v = ((const float4*)src)[i];
    uint32_t h01, l01, h23, l23;
    split2(v.x, v.y, h01, l01);
    split2(v.z, v.w, h23, l23);
    ((uint32_t*)hi)[off + 2 * i]     = h01;
    ((uint32_t*)hi)[off + 2 * i + 1] = h23;
    ((uint32_t*)lo)[off + 2 * i]     = l01;
    ((uint32_t*)lo)[off + 2 * i + 1] = l23;
}

// ---------------------------------------------------------------------------
// bf16x3 GEMM core (R15 proven): 128x128 CTA tile, 256 threads (8 warps =
// 2m x 4n, warp tile 64x32), BK=32, 3-stage pipeline, one barrier per chunk,
// interleaved hi|lo 128B rows with XOR swizzle. 2 CTAs/SM.
// ---------------------------------------------------------------------------
#define BK_       32
#define NCHUNK_   (D_ / BK_)            // 64
#define AI_TILE_  (128 * 128)            // 16384
#define STAGE_B_  (2 * AI_TILE_)         // 32768
#define NSTAGE_   3
#define GEMM_SMEM (NSTAGE_ * STAGE_B_)   // 98304

#define SWZ(row, seg) (((uint32_t)(row)) * 128u + ((((uint32_t)(seg)) ^ (((uint32_t)(row)) & 7u)) * 16u))

__device__ __forceinline__ void load_stage(
    uint32_t base, const __nv_bfloat16* __restrict__ pAh,
    const __nv_bfloat16* __restrict__ pAl,
    const __nv_bfloat16* __restrict__ pBh,
    const __nv_bfloat16* __restrict__ pBl, int c, int tid)
{
    const int seg  = tid & 7;
    const int xseg = seg & 3;
    const bool lo  = (seg >= 4);
    const __nv_bfloat16* srcA = lo ? pAl : pAh;
    const __nv_bfloat16* srcB = lo ? pBl : pBh;
#pragma unroll
    for (int v = 0; v < 4; v++) {
        int row = (tid >> 3) + v * 32;
        cp16(base + SWZ(row, seg),
             srcA + (size_t)row * D_ + c * BK_ + xseg * 8);
    }
#pragma unroll
    for (int v = 0; v < 4; v++) {
        int row = (tid >> 3) + v * 32;
        cp16(base + AI_TILE_ + SWZ(row, seg),
             srcB + (size_t)row * D_ + c * BK_ + xseg * 8);
    }
}

__device__ __forceinline__ void gemm_tile_core(
    uint32_t sb, const __nv_bfloat16* pAh, const __nv_bfloat16* pAl,
    const __nv_bfloat16* pBh, const __nv_bfloat16* pBl,
    float (&acc)[4][4][4], int tid)
{
    const int lane   = tid & 31;
    const int wid    = tid >> 5;
    const int warp_m = wid & 1;
    const int warp_n = wid >> 1;

#pragma unroll
    for (int mt = 0; mt < 4; mt++)
#pragma unroll
        for (int nt = 0; nt < 4; nt++)
#pragma unroll
            for (int q = 0; q < 4; q++) acc[mt][nt][q] = 0.0f;

    load_stage(sb,            pAh, pAl, pBh, pBl, 0, tid); cp_commit();
    load_stage(sb + STAGE_B_, pAh, pAl, pBh, pBl, 1, tid); cp_commit();

    const int ar  = warp_m * 64 + (lane & 15);
    const int axr = ar & 7;
    const int ak  = lane >> 4;
    const int br  = warp_n * 32 + (lane & 7);
    const int bxr = lane & 7;
    const int bk  = (lane >> 3) & 1;

    for (int c = 0; c < NCHUNK_; c++) {
        cp_wait1();
        __syncthreads();

        if (c + 2 < NCHUNK_)
            load_stage(sb + ((c + 2) % NSTAGE_) * STAGE_B_,
                       pAh, pAl, pBh, pBl, c + 2, tid);
        cp_commit();

        const uint32_t bA = sb + (c % NSTAGE_) * STAGE_B_;
        const uint32_t bB = bA + AI_TILE_;
#pragma unroll
        for (int s = 0; s < 2; s++) {
            uint32_t ah[4][4], al[4][4], bh[4][2], bl[4][2];
#pragma unroll
            for (int mt = 0; mt < 4; mt++) {
                const int r = ar + mt * 16;
                ldsm_x4(ah[mt], bA + r * 128 + (((2 * s + ak)     ^ axr) * 16));
                ldsm_x4(al[mt], bA + r * 128 + (((4 + 2 * s + ak) ^ axr) * 16));
            }
#pragma unroll
            for (int nt = 0; nt < 4; nt++) {
                const int r = br + nt * 8;
                ldsm_x2(bh[nt], bB + r * 128 + (((2 * s + bk)     ^ bxr) * 16));
                ldsm_x2(bl[nt], bB + r * 128 + (((4 + 2 * s + bk) ^ bxr) * 16));
            }
#pragma unroll
            for (int mt = 0; mt < 4; mt++)
#pragma unroll
                for (int nt = 0; nt < 4; nt++)
                    mma16816(acc[mt][nt], ah[mt], bh[nt]);
#pragma unroll
            for (int mt = 0; mt < 4; mt++)
#pragma unroll
                for (int nt = 0; nt < 4; nt++)
                    mma16816(acc[mt][nt], ah[mt], bl[nt]);
#pragma unroll
            for (int mt = 0; mt < 4; mt++)
#pragma unroll
                for (int nt = 0; nt < 4; nt++)
                    mma16816(acc[mt][nt], al[mt], bh[nt]);
        }
    }
}

// Fused Q/K/V projection: blockIdx.x = which*16 + nblock; Q,K get RoPE.
__global__ __launch_bounds__(256, 2) void gemm_qkv(
    const __nv_bfloat16* __restrict__ xhi, const __nv_bfloat16* __restrict__ xlo,
    const __nv_bfloat16* __restrict__ whi, const __nv_bfloat16* __restrict__ wlo,
    __nv_bfloat16* __restrict__ qhi, __nv_bfloat16* __restrict__ qlo,
    __nv_bfloat16* __restrict__ khi, __nv_bfloat16* __restrict__ klo,
    __nv_bfloat16* __restrict__ vhi, __nv_bfloat16* __restrict__ vlo)
{
    extern __shared__ __align__(128) char smem[];
    const uint32_t sb = smem_u32(smem);
    const int tid   = threadIdx.x;
    const int which = blockIdx.x >> 4;          // 0=Q 1=K 2=V
    const int bn    = (blockIdx.x & 15) * 128;
    const int bm    = blockIdx.y * 128;

    const __nv_bfloat16* pAh = xhi + (size_t)bm * D_;
    const __nv_bfloat16* pAl = xlo + (size_t)bm * D_;
    const __nv_bfloat16* pBh = whi + (size_t)which * D_ * D_ + (size_t)bn * D_;
    const __nv_bfloat16* pBl = wlo + (size_t)which * D_ * D_ + (size_t)bn * D_;

    float acc[4][4][4];
    gemm_tile_core(sb, pAh, pAl, pBh, pBl, acc, tid);

    __nv_bfloat16* Chi = (which == 0) ? qhi : (which == 1) ? khi : vhi;
    __nv_bfloat16* Clo = (which == 0) ? qlo : (which == 1) ? klo : vlo;
    const bool rope = (which < 2);

    const int lane = tid & 31;
    const int wid  = tid >> 5;
    const int warp_m = wid & 1, warp_n = wid >> 1;
    const int gid = lane >> 2, tig = lane & 3;
#pragma unroll
    for (int mt = 0; mt < 4; mt++) {
        const int row0 = bm + warp_m * 64 + mt * 16 + gid;
        const int row1 = row0 + 8;
        const int s0 = row0 & (S_ - 1);
        const int s1 = row1 & (S_ - 1);
#pragma unroll
        for (int nt = 0; nt < 4; nt++) {
            const int col  = bn + warp_n * 32 + nt * 8 + tig * 2;
            float c0 = acc[mt][nt][0], c1 = acc[mt][nt][1];
            float c2 = acc[mt][nt][2], c3 = acc[mt][nt][3];
            if (rope) {
                const int pr = (col & (DH_ - 1)) >> 1;
                float2 csa = g_rope[s0 * (DH_ / 2) + pr];
                float2 csb = g_rope[s1 * (DH_ / 2) + pr];
                float e0 = c0, o0 = c1, e1 = c2, o1 = c3;
                c0 = e0 * csa.x - o0 * csa.y;
                c1 = e0 * csa.y + o0 * csa.x;
                c2 = e1 * csb.x - o1 * csb.y;
                c3 = e1 * csb.y + o1 * csb.x;
            }
            uint32_t h01, l01, h23, l23;
            split2(c0, c1, h01, l01);
            split2(c2, c3, h23, l23);
            *(uint32_t*)(Chi + (size_t)row0 * D_ + col) = h01;
            *(uint32_t*)(Clo + (size_t)row0 * D_ + col) = l01;
            *(uint32_t*)(Chi + (size_t)row1 * D_ + col) = h23;
            *(uint32_t*)(Clo + (size_t)row1 * D_ + col) = l23;
        }
    }
}

// Output projection: fp32 out.
__global__ __launch_bounds__(256, 2) void gemm_out(
    const __nv_bfloat16* __restrict__ Ahi, const __nv_bfloat16* __restrict__ Alo,
    const __nv_bfloat16* __restrict__ Bhi, const __nv_bfloat16* __restrict__ Blo,
    float* __restrict__ C)
{
    extern __shared__ __align__(128) char smem[];
    const uint32_t sb = smem_u32(smem);
    const int tid = threadIdx.x;
    const int bn  = blockIdx.x * 128;
    const int bm  = blockIdx.y * 128;

    const __nv_bfloat16* pAh = Ahi + (size_t)bm * D_;
    const __nv_bfloat16* pAl = Alo + (size_t)bm * D_;
    const __nv_bfloat16* pBh = Bhi + (size_t)bn * D_;
    const __nv_bfloat16* pBl = Blo + (size_t)bn * D_;

    float acc[4][4][4];
    gemm_tile_core(sb, pAh, pAl, pBh, pBl, acc, tid);

    const int lane = tid & 31;
    const int wid  = tid >> 5;
    const int warp_m = wid & 1, warp_n = wid >> 1;
    const int gid = lane >> 2, tig = lane & 3;
#pragma unroll
    for (int mt = 0; mt < 4; mt++) {
        const int row0 = bm + warp_m * 64 + mt * 16 + gid;
        const int row1 = row0 + 8;
#pragma unroll
        for (int nt = 0; nt < 4; nt++) {
            const int col = bn + warp_n * 32 + nt * 8 + tig * 2;
            *(float2*)(C + (size_t)row0 * D_ + col) = make_float2(acc[mt][nt][0], acc[mt][nt][1]);
            *(float2*)(C + (size_t)row1 * D_ + col) = make_float2(acc[mt][nt][2], acc[mt][nt][3]);
        }
    }
}

// ---------------------------------------------------------------------------
// Flash attention, mma.sync bf16, 2 CTAs/SM. NEW: unpadded 256B rows with
// XOR swizzle (seg ^ (row&7), seg 0..15), THREE KV stages, one barrier per
// key tile (wait1 -> sync -> prefetch kt+2 -> compute kt).
// ---------------------------------------------------------------------------
#define FQ_ROW   256
#define FQ_TILE  (128 * FQ_ROW)          // 32768 (per hi or lo)
#define FK_TILE  (16 * FQ_ROW)           // 4096
#define FK_STAGE (4 * FK_TILE)           // 16384: [Kh|Kl|Vh|Vl]
#define FNSTAGE  3
#define FL_SMEM  (2 * FQ_TILE + FNSTAGE * FK_STAGE)  // 114688

// seg 0..15 (16B units) in a 256B row; xor only low 3 bits (keeps 128B half)
#define FSWZ(row, seg) (((uint32_t)(row)) * 256u + ((((uint32_t)(seg)) ^ (((uint32_t)(row)) & 7u)) * 16u))

__device__ __forceinline__ void flash_load_kv(
    uint32_t base, const __nv_bfloat16* Kh, const __nv_bfloat16* Kl,
    const __nv_bfloat16* Vh, const __nv_bfloat16* Vl, int kt, int tid)
{
    const int row = tid >> 4;             // 0..15
    const int seg = tid & 15;
    const size_t go = ((size_t)kt * 16 + row) * D_ + seg * 8;
    const uint32_t so = FSWZ(row, seg);
    cp16(base + so,               Kh + go);
    cp16(base + FK_TILE + so,     Kl + go);
    cp16(base + 2 * FK_TILE + so, Vh + go);
    cp16(base + 3 * FK_TILE + so, Vl + go);
}

__global__ __launch_bounds__(256, 2) void flash_mma()
{
    extern __shared__ __align__(128) char fsm[];
    const uint32_t sb  = smem_u32(fsm);
    const uint32_t sQh = sb;
    const uint32_t sQl = sb + FQ_TILE;
    const uint32_t sKV = sb + 2 * FQ_TILE;

    const int tid  = threadIdx.x;
    const int lane = tid & 31;
    const int w    = tid >> 5;            // 0..7
    const int gid  = lane >> 2, tig = lane & 3;
    const int bh   = blockIdx.y;
    const int b    = bh >> 4;
    const int h    = bh & 15;
    const int qt   = (int)gridDim.x - 1 - (int)blockIdx.x;   // heavy first
    const int q0   = qt * 128;
    const int nkt  = 8 * (qt + 1);

    const __nv_bfloat16* Qh = g_Qhi + ((size_t)(b * S_ + q0)) * D_ + h * DH_;
    const __nv_bfloat16* Ql = g_Qlo + ((size_t)(b * S_ + q0)) * D_ + h * DH_;
    const __nv_bfloat16* Kh = g_Khi + ((size_t)b * S_) * D_ + h * DH_;
    const __nv_bfloat16* Kl = g_Klo + ((size_t)b * S_) * D_ + h * DH_;
    const __nv_bfloat16* Vh = g_Vhi + ((size_t)b * S_) * D_ + h * DH_;
    const __nv_bfloat16* Vl = g_Vlo + ((size_t)b * S_) * D_ + h * DH_;

    // Q tiles (128 rows x 128 cols, hi+lo, swizzled) + KV stages 0,1
#pragma unroll
    for (int v = 0; v < 8; v++) {
        int idx = tid + v * 256;          // 0..2047
        int row = idx >> 4;               // 0..127
        int seg = idx & 15;
        const size_t go = (size_t)row * D_ + seg * 8;
        const uint32_t so = FSWZ(row, seg);
        cp16(sQh + so, Qh + go);
        cp16(sQl + so, Ql + go);
    }
    flash_load_kv(sKV, Kh, Kl, Vh, Vl, 0, tid);
    cp_commit();                          // group 0: Q + KV stage 0
    flash_load_kv(sKV + FK_STAGE, Kh, Kl, Vh, Vl, 1, tid);
    cp_commit();                          // group 1: KV stage 1

    float accO[16][4];
#pragma unroll
    for (int nt = 0; nt < 16; nt++)
#pragma unroll
        for (int q = 0; q < 4; q++) accO[nt][q] = 0.0f;
    float m0 = -INFINITY, m1 = -INFINITY, l0 = 0.0f, l1 = 0.0f;

    const float scale = 0.08838834764831845f;  // 1/sqrt(128)
    const int rq0 = q0 + w * 16 + gid;
    const int rq1 = rq0 + 8;

    // Per-lane row/seg components (row&7 == lane&7 for all three mappings)
    const int aqr = w * 16 + (lane & 15);       // Q row
    const int akx = lane & 7;
    const int akk = lane >> 4;                  // 16B half select
    const int kr  = (lane & 7) + (lane >> 4) * 8;  // K row
    const int kkx = lane & 7;
    const int kks = (lane >> 3) & 1;
    const int vr  = lane & 15;                  // V row
    const int vkx = lane & 7;
    const int vks = lane >> 4;

    for (int kt = 0; kt < nkt; kt++) {
        cp_wait1();            // own groups <= kt done (kt+1 may be in flight)
        __syncthreads();       // all writes of tile kt visible; stage (kt+2)%3
                               // free (read last as tile kt-1)

        if (kt + 2 < nkt)
            flash_load_kv(sKV + ((kt + 2) % FNSTAGE) * FK_STAGE,
                          Kh, Kl, Vh, Vl, kt + 2, tid);
        cp_commit();

        const uint32_t kb = sKV + (kt % FNSTAGE) * FK_STAGE;
        const uint32_t kbh = kb;
        const uint32_t kbl = kb + FK_TILE;
        const uint32_t vbh = kb + 2 * FK_TILE;
        const uint32_t vbl = kb + 3 * FK_TILE;

        // ---- S = Q @ K^T (3-term split), 16 keys ----
        float sf[2][4];
#pragma unroll
        for (int nt = 0; nt < 2; nt++)
#pragma unroll
            for (int q = 0; q < 4; q++) sf[nt][q] = 0.0f;

#pragma unroll
        for (int ks = 0; ks < 8; ks++) {
            uint32_t ah[4], al[4], bh4[4], bl4[4];
            const uint32_t qa = aqr * 256 + (((2 * ks + akk) ^ akx) * 16);
            ldsm_x4(ah, sQh + qa);
            ldsm_x4(al, sQl + qa);
            const uint32_t ka = kr * 256 + (((2 * ks + kks) ^ kkx) * 16);
            ldsm_x4(bh4, kbh + ka);
            ldsm_x4(bl4, kbl + ka);
            mma16816v(sf[0], ah, bh4[0], bh4[1]);
            mma16816v(sf[0], ah, bl4[0], bl4[1]);
            mma16816v(sf[0], al, bh4[0], bh4[1]);
            mma16816v(sf[1], ah, bh4[2], bh4[3]);
            mma16816v(sf[1], ah, bl4[2], bl4[3]);
            mma16816v(sf[1], al, bh4[2], bh4[3]);
        }

        // ---- scale + causal mask ----
        const bool msk = (kt >= nkt - 8);
#pragma unroll
        for (int nt = 0; nt < 2; nt++) {
            const int col = kt * 16 + nt * 8 + 2 * tig;
            sf[nt][0] *= scale; sf[nt][1] *= scale;
            sf[nt][2] *= scale; sf[nt][3] *= scale;
            if (msk) {
                if (col     > rq0) sf[nt][0] = -INFINITY;
                if (col + 1 > rq0) sf[nt][1] = -INFINITY;
                if (col     > rq1) sf[nt][2] = -INFINITY;
                if (col + 1 > rq1) sf[nt][3] = -INFINITY;
            }
        }

        // ---- online softmax ----
        float mx0 = fmaxf(fmaxf(sf[0][0], sf[0][1]), fmaxf(sf[1][0], sf[1][1]));
        float mx1 = fmaxf(fmaxf(sf[0][2], sf[0][3]), fmaxf(sf[1][2], sf[1][3]));
        mx0 = fmaxf(mx0, __shfl_xor_sync(0xffffffffu, mx0, 1));
        mx0 = fmaxf(mx0, __shfl_xor_sync(0xffffffffu, mx0, 2));
        mx1 = fmaxf(mx1, __shfl_xor_sync(0xffffffffu, mx1, 1));
        mx1 = fmaxf(mx1, __shfl_xor_sync(0xffffffffu, mx1, 2));

        const bool upd = (mx0 > m0) || (mx1 > m1);
        const float mn0 = fmaxf(m0, mx0), mn1 = fmaxf(m1, mx1);
        const float cr0 = __expf(m0 - mn0), cr1 = __expf(m1 - mn1);

        float sum0 = 0.0f, sum1 = 0.0f;
#pragma unroll
        for (int nt = 0; nt < 2; nt++) {
            sf[nt][0] = __expf(sf[nt][0] - mn0);
            sf[nt][1] = __expf(sf[nt][1] - mn0);
            sf[nt][2] = __expf(sf[nt][2] - mn1);
            sf[nt][3] = __expf(sf[nt][3] - mn1);
            sum0 += sf[nt][0] + sf[nt][1];
            sum1 += sf[nt][2] + sf[nt][3];
        }
        sum0 += __shfl_xor_sync(0xffffffffu, sum0, 1);
        sum0 += __shfl_xor_sync(0xffffffffu, sum0, 2);
        sum1 += __shfl_xor_sync(0xffffffffu, sum1, 1);
        sum1 += __shfl_xor_sync(0xffffffffu, sum1, 2);
        l0 = l0 * cr0 + sum0; m0 = mn0;
        l1 = l1 * cr1 + sum1; m1 = mn1;

        if (__any_sync(0xffffffffu, upd)) {
#pragma unroll
            for (int nt = 0; nt < 16; nt++) {
                accO[nt][0] *= cr0; accO[nt][1] *= cr0;
                accO[nt][2] *= cr1; accO[nt][3] *= cr1;
            }
        }

        // ---- pack P hi/lo A-fragment ----
        uint32_t pah[4], pal[4];
        split2(sf[0][0], sf[0][1], pah[0], pal[0]);
        split2(sf[0][2], sf[0][3], pah[1], pal[1]);
        split2(sf[1][0], sf[1][1], pah[2], pal[2]);
        split2(sf[1][2], sf[1][3], pah[3], pal[3]);

        // ---- O += P @ V (3-term split), V via ldmatrix trans ----
#pragma unroll
        for (int ntp = 0; ntp < 8; ntp++) {
            uint32_t vh4[4], vl4[4];
            const uint32_t va = vr * 256 + (((2 * ntp + vks) ^ vkx) * 16);
            ldsm_x4t(vh4, vbh + va);
            ldsm_x4t(vl4, vbl + va);
            mma16816v(accO[2 * ntp],     pah, vh4[0], vh4[1]);
            mma16816v(accO[2 * ntp],     pal, vh4[0], vh4[1]);
            mma16816v(accO[2 * ntp],     pah, vl4[0], vl4[1]);
            mma16816v(accO[2 * ntp + 1], pah, vh4[2], vh4[3]);
            mma16816v(accO[2 * ntp + 1], pal, vh4[2], vh4[3]);
            mma16816v(accO[2 * ntp + 1], pah, vl4[2], vl4[3]);
        }
    }

    // ---- epilogue: normalize, split to bf16 hi/lo ----
    const float inv0 = 1.0f / l0, inv1 = 1.0f / l1;
    __nv_bfloat16* Oh = g_Ohi + ((size_t)(b * S_ + q0 + w * 16)) * D_ + h * DH_;
    __nv_bfloat16* Ol = g_Olo + ((size_t)(b * S_ + q0 + w * 16)) * D_ + h * DH_;
#pragma unroll
    for (int nt = 0; nt < 16; nt++) {
        const int col = nt * 8 + 2 * tig;
        uint32_t h01, l01, h23, l23;
        split2(accO[nt][0] * inv0, accO[nt][1] * inv0, h01, l01);
        split2(accO[nt][2] * inv1, accO[nt][3] * inv1, h23, l23);
        *(uint32_t*)(Oh + (size_t)gid * D_ + col)       = h01;
        *(uint32_t*)(Ol + (size_t)gid * D_ + col)       = l01;
        *(uint32_t*)(Oh + (size_t)(gid + 8) * D_ + col) = h23;
        *(uint32_t*)(Ol + (size_t)(gid + 8) * D_ + col) = l23;
    }
}

// ---------------------------------------------------------------------------
// Launch
// ---------------------------------------------------------------------------
extern "C" void kernel_launch(void* const* d_in, const int* in_sizes, int n_in,
                              void* d_out, int out_size)
{
    const float* x   = (const float*)d_in[0];
    const int*   pos = (const int*)  d_in[1];
    const float* Wq  = (const float*)d_in[2];
    const float* Wk  = (const float*)d_in[3];
    const float* Wv  = (const float*)d_in[4];
    const float* Wo  = (const float*)d_in[5];
    float*       out = (float*)d_out;

    __nv_bfloat16 *xhi, *xlo, *whi, *wlo;
    __nv_bfloat16 *qhi, *qlo, *khi, *klo, *vhi, *vlo, *ohi, *olo;
    cudaGetSymbolAddress((void**)&xhi, g_xhi);
    cudaGetSymbolAddress((void**)&xlo, g_xlo);
    cudaGetSymbolAddress((void**)&whi, g_Whi);
    cudaGetSymbolAddress((void**)&wlo, g_Wlo);
    cudaGetSymbolAddress((void**)&qhi, g_Qhi);
    cudaGetSymbolAddress((void**)&qlo, g_Qlo);
    cudaGetSymbolAddress((void**)&khi, g_Khi);
    cudaGetSymbolAddress((void**)&klo, g_Klo);
    cudaGetSymbolAddress((void**)&vhi, g_Vhi);
    cudaGetSymbolAddress((void**)&vlo, g_Vlo);
    cudaGetSymbolAddress((void**)&ohi, g_Ohi);
    cudaGetSymbolAddress((void**)&olo, g_Olo);

    cudaFuncSetAttribute(gemm_qkv, cudaFuncAttributeMaxDynamicSharedMemorySize, GEMM_SMEM);
    cudaFuncSetAttribute(gemm_out, cudaFuncAttributeMaxDynamicSharedMemorySize, GEMM_SMEM);
    cudaFuncSetAttribute(flash_mma, cudaFuncAttributeMaxDynamicSharedMemorySize, FL_SMEM);

    const int nx4 = M_ * D_ / 4;
    const int nw4 = D_ * D_ / 4;

    rope_table_kernel<<<(S_ * (DH_ / 2) + 255) / 256, 256>>>(pos);
    split_kernel<<<(nx4 + 255) / 256, 256>>>(x, xhi, xlo, nx4);
    split4_kernel<<<dim3((nw4 + 255) / 256, 4), 256>>>(Wq, Wk, Wv, Wo, whi, wlo, nw4);

    gemm_qkv<<<dim3(48, 32), 256, GEMM_SMEM>>>(xhi, xlo, whi, wlo,
                                               qhi, qlo, khi, klo, vhi, vlo);

    flash_mma<<<dim3(S_ / 128, B_ * H_), 256, FL_SMEM>>>();

    gemm_out<<<dim3(16, 32), 256, GEMM_SMEM>>>(ohi, olo,
                                               whi + 3 * (size_t)D_ * D_,
                                               wlo + 3 * (size_t)D_ * D_, out);
}